// round 4
// baseline (speedup 1.0000x reference)
#include <cuda_runtime.h>
#include <math.h>

#define SEQP 512
#define DIM 768
#define NH 16
#define DH 48
#define NF 2048
#define INV_SCALE 0.14433756729740643f  // 1/sqrt(768/16)

// ---------------- scratch (device globals; reused across the 6 serialized instances) ----
__device__ float g_cnt[3 * 2 * SEQP];          // [b][0]=fpos counts, [b][1]=tpos counts
__device__ float g_Q[SEQP * DIM];
__device__ float g_K[SEQP * DIM];
__device__ float g_V[SEQP * DIM];
__device__ float g_cb[SEQP * NH];              // cb[r][h]
__device__ float g_scores[NH * SEQP * SEQP];   // [h][p][r]
__device__ float g_ctx[SEQP * DIM];
__device__ float g_dproj[SEQP * DIM];
__device__ float g_y[SEQP * DIM];

// ---------------- counts ----------------
__global__ void zero_counts_kernel() {
    int i = blockIdx.x * blockDim.x + threadIdx.x;
    if (i < 3 * 2 * SEQP) g_cnt[i] = 0.f;
}

__global__ void count_kernel(const int* __restrict__ fpos, const int* __restrict__ tpos) {
    int i = blockIdx.x * blockDim.x + threadIdx.x;
    if (i >= 3 * NF) return;
    int b = i / NF;
    atomicAdd(&g_cnt[(b * 2 + 0) * SEQP + (fpos[i] & (SEQP - 1))], 1.f);
    atomicAdd(&g_cnt[(b * 2 + 1) * SEQP + (tpos[i] & (SEQP - 1))], 1.f);
}

// ---------------- generic tiled GEMM: C[M,N] = A[M,K] @ B[N,K]^T (+bias) ----------------
// Optional per-z mix vector multiplies A's k-dim on load (for per-head mixed scores).
// Optional per-z C offset (strideCz) so z can index heads.
#define BM 64
#define BN 64
#define BKK 16

__global__ void gemm_abT(const float* __restrict__ A, const float* __restrict__ B,
                         float* __restrict__ C,
                         int M, int N, int K, int lda, int ldb, int ldc,
                         const float* __restrict__ bias,
                         const float* __restrict__ mix, int mixStride,
                         long long strideCz) {
    __shared__ float As[BKK][BM];
    __shared__ float Bs[BKK][BN];
    int tx = threadIdx.x & 15;
    int ty = threadIdx.x >> 4;
    int row0 = blockIdx.y * BM;
    int col0 = blockIdx.x * BN;
    const float* mixv = mix ? (mix + (long long)blockIdx.z * mixStride) : nullptr;
    C += (long long)blockIdx.z * strideCz;

    float acc[4][4] = {};

    for (int k0 = 0; k0 < K; k0 += BKK) {
#pragma unroll
        for (int i = 0; i < 4; i++) {
            int idx = threadIdx.x + i * 256;
            int m = idx >> 4, kk = idx & 15;
            int gm = row0 + m, gk = k0 + kk;
            float v = 0.f;
            if (gm < M && gk < K) {
                v = A[(long long)gm * lda + gk];
                if (mixv) v *= mixv[gk];
            }
            As[kk][m] = v;
        }
#pragma unroll
        for (int i = 0; i < 4; i++) {
            int idx = threadIdx.x + i * 256;
            int n = idx >> 4, kk = idx & 15;
            int gn = col0 + n, gk = k0 + kk;
            Bs[kk][n] = (gn < N && gk < K) ? B[(long long)gn * ldb + gk] : 0.f;
        }
        __syncthreads();
#pragma unroll
        for (int kk = 0; kk < BKK; kk++) {
            float a[4], bb[4];
#pragma unroll
            for (int i = 0; i < 4; i++) a[i] = As[kk][ty * 4 + i];
#pragma unroll
            for (int j = 0; j < 4; j++) bb[j] = Bs[kk][tx * 4 + j];
#pragma unroll
            for (int i = 0; i < 4; i++)
#pragma unroll
                for (int j = 0; j < 4; j++) acc[i][j] += a[i] * bb[j];
        }
        __syncthreads();
    }

#pragma unroll
    for (int i = 0; i < 4; i++) {
        int gm = row0 + ty * 4 + i;
        if (gm >= M) continue;
#pragma unroll
        for (int j = 0; j < 4; j++) {
            int gn = col0 + tx * 4 + j;
            if (gn >= N) continue;
            float v = acc[i][j];
            if (bias) v += bias[gn];
            C[(long long)gm * ldc + gn] = v;
        }
    }
}

// ---------------- C[M,N] = A[M,K] @ B[K,N] with per-z strides (PV per head) ----------------
__global__ void gemm_ab(const float* __restrict__ A, const float* __restrict__ B,
                        float* __restrict__ C,
                        int M, int N, int K, int lda, int ldb, int ldc,
                        long long strideAz, long long strideBz, long long strideCz) {
    __shared__ float As[BKK][BM];
    __shared__ float Bs[BKK][BN];
    int tx = threadIdx.x & 15;
    int ty = threadIdx.x >> 4;
    int row0 = blockIdx.y * BM;
    int col0 = blockIdx.x * BN;
    A += (long long)blockIdx.z * strideAz;
    B += (long long)blockIdx.z * strideBz;
    C += (long long)blockIdx.z * strideCz;

    float acc[4][4] = {};

    for (int k0 = 0; k0 < K; k0 += BKK) {
#pragma unroll
        for (int i = 0; i < 4; i++) {
            int idx = threadIdx.x + i * 256;
            int m = idx >> 4, kk = idx & 15;
            int gm = row0 + m, gk = k0 + kk;
            As[kk][m] = (gm < M && gk < K) ? A[(long long)gm * lda + gk] : 0.f;
        }
#pragma unroll
        for (int i = 0; i < 4; i++) {
            int idx = threadIdx.x + i * 256;
            int kk = idx >> 6, n = idx & 63;
            int gn = col0 + n, gk = k0 + kk;
            Bs[kk][n] = (gn < N && gk < K) ? B[(long long)gk * ldb + gn] : 0.f;
        }
        __syncthreads();
#pragma unroll
        for (int kk = 0; kk < BKK; kk++) {
            float a[4], bb[4];
#pragma unroll
            for (int i = 0; i < 4; i++) a[i] = As[kk][ty * 4 + i];
#pragma unroll
            for (int j = 0; j < 4; j++) bb[j] = Bs[kk][tx * 4 + j];
#pragma unroll
            for (int i = 0; i < 4; i++)
#pragma unroll
                for (int j = 0; j < 4; j++) acc[i][j] += a[i] * bb[j];
        }
        __syncthreads();
    }

#pragma unroll
    for (int i = 0; i < 4; i++) {
        int gm = row0 + ty * 4 + i;
        if (gm >= M) continue;
#pragma unroll
        for (int j = 0; j < 4; j++) {
            int gn = col0 + tx * 4 + j;
            if (gn >= N) continue;
            C[(long long)gm * ldc + gn] = acc[i][j];
        }
    }
}

// ---------------- block reductions ----------------
__device__ __forceinline__ float blockReduceMax(float v) {
    __shared__ float sh[8];
    __shared__ float res;
#pragma unroll
    for (int o = 16; o > 0; o >>= 1) v = fmaxf(v, __shfl_xor_sync(0xffffffffu, v, o));
    __syncthreads();
    if ((threadIdx.x & 31) == 0) sh[threadIdx.x >> 5] = v;
    __syncthreads();
    if (threadIdx.x == 0) {
        float m = sh[0];
        for (int i = 1; i < 8; i++) m = fmaxf(m, sh[i]);
        res = m;
    }
    __syncthreads();
    return res;
}

__device__ __forceinline__ float blockReduceSum(float v) {
    __shared__ float sh[8];
    __shared__ float res;
#pragma unroll
    for (int o = 16; o > 0; o >>= 1) v += __shfl_xor_sync(0xffffffffu, v, o);
    __syncthreads();
    if ((threadIdx.x & 31) == 0) sh[threadIdx.x >> 5] = v;
    __syncthreads();
    if (threadIdx.x == 0) {
        float s = 0.f;
        for (int i = 0; i < 8; i++) s += sh[i];
        res = s;
    }
    __syncthreads();
    return res;
}

// ---------------- count-weighted softmax (in-place on g_scores) ----------------
// blockIdx.x = h*512 + p, 256 threads, 2 cols each.
__global__ void softmax_kernel(const float* __restrict__ kcnt) {
    int h = blockIdx.x >> 9;
    float* row = g_scores + (long long)blockIdx.x * SEQP;
    int t0 = threadIdx.x, t1 = threadIdx.x + 256;
    float s0 = (row[t0] + g_cb[t0 * NH + h]) * INV_SCALE;
    float s1 = (row[t1] + g_cb[t1 * NH + h]) * INV_SCALE;
    float m = blockReduceMax(fmaxf(s0, s1));
    float w0 = kcnt[t0] * expf(s0 - m);
    float w1 = kcnt[t1] * expf(s1 - m);
    float inv = 1.f / blockReduceSum(w0 + w1);
    row[t0] = w0 * inv;
    row[t1] = w1 * inv;
}

// ---------------- residual + LayerNorm + count-weighting ----------------
// block p in [0,512), 256 threads, 3 cols each.
__global__ void ln_kernel(const float* __restrict__ hb,
                          const float* __restrict__ lng, const float* __restrict__ lnb,
                          const float* __restrict__ qcnt) {
    int p = blockIdx.x;
    const float* hr = hb + (long long)p * DIM;
    const float* dr = g_dproj + (long long)p * DIM;
    float x[3];
    float s = 0.f;
#pragma unroll
    for (int i = 0; i < 3; i++) {
        int j = threadIdx.x + i * 256;
        x[i] = hr[j] + dr[j];
        s += x[i];
    }
    float mu = blockReduceSum(s) * (1.f / DIM);
    float vs = 0.f;
#pragma unroll
    for (int i = 0; i < 3; i++) {
        float d = x[i] - mu;
        vs += d * d;
    }
    float var = blockReduceSum(vs) * (1.f / DIM);
    float inv = rsqrtf(var + 1e-5f);
    float w = qcnt[p] * (1.f / 2048.f);
#pragma unroll
    for (int i = 0; i < 3; i++) {
        int j = threadIdx.x + i * 256;
        g_y[(long long)p * DIM + j] = (lng[j] * (x[i] - mu) * inv + lnb[j]) * w;
    }
}

// ---------------- column sum over 512 weighted rows -> output [768] ----------------
__global__ void colsum_kernel(float* __restrict__ o) {
    int j = blockIdx.x * blockDim.x + threadIdx.x;
    if (j >= DIM) return;
    float s = 0.f;
    for (int p = 0; p < SEQP; p++) s += g_y[(long long)p * DIM + j];
    o[j] = s;
}

// ---------------- host ----------------
extern "C" void kernel_launch(void* const* d_in, const int* in_sizes, int n_in,
                              void* d_out, int out_size) {
    const float* hidden = (const float*)d_in[0];
    const int* fpos = (const int*)d_in[1];
    const int* tpos = (const int*)d_in[2];
    float* out = (float*)d_out;

    float *Q, *K, *V, *cb, *scores, *ctx, *dproj, *cnt;
    cudaGetSymbolAddress((void**)&cnt, g_cnt);
    cudaGetSymbolAddress((void**)&Q, g_Q);
    cudaGetSymbolAddress((void**)&K, g_K);
    cudaGetSymbolAddress((void**)&V, g_V);
    cudaGetSymbolAddress((void**)&cb, g_cb);
    cudaGetSymbolAddress((void**)&scores, g_scores);
    cudaGetSymbolAddress((void**)&ctx, g_ctx);
    cudaGetSymbolAddress((void**)&dproj, g_dproj);

    zero_counts_kernel<<<(3 * 2 * SEQP + 255) / 256, 256>>>();
    count_kernel<<<(3 * NF + 255) / 256, 256>>>(fpos, tpos);

    dim3 blk(256);
    for (int b = 0; b < 3; b++) {
        const float* hb = hidden + (long long)b * SEQP * DIM;
        for (int inst = 0; inst < 2; inst++) {
            void* const* P = d_in + 3 + inst * 10;
            const float* Wq  = (const float*)P[0];
            const float* Wk  = (const float*)P[1];
            const float* Wcb = (const float*)P[2];
            const float* Wv  = (const float*)P[3];
            const float* Wd  = (const float*)P[4];
            const float* mix = (const float*)P[5];
            const float* bv  = (const float*)P[6];
            const float* bd  = (const float*)P[7];
            const float* lng = (const float*)P[8];
            const float* lnb = (const float*)P[9];

            const float* qcnt = cnt + (b * 2 + inst) * SEQP;       // inst0: fpos; inst1: tpos
            const float* kcnt = cnt + (b * 2 + (1 - inst)) * SEQP;

            // projections over 512 unique positions
            gemm_abT<<<dim3(12, 8), blk>>>(hb, Wq, Q, SEQP, DIM, DIM, DIM, DIM, DIM,
                                           nullptr, nullptr, 0, 0);
            gemm_abT<<<dim3(12, 8), blk>>>(hb, Wk, K, SEQP, DIM, DIM, DIM, DIM, DIM,
                                           nullptr, nullptr, 0, 0);
            gemm_abT<<<dim3(12, 8), blk>>>(hb, Wv, V, SEQP, DIM, DIM, DIM, DIM, DIM,
                                           bv, nullptr, 0, 0);
            gemm_abT<<<dim3(1, 8), blk>>>(hb, Wcb, cb, SEQP, NH, DIM, DIM, DIM, NH,
                                          nullptr, nullptr, 0, 0);

            // per-head mixed scores: scores[h] = (Q * mix[h]) @ K^T   [512,512] x16
            gemm_abT<<<dim3(8, 8, NH), blk>>>(Q, K, scores, SEQP, SEQP, DIM, DIM, DIM, SEQP,
                                              nullptr, mix, DIM, (long long)SEQP * SEQP);

            // count-weighted softmax in place
            softmax_kernel<<<NH * SEQP, 256>>>(kcnt);

            // PV per head: ctx[:, h*48:(h+1)*48] = probs[h] @ V[:, h*48:(h+1)*48]
            gemm_ab<<<dim3(1, 8, NH), blk>>>(scores, V, ctx, SEQP, DH, SEQP, SEQP, DIM, DIM,
                                             (long long)SEQP * SEQP, DH, DH);

            // output projection (+bd)
            gemm_abT<<<dim3(12, 8), blk>>>(ctx, Wd, dproj, SEQP, DIM, DIM, DIM, DIM, DIM,
                                           bd, nullptr, 0, 0);

            // residual + LN + query-count weighting, then column sum -> out segment
            ln_kernel<<<SEQP, 256>>>(hb, lng, lnb, qcnt);
            colsum_kernel<<<3, 256>>>(out + (long long)b * 2 * DIM + inst * DIM);
        }
    }
}

// round 5
// speedup vs baseline: 2.8597x; 2.8597x over previous
#include <cuda_runtime.h>
#include <math.h>

#define SEQP 512
#define DIM 768
#define NH 16
#define DH 48
#define NF 2048
#define INV_SCALE 0.14433756729740643f  // 1/sqrt(768/16)

// ---------------- scratch: per-instance private, fully batched ----------------
__device__ float g_cnt[3 * 2 * SEQP];             // [b][0]=fpos counts, [b][1]=tpos counts
__device__ float g_QKV[6][SEQP][3 * DIM];         // per z6: Q | K | V(+bv)
__device__ float g_cb[6][SEQP][NH];               // cb[z6][t][h]
__device__ float g_scores[96][SEQP][SEQP];        // z96 = inst6*16 + h
__device__ float g_ctx[6][SEQP][DIM];
__device__ float g_dproj[6][SEQP][DIM];
__device__ float g_y[6][SEQP][DIM];

struct EncParams {
    const float *Wq[2], *Wk[2], *Wv[2], *Wcb[2], *Wd[2], *mix[2];
    const float *bv[2], *bd[2], *lng[2], *lnb[2];
};

// ---------------- counts ----------------
__global__ void zero_counts_kernel() {
    int i = blockIdx.x * blockDim.x + threadIdx.x;
    if (i < 3 * 2 * SEQP) g_cnt[i] = 0.f;
}

__global__ void count_kernel(const int* __restrict__ fpos, const int* __restrict__ tpos) {
    int i = blockIdx.x * blockDim.x + threadIdx.x;
    if (i >= 3 * NF) return;
    int b = i / NF;
    atomicAdd(&g_cnt[(b * 2 + 0) * SEQP + (fpos[i] & (SEQP - 1))], 1.f);
    atomicAdd(&g_cnt[(b * 2 + 1) * SEQP + (tpos[i] & (SEQP - 1))], 1.f);
}

// ---------------- 128x128x16 SGEMM core, 8x8/thread, C = A @ B^T (+bias) ------
// A[M,K] row-major (lda), B[N,K] row-major (ldb). Full tiles assumed
// (M,N multiples of 128 within this call; K multiple of 16).
template <bool HAS_MIX>
__device__ __forceinline__ void sgemm128(
    const float* __restrict__ A, int lda,
    const float* __restrict__ B, int ldb,
    float* __restrict__ C, int ldc,
    int K, const float* __restrict__ bias, const float* __restrict__ mix,
    int row0, int col0)
{
    __shared__ float As[16][132];
    __shared__ float Bs[16][132];
    const int tid = threadIdx.x;
    const int tx = tid & 15;        // 0..15 -> 8 cols each
    const int ty = tid >> 4;        // 0..15 -> 8 rows each
    const int lrow = tid >> 2;      // 0..63
    const int lc4  = tid & 3;       // float4 slot within 16-float k-strip

    float acc[8][8] = {};

    for (int k0 = 0; k0 < K; k0 += 16) {
#pragma unroll
        for (int r = 0; r < 2; r++) {
            int m = lrow + r * 64;
            float4 v = *(const float4*)(A + (long long)(row0 + m) * lda + k0 + lc4 * 4);
            if (HAS_MIX) {
                v.x *= mix[k0 + lc4 * 4 + 0];
                v.y *= mix[k0 + lc4 * 4 + 1];
                v.z *= mix[k0 + lc4 * 4 + 2];
                v.w *= mix[k0 + lc4 * 4 + 3];
            }
            As[lc4 * 4 + 0][m] = v.x; As[lc4 * 4 + 1][m] = v.y;
            As[lc4 * 4 + 2][m] = v.z; As[lc4 * 4 + 3][m] = v.w;
        }
#pragma unroll
        for (int r = 0; r < 2; r++) {
            int n = lrow + r * 64;
            float4 v = *(const float4*)(B + (long long)(col0 + n) * ldb + k0 + lc4 * 4);
            Bs[lc4 * 4 + 0][n] = v.x; Bs[lc4 * 4 + 1][n] = v.y;
            Bs[lc4 * 4 + 2][n] = v.z; Bs[lc4 * 4 + 3][n] = v.w;
        }
        __syncthreads();
#pragma unroll
        for (int kk = 0; kk < 16; kk++) {
            float a[8], bb[8];
            *(float4*)(a)     = *(const float4*)&As[kk][ty * 8];
            *(float4*)(a + 4) = *(const float4*)&As[kk][ty * 8 + 4];
            *(float4*)(bb)     = *(const float4*)&Bs[kk][tx * 8];
            *(float4*)(bb + 4) = *(const float4*)&Bs[kk][tx * 8 + 4];
#pragma unroll
            for (int i = 0; i < 8; i++)
#pragma unroll
                for (int j = 0; j < 8; j++)
                    acc[i][j] = fmaf(a[i], bb[j], acc[i][j]);
        }
        __syncthreads();
    }

#pragma unroll
    for (int i = 0; i < 8; i++) {
        int gm = row0 + ty * 8 + i;
        float* crow = C + (long long)gm * ldc + col0 + tx * 8;
        float4 o0 = make_float4(acc[i][0], acc[i][1], acc[i][2], acc[i][3]);
        float4 o1 = make_float4(acc[i][4], acc[i][5], acc[i][6], acc[i][7]);
        if (bias) {
            const float* bp = bias + col0 + tx * 8;
            o0.x += bp[0]; o0.y += bp[1]; o0.z += bp[2]; o0.w += bp[3];
            o1.x += bp[4]; o1.y += bp[5]; o1.z += bp[6]; o1.w += bp[7];
        }
        *(float4*)crow = o0;
        *(float4*)(crow + 4) = o1;
    }
}

// ---------------- projections: QKV fused, batched over z6 ----------------
// grid (18, 4, 6): x = sector(3) * coltile(6); C[z][512, 2304]
__global__ __launch_bounds__(256, 2) void proj_kernel(const float* __restrict__ hidden,
                                                      EncParams p) {
    int z = blockIdx.z, inst = z & 1, b = z >> 1;
    int sector = blockIdx.x / 6;
    int colL = (blockIdx.x % 6) * 128;
    int row0 = blockIdx.y * 128;
    const float* A = hidden + (long long)b * SEQP * DIM;
    const float* W = sector == 0 ? p.Wq[inst] : sector == 1 ? p.Wk[inst] : p.Wv[inst];
    const float* bias = sector == 2 ? p.bv[inst] : nullptr;
    float* C = &g_QKV[z][0][sector * DIM];
    sgemm128<false>(A, DIM, W, DIM, C, 3 * DIM, DIM, bias, nullptr, row0, colL);
}

// ---------------- content bias: cb[z][t][h] = hidden_row(t) . Wcb[h] ----------
// grid (512, 6), 128 threads
__global__ void cb_kernel(const float* __restrict__ hidden, EncParams p) {
    int z = blockIdx.y, inst = z & 1, b = z >> 1;
    const float* row = hidden + ((long long)b * SEQP + blockIdx.x) * DIM;
    __shared__ float sh[DIM];
    for (int i = threadIdx.x; i < DIM; i += 128) sh[i] = row[i];
    __syncthreads();
    int warp = threadIdx.x >> 5, lane = threadIdx.x & 31;
#pragma unroll
    for (int hh = 0; hh < 4; hh++) {
        int h = warp * 4 + hh;
        const float* w = p.Wcb[inst] + h * DIM;
        float s = 0.f;
        for (int i = lane; i < DIM; i += 32) s += sh[i] * w[i];
#pragma unroll
        for (int o = 16; o > 0; o >>= 1) s += __shfl_xor_sync(0xffffffffu, s, o);
        if (lane == 0) g_cb[z][blockIdx.x][h] = s;
    }
}

// ---------------- scores: (Q*mix[h]) @ K^T, batched over 96 head-instances ----
// grid (4, 4, 96)
__global__ __launch_bounds__(256, 2) void scores_kernel(EncParams p) {
    int z = blockIdx.z;
    int inst6 = z >> 4, h = z & 15, inst = inst6 & 1;
    const float* A = &g_QKV[inst6][0][0];        // Q, lda 2304
    const float* B = &g_QKV[inst6][0][DIM];      // K, ldb 2304
    const float* mix = p.mix[inst] + h * DIM;
    sgemm128<true>(A, 3 * DIM, B, 3 * DIM, &g_scores[z][0][0], SEQP, DIM,
                   nullptr, mix, blockIdx.y * 128, blockIdx.x * 128);
}

// ---------------- block reductions ----------------
__device__ __forceinline__ float blockReduceMax(float v) {
    __shared__ float sh[8];
    __shared__ float res;
#pragma unroll
    for (int o = 16; o > 0; o >>= 1) v = fmaxf(v, __shfl_xor_sync(0xffffffffu, v, o));
    __syncthreads();
    if ((threadIdx.x & 31) == 0) sh[threadIdx.x >> 5] = v;
    __syncthreads();
    if (threadIdx.x == 0) {
        float m = sh[0];
        for (int i = 1; i < 8; i++) m = fmaxf(m, sh[i]);
        res = m;
    }
    __syncthreads();
    return res;
}

__device__ __forceinline__ float blockReduceSum(float v) {
    __shared__ float sh[8];
    __shared__ float res;
#pragma unroll
    for (int o = 16; o > 0; o >>= 1) v += __shfl_xor_sync(0xffffffffu, v, o);
    __syncthreads();
    if ((threadIdx.x & 31) == 0) sh[threadIdx.x >> 5] = v;
    __syncthreads();
    if (threadIdx.x == 0) {
        float s = 0.f;
        for (int i = 0; i < 8; i++) s += sh[i];
        res = s;
    }
    __syncthreads();
    return res;
}

// ---------------- count-weighted softmax, in place. grid (512, 96), 256 thr ----
__global__ void softmax_kernel() {
    int p_ = blockIdx.x, z = blockIdx.y;
    int inst6 = z >> 4, h = z & 15, inst = inst6 & 1, b = inst6 >> 1;
    const float* kcnt = g_cnt + (b * 2 + (1 - inst)) * SEQP;
    float* row = &g_scores[z][p_][0];
    int t0 = threadIdx.x, t1 = threadIdx.x + 256;
    float s0 = (row[t0] + g_cb[inst6][t0][h]) * INV_SCALE;
    float s1 = (row[t1] + g_cb[inst6][t1][h]) * INV_SCALE;
    float m = blockReduceMax(fmaxf(s0, s1));
    float w0 = kcnt[t0] * expf(s0 - m);
    float w1 = kcnt[t1] * expf(s1 - m);
    float inv = 1.f / blockReduceSum(w0 + w1);
    row[t0] = w0 * inv;
    row[t1] = w1 * inv;
}

// ---------------- PV: ctx[:, h*48:+48] = probs[z] @ V. grid (1, 8, 96) --------
__global__ void pv_kernel() {
    int z = blockIdx.z, inst6 = z >> 4, h = z & 15;
    const float* A = &g_scores[z][0][0];                 // [512,512]
    const float* B = &g_QKV[inst6][0][2 * DIM + h * DH]; // [512 k-rows], ldb 2304
    float* C = &g_ctx[inst6][0][h * DH];                 // ldc 768
    __shared__ float As[16][64];
    __shared__ float Bs[16][64];
    int tx = threadIdx.x & 15, ty = threadIdx.x >> 4;
    int row0 = blockIdx.y * 64;
    float acc[4][4] = {};

    for (int k0 = 0; k0 < SEQP; k0 += 16) {
#pragma unroll
        for (int i = 0; i < 4; i++) {
            int idx = threadIdx.x + i * 256;
            int m = idx >> 4, kk = idx & 15;
            As[kk][m] = A[(long long)(row0 + m) * SEQP + k0 + kk];
        }
#pragma unroll
        for (int i = 0; i < 4; i++) {
            int idx = threadIdx.x + i * 256;
            int kk = idx >> 6, n = idx & 63;
            Bs[kk][n] = (n < DH) ? B[(long long)(k0 + kk) * (3 * DIM) + n] : 0.f;
        }
        __syncthreads();
#pragma unroll
        for (int kk = 0; kk < 16; kk++) {
            float a[4], bb[4];
#pragma unroll
            for (int i = 0; i < 4; i++) a[i] = As[kk][ty * 4 + i];
#pragma unroll
            for (int j = 0; j < 4; j++) bb[j] = Bs[kk][tx * 4 + j];
#pragma unroll
            for (int i = 0; i < 4; i++)
#pragma unroll
                for (int j = 0; j < 4; j++) acc[i][j] = fmaf(a[i], bb[j], acc[i][j]);
        }
        __syncthreads();
    }
#pragma unroll
    for (int i = 0; i < 4; i++) {
        int gm = row0 + ty * 4 + i;
#pragma unroll
        for (int j = 0; j < 4; j++) {
            int gn = tx * 4 + j;
            if (gn < DH) C[(long long)gm * DIM + gn] = acc[i][j];
        }
    }
}

// ---------------- output projection: dproj = ctx @ Wd^T + bd. grid (6,4,6) ----
__global__ __launch_bounds__(256, 2) void wd_kernel(EncParams p) {
    int z = blockIdx.z, inst = z & 1;
    sgemm128<false>(&g_ctx[z][0][0], DIM, p.Wd[inst], DIM, &g_dproj[z][0][0], DIM,
                    DIM, p.bd[inst], nullptr, blockIdx.y * 128, blockIdx.x * 128);
}

// ---------------- residual + LN + count weighting. grid (512, 6), 256 thr -----
__global__ void ln_kernel(const float* __restrict__ hidden, EncParams p) {
    int pos = blockIdx.x, z = blockIdx.y, inst = z & 1, b = z >> 1;
    const float* hr = hidden + ((long long)b * SEQP + pos) * DIM;
    const float* dr = &g_dproj[z][pos][0];
    const float* lng = p.lng[inst];
    const float* lnb = p.lnb[inst];
    float x[3];
    float s = 0.f;
#pragma unroll
    for (int i = 0; i < 3; i++) {
        int j = threadIdx.x + i * 256;
        x[i] = hr[j] + dr[j];
        s += x[i];
    }
    float mu = blockReduceSum(s) * (1.f / DIM);
    float vs = 0.f;
#pragma unroll
    for (int i = 0; i < 3; i++) {
        float d = x[i] - mu;
        vs += d * d;
    }
    float var = blockReduceSum(vs) * (1.f / DIM);
    float inv = rsqrtf(var + 1e-5f);
    float w = g_cnt[(b * 2 + inst) * SEQP + pos] * (1.f / 2048.f);
#pragma unroll
    for (int i = 0; i < 3; i++) {
        int j = threadIdx.x + i * 256;
        g_y[z][pos][j] = (lng[j] * (x[i] - mu) * inv + lnb[j]) * w;
    }
}

// ---------------- column sum -> output. grid (3, 6), 256 thr ----------------
__global__ void colsum_kernel(float* __restrict__ out) {
    int z = blockIdx.y;
    int j = blockIdx.x * 256 + threadIdx.x;
    const float* Y = &g_y[z][0][0];
    float s = 0.f;
#pragma unroll 8
    for (int p = 0; p < SEQP; p++) s += Y[(long long)p * DIM + j];
    out[(z >> 1) * 2 * DIM + (z & 1) * DIM + j] = s;
}

// ---------------- host ----------------
extern "C" void kernel_launch(void* const* d_in, const int* in_sizes, int n_in,
                              void* d_out, int out_size) {
    const float* hidden = (const float*)d_in[0];
    const int* fpos = (const int*)d_in[1];
    const int* tpos = (const int*)d_in[2];
    float* out = (float*)d_out;

    EncParams p;
    for (int inst = 0; inst < 2; inst++) {
        void* const* P = d_in + 3 + inst * 10;
        p.Wq[inst]  = (const float*)P[0];
        p.Wk[inst]  = (const float*)P[1];
        p.Wcb[inst] = (const float*)P[2];
        p.Wv[inst]  = (const float*)P[3];
        p.Wd[inst]  = (const float*)P[4];
        p.mix[inst] = (const float*)P[5];
        p.bv[inst]  = (const float*)P[6];
        p.bd[inst]  = (const float*)P[7];
        p.lng[inst] = (const float*)P[8];
        p.lnb[inst] = (const float*)P[9];
    }

    zero_counts_kernel<<<6, 512>>>();
    count_kernel<<<(3 * NF + 255) / 256, 256>>>(fpos, tpos);

    proj_kernel<<<dim3(18, 4, 6), 256>>>(hidden, p);     // QKV for all 6 instances
    cb_kernel<<<dim3(512, 6), 128>>>(hidden, p);         // content bias
    scores_kernel<<<dim3(4, 4, 96), 256>>>(p);           // 96 head-instances
    softmax_kernel<<<dim3(512, 96), 256>>>();            // count-weighted softmax
    pv_kernel<<<dim3(1, 8, 96), 256>>>();                // probs @ V
    wd_kernel<<<dim3(6, 4, 6), 256>>>(p);                // output projection
    ln_kernel<<<dim3(512, 6), 256>>>(hidden, p);         // residual + LN + weight
    colsum_kernel<<<dim3(3, 6), 256>>>(out);             // weighted mean -> out
}

// round 6
// speedup vs baseline: 4.0092x; 1.4020x over previous
#include <cuda_runtime.h>
#include <math.h>
#include <stdint.h>

#define SEQP 512
#define DIM 768
#define NH 16
#define DH 48
#define NF 2048
#define INV_SCALE 0.14433756729740643f  // 1/sqrt(768/16)

// ---------------- scratch: per-instance private, fully batched ----------------
__device__ float g_cnt[3 * 2 * SEQP];             // [b][0]=fpos counts, [b][1]=tpos counts
__device__ float g_QKV[6][SEQP][3 * DIM];         // per z6: Q | K | V(+bv)
__device__ float g_cb[6][SEQP][NH];               // cb[z6][t][h]
__device__ float g_scores[96][SEQP][SEQP];        // z96 = inst6*16 + h
__device__ float g_ctx[6][SEQP][DIM];
__device__ float g_dproj[6][SEQP][DIM];
__device__ float g_y[6][SEQP][DIM];

struct EncParams {
    const float *Wq[2], *Wk[2], *Wv[2], *Wcb[2], *Wd[2], *mix[2];
    const float *bv[2], *bd[2], *lng[2], *lnb[2];
};

// ---------------- counts ----------------
__global__ void zero_counts_kernel() {
    int i = blockIdx.x * blockDim.x + threadIdx.x;
    if (i < 3 * 2 * SEQP) g_cnt[i] = 0.f;
}

__global__ void count_kernel(const int* __restrict__ fpos, const int* __restrict__ tpos) {
    int i = blockIdx.x * blockDim.x + threadIdx.x;
    if (i >= 3 * NF) return;
    int b = i / NF;
    atomicAdd(&g_cnt[(b * 2 + 0) * SEQP + (fpos[i] & (SEQP - 1))], 1.f);
    atomicAdd(&g_cnt[(b * 2 + 1) * SEQP + (tpos[i] & (SEQP - 1))], 1.f);
}

// ---------------- 128x128x16 fp32 SGEMM core, 8x8/thread, C = A @ B^T (+bias) --
__device__ __forceinline__ void sgemm128(
    const float* __restrict__ A, int lda,
    const float* __restrict__ B, int ldb,
    float* __restrict__ C, int ldc,
    int K, const float* __restrict__ bias,
    int row0, int col0)
{
    __shared__ float As[16][132];
    __shared__ float Bs[16][132];
    const int tid = threadIdx.x;
    const int tx = tid & 15;
    const int ty = tid >> 4;
    const int lrow = tid >> 2;
    const int lc4  = tid & 3;

    float acc[8][8] = {};

    for (int k0 = 0; k0 < K; k0 += 16) {
#pragma unroll
        for (int r = 0; r < 2; r++) {
            int m = lrow + r * 64;
            float4 v = *(const float4*)(A + (long long)(row0 + m) * lda + k0 + lc4 * 4);
            As[lc4 * 4 + 0][m] = v.x; As[lc4 * 4 + 1][m] = v.y;
            As[lc4 * 4 + 2][m] = v.z; As[lc4 * 4 + 3][m] = v.w;
        }
#pragma unroll
        for (int r = 0; r < 2; r++) {
            int n = lrow + r * 64;
            float4 v = *(const float4*)(B + (long long)(col0 + n) * ldb + k0 + lc4 * 4);
            Bs[lc4 * 4 + 0][n] = v.x; Bs[lc4 * 4 + 1][n] = v.y;
            Bs[lc4 * 4 + 2][n] = v.z; Bs[lc4 * 4 + 3][n] = v.w;
        }
        __syncthreads();
#pragma unroll
        for (int kk = 0; kk < 16; kk++) {
            float a[8], bb[8];
            *(float4*)(a)      = *(const float4*)&As[kk][ty * 8];
            *(float4*)(a + 4)  = *(const float4*)&As[kk][ty * 8 + 4];
            *(float4*)(bb)     = *(const float4*)&Bs[kk][tx * 8];
            *(float4*)(bb + 4) = *(const float4*)&Bs[kk][tx * 8 + 4];
#pragma unroll
            for (int i = 0; i < 8; i++)
#pragma unroll
                for (int j = 0; j < 8; j++)
                    acc[i][j] = fmaf(a[i], bb[j], acc[i][j]);
        }
        __syncthreads();
    }

#pragma unroll
    for (int i = 0; i < 8; i++) {
        int gm = row0 + ty * 8 + i;
        float* crow = C + (long long)gm * ldc + col0 + tx * 8;
        float4 o0 = make_float4(acc[i][0], acc[i][1], acc[i][2], acc[i][3]);
        float4 o1 = make_float4(acc[i][4], acc[i][5], acc[i][6], acc[i][7]);
        if (bias) {
            const float* bp = bias + col0 + tx * 8;
            o0.x += bp[0]; o0.y += bp[1]; o0.z += bp[2]; o0.w += bp[3];
            o1.x += bp[4]; o1.y += bp[5]; o1.z += bp[6]; o1.w += bp[7];
        }
        *(float4*)crow = o0;
        *(float4*)(crow + 4) = o1;
    }
}

// ---------------- projections: QKV fused, batched over z6. grid (18,4,6) ------
__global__ __launch_bounds__(256, 2) void proj_kernel(const float* __restrict__ hidden,
                                                      EncParams p) {
    int z = blockIdx.z, inst = z & 1, b = z >> 1;
    int sector = blockIdx.x / 6;
    int colL = (blockIdx.x % 6) * 128;
    int row0 = blockIdx.y * 128;
    const float* A = hidden + (long long)b * SEQP * DIM;
    const float* W = sector == 0 ? p.Wq[inst] : sector == 1 ? p.Wk[inst] : p.Wv[inst];
    const float* bias = sector == 2 ? p.bv[inst] : nullptr;
    float* C = &g_QKV[z][0][sector * DIM];
    sgemm128(A, DIM, W, DIM, C, 3 * DIM, DIM, bias, row0, colL);
}

// ---------------- content bias. grid (512, 6), 128 threads ----------------
__global__ void cb_kernel(const float* __restrict__ hidden, EncParams p) {
    int z = blockIdx.y, inst = z & 1, b = z >> 1;
    const float* row = hidden + ((long long)b * SEQP + blockIdx.x) * DIM;
    __shared__ float sh[DIM];
    for (int i = threadIdx.x; i < DIM; i += 128) sh[i] = row[i];
    __syncthreads();
    int warp = threadIdx.x >> 5, lane = threadIdx.x & 31;
#pragma unroll
    for (int hh = 0; hh < 4; hh++) {
        int h = warp * 4 + hh;
        const float* w = p.Wcb[inst] + h * DIM;
        float s = 0.f;
        for (int i = lane; i < DIM; i += 32) s += sh[i] * w[i];
#pragma unroll
        for (int o = 16; o > 0; o >>= 1) s += __shfl_xor_sync(0xffffffffu, s, o);
        if (lane == 0) g_cb[z][blockIdx.x][h] = s;
    }
}

// ================= tf32 tensor-core scores kernel =================
__device__ __forceinline__ uint32_t f2tf32(float v) {
    uint32_t u;
    asm("cvt.rna.tf32.f32 %0, %1;" : "=r"(u) : "f"(v));
    return u;
}

__device__ __forceinline__ void mma_tf32(float* c, const uint32_t* a, const uint32_t* b) {
    asm volatile(
        "mma.sync.aligned.m16n8k8.row.col.f32.tf32.tf32.f32 "
        "{%0,%1,%2,%3}, {%4,%5,%6,%7}, {%8,%9}, {%0,%1,%2,%3};\n"
        : "+f"(c[0]), "+f"(c[1]), "+f"(c[2]), "+f"(c[3])
        : "r"(a[0]), "r"(a[1]), "r"(a[2]), "r"(a[3]), "r"(b[0]), "r"(b[1]));
}

// scores[z] = (Q*mix[h]) @ K^T, 128x128 block tile, 8 warps (2x4), 64x32 warp tile.
// grid (4, 4, 96), 256 threads.
__global__ __launch_bounds__(256) void scores_tf32_kernel(EncParams p) {
    int z = blockIdx.z;
    int inst6 = z >> 4, h = z & 15, inst = inst6 & 1;
    const float* A = &g_QKV[inst6][0][0];      // Q, lda 2304
    const float* B = &g_QKV[inst6][0][DIM];    // K, ldb 2304
    const float* mix = p.mix[inst] + h * DIM;
    float* C = &g_scores[z][0][0];
    const int row0 = blockIdx.y * 128, col0 = blockIdx.x * 128;

    __shared__ uint32_t As[16][132];
    __shared__ uint32_t Bs[16][132];

    const int tid = threadIdx.x;
    const int lane = tid & 31;
    const int g = lane >> 2, tig = lane & 3;
    const int warp = tid >> 5;
    const int wm0 = (warp >> 2) * 64;          // warp row origin (2 rows)
    const int wn0 = (warp & 3) * 32;           // warp col origin (4 cols)
    const int lrow = tid >> 2, lc4 = tid & 3;

    float acc[4][4][4] = {};

    for (int k0 = 0; k0 < DIM; k0 += 16) {
#pragma unroll
        for (int r = 0; r < 2; r++) {
            int m = lrow + r * 64;
            float4 v = *(const float4*)(A + (long long)(row0 + m) * (3 * DIM) + k0 + lc4 * 4);
            v.x *= mix[k0 + lc4 * 4 + 0];
            v.y *= mix[k0 + lc4 * 4 + 1];
            v.z *= mix[k0 + lc4 * 4 + 2];
            v.w *= mix[k0 + lc4 * 4 + 3];
            As[lc4 * 4 + 0][m] = f2tf32(v.x);
            As[lc4 * 4 + 1][m] = f2tf32(v.y);
            As[lc4 * 4 + 2][m] = f2tf32(v.z);
            As[lc4 * 4 + 3][m] = f2tf32(v.w);
        }
#pragma unroll
        for (int r = 0; r < 2; r++) {
            int n = lrow + r * 64;
            float4 v = *(const float4*)(B + (long long)(col0 + n) * (3 * DIM) + k0 + lc4 * 4);
            Bs[lc4 * 4 + 0][n] = f2tf32(v.x);
            Bs[lc4 * 4 + 1][n] = f2tf32(v.y);
            Bs[lc4 * 4 + 2][n] = f2tf32(v.z);
            Bs[lc4 * 4 + 3][n] = f2tf32(v.w);
        }
        __syncthreads();
#pragma unroll
        for (int ks = 0; ks < 2; ks++) {
            const int kb = ks * 8;
            uint32_t af[4][4], bf[4][2];
#pragma unroll
            for (int i = 0; i < 4; i++) {
                int m = wm0 + i * 16 + g;
                af[i][0] = As[kb + tig][m];
                af[i][1] = As[kb + tig][m + 8];
                af[i][2] = As[kb + tig + 4][m];
                af[i][3] = As[kb + tig + 4][m + 8];
            }
#pragma unroll
            for (int j = 0; j < 4; j++) {
                int n = wn0 + j * 8 + g;
                bf[j][0] = Bs[kb + tig][n];
                bf[j][1] = Bs[kb + tig + 4][n];
            }
#pragma unroll
            for (int i = 0; i < 4; i++)
#pragma unroll
                for (int j = 0; j < 4; j++)
                    mma_tf32(acc[i][j], af[i], bf[j]);
        }
        __syncthreads();
    }

#pragma unroll
    for (int i = 0; i < 4; i++) {
        int m = row0 + wm0 + i * 16 + g;
#pragma unroll
        for (int j = 0; j < 4; j++) {
            int n = col0 + wn0 + j * 8 + tig * 2;
            *(float2*)&C[(long long)m * SEQP + n]       = make_float2(acc[i][j][0], acc[i][j][1]);
            *(float2*)&C[(long long)(m + 8) * SEQP + n] = make_float2(acc[i][j][2], acc[i][j][3]);
        }
    }
}

// ---------------- block reductions ----------------
__device__ __forceinline__ float blockReduceMax(float v) {
    __shared__ float sh[8];
    __shared__ float res;
#pragma unroll
    for (int o = 16; o > 0; o >>= 1) v = fmaxf(v, __shfl_xor_sync(0xffffffffu, v, o));
    __syncthreads();
    if ((threadIdx.x & 31) == 0) sh[threadIdx.x >> 5] = v;
    __syncthreads();
    if (threadIdx.x == 0) {
        float m = sh[0];
        for (int i = 1; i < 8; i++) m = fmaxf(m, sh[i]);
        res = m;
    }
    __syncthreads();
    return res;
}

__device__ __forceinline__ float blockReduceSum(float v) {
    __shared__ float sh[8];
    __shared__ float res;
#pragma unroll
    for (int o = 16; o > 0; o >>= 1) v += __shfl_xor_sync(0xffffffffu, v, o);
    __syncthreads();
    if ((threadIdx.x & 31) == 0) sh[threadIdx.x >> 5] = v;
    __syncthreads();
    if (threadIdx.x == 0) {
        float s = 0.f;
        for (int i = 0; i < 8; i++) s += sh[i];
        res = s;
    }
    __syncthreads();
    return res;
}

// ---------------- count-weighted softmax, in place. grid (512, 96), 256 thr ----
__global__ void softmax_kernel() {
    int p_ = blockIdx.x, z = blockIdx.y;
    int inst6 = z >> 4, h = z & 15, inst = inst6 & 1, b = inst6 >> 1;
    const float* kcnt = g_cnt + (b * 2 + (1 - inst)) * SEQP;
    float* row = &g_scores[z][p_][0];
    int t0 = threadIdx.x, t1 = threadIdx.x + 256;
    float s0 = (row[t0] + g_cb[inst6][t0][h]) * INV_SCALE;
    float s1 = (row[t1] + g_cb[inst6][t1][h]) * INV_SCALE;
    float m = blockReduceMax(fmaxf(s0, s1));
    float w0 = kcnt[t0] * expf(s0 - m);
    float w1 = kcnt[t1] * expf(s1 - m);
    float inv = 1.f / blockReduceSum(w0 + w1);
    row[t0] = w0 * inv;
    row[t1] = w1 * inv;
}

// ---------------- PV: ctx[:, h*48:+48] = probs[z] @ V. grid (1, 8, 96) --------
__global__ void pv_kernel() {
    int z = blockIdx.z, inst6 = z >> 4, h = z & 15;
    const float* A = &g_scores[z][0][0];                 // [512,512]
    const float* B = &g_QKV[inst6][0][2 * DIM + h * DH]; // [512 k-rows], ldb 2304
    float* C = &g_ctx[inst6][0][h * DH];                 // ldc 768
    __shared__ float As[16][64];
    __shared__ float Bs[16][64];
    int tx = threadIdx.x & 15, ty = threadIdx.x >> 4;
    int row0 = blockIdx.y * 64;
    float acc[4][4] = {};

    for (int k0 = 0; k0 < SEQP; k0 += 16) {
#pragma unroll
        for (int i = 0; i < 4; i++) {
            int idx = threadIdx.x + i * 256;
            int m = idx >> 4, kk = idx & 15;
            As[kk][m] = A[(long long)(row0 + m) * SEQP + k0 + kk];
        }
#pragma unroll
        for (int i = 0; i < 4; i++) {
            int idx = threadIdx.x + i * 256;
            int kk = idx >> 6, n = idx & 63;
            Bs[kk][n] = (n < DH) ? B[(long long)(k0 + kk) * (3 * DIM) + n] : 0.f;
        }
        __syncthreads();
#pragma unroll
        for (int kk = 0; kk < 16; kk++) {
            float a[4], bb[4];
#pragma unroll
            for (int i = 0; i < 4; i++) a[i] = As[kk][ty * 4 + i];
#pragma unroll
            for (int j = 0; j < 4; j++) bb[j] = Bs[kk][tx * 4 + j];
#pragma unroll
            for (int i = 0; i < 4; i++)
#pragma unroll
                for (int j = 0; j < 4; j++) acc[i][j] = fmaf(a[i], bb[j], acc[i][j]);
        }
        __syncthreads();
    }
#pragma unroll
    for (int i = 0; i < 4; i++) {
        int gm = row0 + ty * 4 + i;
#pragma unroll
        for (int j = 0; j < 4; j++) {
            int gn = tx * 4 + j;
            if (gn < DH) C[(long long)gm * DIM + gn] = acc[i][j];
        }
    }
}

// ---------------- output projection: dproj = ctx @ Wd^T + bd. grid (6,4,6) ----
__global__ __launch_bounds__(256, 2) void wd_kernel(EncParams p) {
    int z = blockIdx.z, inst = z & 1;
    sgemm128(&g_ctx[z][0][0], DIM, p.Wd[inst], DIM, &g_dproj[z][0][0], DIM,
             DIM, p.bd[inst], blockIdx.y * 128, blockIdx.x * 128);
}

// ---------------- residual + LN + count weighting. grid (512, 6), 256 thr -----
__global__ void ln_kernel(const float* __restrict__ hidden, EncParams p) {
    int pos = blockIdx.x, z = blockIdx.y, inst = z & 1, b = z >> 1;
    const float* hr = hidden + ((long long)b * SEQP + pos) * DIM;
    const float* dr = &g_dproj[z][pos][0];
    const float* lng = p.lng[inst];
    const float* lnb = p.lnb[inst];
    float x[3];
    float s = 0.f;
#pragma unroll
    for (int i = 0; i < 3; i++) {
        int j = threadIdx.x + i * 256;
        x[i] = hr[j] + dr[j];
        s += x[i];
    }
    float mu = blockReduceSum(s) * (1.f / DIM);
    float vs = 0.f;
#pragma unroll
    for (int i = 0; i < 3; i++) {
        float d = x[i] - mu;
        vs += d * d;
    }
    float var = blockReduceSum(vs) * (1.f / DIM);
    float inv = rsqrtf(var + 1e-5f);
    float w = g_cnt[(b * 2 + inst) * SEQP + pos] * (1.f / 2048.f);
#pragma unroll
    for (int i = 0; i < 3; i++) {
        int j = threadIdx.x + i * 256;
        g_y[z][pos][j] = (lng[j] * (x[i] - mu) * inv + lnb[j]) * w;
    }
}

// ---------------- column sum -> output. grid (3, 6), 256 thr ----------------
__global__ void colsum_kernel(float* __restrict__ out) {
    int z = blockIdx.y;
    int j = blockIdx.x * 256 + threadIdx.x;
    const float* Y = &g_y[z][0][0];
    float s = 0.f;
#pragma unroll 8
    for (int p = 0; p < SEQP; p++) s += Y[(long long)p * DIM + j];
    out[(z >> 1) * 2 * DIM + (z & 1) * DIM + j] = s;
}

// ---------------- host ----------------
extern "C" void kernel_launch(void* const* d_in, const int* in_sizes, int n_in,
                              void* d_out, int out_size) {
    const float* hidden = (const float*)d_in[0];
    const int* fpos = (const int*)d_in[1];
    const int* tpos = (const int*)d_in[2];
    float* out = (float*)d_out;

    EncParams p;
    for (int inst = 0; inst < 2; inst++) {
        void* const* P = d_in + 3 + inst * 10;
        p.Wq[inst]  = (const float*)P[0];
        p.Wk[inst]  = (const float*)P[1];
        p.Wcb[inst] = (const float*)P[2];
        p.Wv[inst]  = (const float*)P[3];
        p.Wd[inst]  = (const float*)P[4];
        p.mix[inst] = (const float*)P[5];
        p.bv[inst]  = (const float*)P[6];
        p.bd[inst]  = (const float*)P[7];
        p.lng[inst] = (const float*)P[8];
        p.lnb[inst] = (const float*)P[9];
    }

    zero_counts_kernel<<<6, 512>>>();
    count_kernel<<<(3 * NF + 255) / 256, 256>>>(fpos, tpos);

    proj_kernel<<<dim3(18, 4, 6), 256>>>(hidden, p);     // QKV for all 6 instances
    cb_kernel<<<dim3(512, 6), 128>>>(hidden, p);         // content bias
    scores_tf32_kernel<<<dim3(4, 4, 96), 256>>>(p);      // tf32 tensor-core scores
    softmax_kernel<<<dim3(512, 96), 256>>>();            // count-weighted softmax
    pv_kernel<<<dim3(1, 8, 96), 256>>>();                // probs @ V
    wd_kernel<<<dim3(6, 4, 6), 256>>>(p);                // output projection
    ln_kernel<<<dim3(512, 6), 256>>>(hidden, p);         // residual + LN + weight
    colsum_kernel<<<dim3(3, 6), 256>>>(out);             // weighted mean -> out
}

// round 7
// speedup vs baseline: 5.2321x; 1.3050x over previous
#include <cuda_runtime.h>
#include <math.h>
#include <stdint.h>

#define SEQP 512
#define DIM 768
#define NH 16
#define DH 48
#define NF 2048
#define INV_SCALE 0.14433756729740643f  // 1/sqrt(768/16)

// ---------------- scratch ----------------
__device__ float g_cnt[3 * 2 * SEQP];
__device__ float g_QKV[6][SEQP][3 * DIM];         // per z6: Q | K | V(+bv)
__device__ float g_cb[6][SEQP][NH];
__device__ float g_scores[96][SEQP][SEQP];        // z96 = inst6*16 + h
__device__ float g_ctx[6][SEQP][DIM];
__device__ float g_dproj[6][SEQP][DIM];
__device__ float g_y[6][SEQP][DIM];

struct EncParams {
    const float *Wq[2], *Wk[2], *Wv[2], *Wcb[2], *Wd[2], *mix[2];
    const float *bv[2], *bd[2], *lng[2], *lnb[2];
};

// ---------------- counts ----------------
__global__ void zero_counts_kernel() {
    int i = blockIdx.x * blockDim.x + threadIdx.x;
    if (i < 3 * 2 * SEQP) g_cnt[i] = 0.f;
}

__global__ void count_kernel(const int* __restrict__ fpos, const int* __restrict__ tpos) {
    int i = blockIdx.x * blockDim.x + threadIdx.x;
    if (i >= 3 * NF) return;
    int b = i / NF;
    atomicAdd(&g_cnt[(b * 2 + 0) * SEQP + (fpos[i] & (SEQP - 1))], 1.f);
    atomicAdd(&g_cnt[(b * 2 + 1) * SEQP + (tpos[i] & (SEQP - 1))], 1.f);
}

// ================= tf32 mma primitives =================
__device__ __forceinline__ uint32_t f2tf32(float v) {
    uint32_t u;
    asm("cvt.rna.tf32.f32 %0, %1;" : "=r"(u) : "f"(v));
    return u;
}

__device__ __forceinline__ void mma_tf32(float* c, const uint32_t* a, const uint32_t* b) {
    asm volatile(
        "mma.sync.aligned.m16n8k8.row.col.f32.tf32.tf32.f32 "
        "{%0,%1,%2,%3}, {%4,%5,%6,%7}, {%8,%9}, {%0,%1,%2,%3};\n"
        : "+f"(c[0]), "+f"(c[1]), "+f"(c[2]), "+f"(c[3])
        : "r"(a[0]), "r"(a[1]), "r"(a[2]), "r"(a[3]), "r"(b[0]), "r"(b[1]));
}

// --------- generic 128x128 tf32 GEMM tile: C = A @ B^T (+bias, optional A-mix) ----
// 256 threads = 8 warps (2x4), warp tile 64x32. K multiple of 16, float4-aligned rows.
template <bool HAS_MIX, bool HAS_BIAS>
__device__ __forceinline__ void tf32_gemm128(
    const float* __restrict__ A, int lda,
    const float* __restrict__ B, int ldb,
    float* __restrict__ C, int ldc,
    int K, const float* __restrict__ bias, const float* __restrict__ mix,
    int row0, int col0)
{
    __shared__ uint32_t As[16][132];
    __shared__ uint32_t Bs[16][132];

    const int tid = threadIdx.x;
    const int lane = tid & 31;
    const int g = lane >> 2, tig = lane & 3;
    const int warp = tid >> 5;
    const int wm0 = (warp >> 2) * 64;
    const int wn0 = (warp & 3) * 32;
    const int lrow = tid >> 2, lc4 = tid & 3;

    float acc[4][4][4] = {};

    for (int k0 = 0; k0 < K; k0 += 16) {
#pragma unroll
        for (int r = 0; r < 2; r++) {
            int m = lrow + r * 64;
            float4 v = *(const float4*)(A + (long long)(row0 + m) * lda + k0 + lc4 * 4);
            if (HAS_MIX) {
                v.x *= mix[k0 + lc4 * 4 + 0];
                v.y *= mix[k0 + lc4 * 4 + 1];
                v.z *= mix[k0 + lc4 * 4 + 2];
                v.w *= mix[k0 + lc4 * 4 + 3];
            }
            As[lc4 * 4 + 0][m] = f2tf32(v.x);
            As[lc4 * 4 + 1][m] = f2tf32(v.y);
            As[lc4 * 4 + 2][m] = f2tf32(v.z);
            As[lc4 * 4 + 3][m] = f2tf32(v.w);
        }
#pragma unroll
        for (int r = 0; r < 2; r++) {
            int n = lrow + r * 64;
            float4 v = *(const float4*)(B + (long long)(col0 + n) * ldb + k0 + lc4 * 4);
            Bs[lc4 * 4 + 0][n] = f2tf32(v.x);
            Bs[lc4 * 4 + 1][n] = f2tf32(v.y);
            Bs[lc4 * 4 + 2][n] = f2tf32(v.z);
            Bs[lc4 * 4 + 3][n] = f2tf32(v.w);
        }
        __syncthreads();
#pragma unroll
        for (int ks = 0; ks < 2; ks++) {
            const int kb = ks * 8;
            uint32_t af[4][4], bf[4][2];
#pragma unroll
            for (int i = 0; i < 4; i++) {
                int m = wm0 + i * 16 + g;
                af[i][0] = As[kb + tig][m];
                af[i][1] = As[kb + tig][m + 8];
                af[i][2] = As[kb + tig + 4][m];
                af[i][3] = As[kb + tig + 4][m + 8];
            }
#pragma unroll
            for (int j = 0; j < 4; j++) {
                int n = wn0 + j * 8 + g;
                bf[j][0] = Bs[kb + tig][n];
                bf[j][1] = Bs[kb + tig + 4][n];
            }
#pragma unroll
            for (int i = 0; i < 4; i++)
#pragma unroll
                for (int j = 0; j < 4; j++)
                    mma_tf32(acc[i][j], af[i], bf[j]);
        }
        __syncthreads();
    }

#pragma unroll
    for (int i = 0; i < 4; i++) {
        int m = row0 + wm0 + i * 16 + g;
#pragma unroll
        for (int j = 0; j < 4; j++) {
            int n = col0 + wn0 + j * 8 + tig * 2;
            float2 lo = make_float2(acc[i][j][0], acc[i][j][1]);
            float2 hi = make_float2(acc[i][j][2], acc[i][j][3]);
            if (HAS_BIAS) {
                float2 bb = *(const float2*)&bias[n];
                lo.x += bb.x; lo.y += bb.y;
                hi.x += bb.x; hi.y += bb.y;
            }
            *(float2*)&C[(long long)m * ldc + n]       = lo;
            *(float2*)&C[(long long)(m + 8) * ldc + n] = hi;
        }
    }
}

// ---------------- projections (tf32): QKV fused. grid (18,4,6), 256 thr -------
__global__ __launch_bounds__(256) void proj_kernel(const float* __restrict__ hidden,
                                                   EncParams p) {
    int z = blockIdx.z, inst = z & 1, b = z >> 1;
    int sector = blockIdx.x / 6;
    int colL = (blockIdx.x % 6) * 128;
    int row0 = blockIdx.y * 128;
    const float* A = hidden + (long long)b * SEQP * DIM;
    const float* W = sector == 0 ? p.Wq[inst] : sector == 1 ? p.Wk[inst] : p.Wv[inst];
    float* C = &g_QKV[z][0][sector * DIM];
    if (sector == 2)
        tf32_gemm128<false, true>(A, DIM, W, DIM, C, 3 * DIM, DIM, p.bv[inst], nullptr, row0, colL);
    else
        tf32_gemm128<false, false>(A, DIM, W, DIM, C, 3 * DIM, DIM, nullptr, nullptr, row0, colL);
}

// ---------------- content bias. grid (512, 6), 128 threads ----------------
__global__ void cb_kernel(const float* __restrict__ hidden, EncParams p) {
    int z = blockIdx.y, inst = z & 1, b = z >> 1;
    const float* row = hidden + ((long long)b * SEQP + blockIdx.x) * DIM;
    __shared__ float sh[DIM];
    for (int i = threadIdx.x; i < DIM; i += 128) sh[i] = row[i];
    __syncthreads();
    int warp = threadIdx.x >> 5, lane = threadIdx.x & 31;
#pragma unroll
    for (int hh = 0; hh < 4; hh++) {
        int h = warp * 4 + hh;
        const float* w = p.Wcb[inst] + h * DIM;
        float s = 0.f;
        for (int i = lane; i < DIM; i += 32) s += sh[i] * w[i];
#pragma unroll
        for (int o = 16; o > 0; o >>= 1) s += __shfl_xor_sync(0xffffffffu, s, o);
        if (lane == 0) g_cb[z][blockIdx.x][h] = s;
    }
}

// ---------------- scores (tf32): (Q*mix[h]) @ K^T. grid (4,4,96), 256 thr -----
__global__ __launch_bounds__(256) void scores_kernel(EncParams p) {
    int z = blockIdx.z;
    int inst6 = z >> 4, h = z & 15, inst = inst6 & 1;
    tf32_gemm128<true, false>(&g_QKV[inst6][0][0], 3 * DIM,
                              &g_QKV[inst6][0][DIM], 3 * DIM,
                              &g_scores[z][0][0], SEQP, DIM,
                              nullptr, p.mix[inst] + h * DIM,
                              blockIdx.y * 128, blockIdx.x * 128);
}

// ---------------- count-weighted softmax, warp-per-row. grid (64, 96), 256 thr -
__global__ void softmax_kernel() {
    int z = blockIdx.y;
    int inst6 = z >> 4, h = z & 15, inst = inst6 & 1, b = inst6 >> 1;
    const float* kcnt = g_cnt + (b * 2 + (1 - inst)) * SEQP;
    int warp = threadIdx.x >> 5, lane = threadIdx.x & 31;
    int r = blockIdx.x * 8 + warp;
    float* row = &g_scores[z][r][0];

    float s[16];
    float m = -1e30f;
#pragma unroll
    for (int j = 0; j < 4; j++) {
        int t = (lane + j * 32) * 4;
        float4 x = *(const float4*)&row[t];
        s[j * 4 + 0] = (x.x + g_cb[inst6][t + 0][h]) * INV_SCALE;
        s[j * 4 + 1] = (x.y + g_cb[inst6][t + 1][h]) * INV_SCALE;
        s[j * 4 + 2] = (x.z + g_cb[inst6][t + 2][h]) * INV_SCALE;
        s[j * 4 + 3] = (x.w + g_cb[inst6][t + 3][h]) * INV_SCALE;
#pragma unroll
        for (int c = 0; c < 4; c++) m = fmaxf(m, s[j * 4 + c]);
    }
#pragma unroll
    for (int o = 16; o > 0; o >>= 1) m = fmaxf(m, __shfl_xor_sync(0xffffffffu, m, o));

    float w[16];
    float sum = 0.f;
#pragma unroll
    for (int j = 0; j < 4; j++) {
        int t = (lane + j * 32) * 4;
        float4 c4 = *(const float4*)&kcnt[t];
        w[j * 4 + 0] = c4.x * __expf(s[j * 4 + 0] - m);
        w[j * 4 + 1] = c4.y * __expf(s[j * 4 + 1] - m);
        w[j * 4 + 2] = c4.z * __expf(s[j * 4 + 2] - m);
        w[j * 4 + 3] = c4.w * __expf(s[j * 4 + 3] - m);
        sum += w[j * 4 + 0] + w[j * 4 + 1] + w[j * 4 + 2] + w[j * 4 + 3];
    }
#pragma unroll
    for (int o = 16; o > 0; o >>= 1) sum += __shfl_xor_sync(0xffffffffu, sum, o);
    float inv = 1.f / sum;
#pragma unroll
    for (int j = 0; j < 4; j++) {
        int t = (lane + j * 32) * 4;
        *(float4*)&row[t] = make_float4(w[j * 4 + 0] * inv, w[j * 4 + 1] * inv,
                                        w[j * 4 + 2] * inv, w[j * 4 + 3] * inv);
    }
}

// ---------------- PV (tf32): ctx[:, h*48:+48] = probs[z] @ V. grid (4, 96) ----
// 128x48 block tile, 8 warps (4x2), warp tile 32x24 (2 m-frags x 3 n-frags).
__global__ __launch_bounds__(256) void pv_kernel() {
    int z = blockIdx.y, inst6 = z >> 4, h = z & 15;
    const float* A = &g_scores[z][0][0];                 // [512,512] probs
    const float* B = &g_QKV[inst6][0][2 * DIM + h * DH]; // V block [512 x 48], ldb 2304
    float* C = &g_ctx[inst6][0][h * DH];                 // ldc 768
    const int row0 = blockIdx.x * 128;

    __shared__ uint32_t As[16][132];
    __shared__ uint32_t Bs[16][56];

    const int tid = threadIdx.x;
    const int lane = tid & 31;
    const int g = lane >> 2, tig = lane & 3;
    const int warp = tid >> 5;
    const int wm0 = (warp >> 1) * 32;
    const int wn0 = (warp & 1) * 24;
    const int lrow = tid >> 2, lc4 = tid & 3;

    float acc[2][3][4] = {};

    for (int k0 = 0; k0 < SEQP; k0 += 16) {
#pragma unroll
        for (int r = 0; r < 2; r++) {
            int m = lrow + r * 64;
            float4 v = *(const float4*)(A + (long long)(row0 + m) * SEQP + k0 + lc4 * 4);
            As[lc4 * 4 + 0][m] = f2tf32(v.x);
            As[lc4 * 4 + 1][m] = f2tf32(v.y);
            As[lc4 * 4 + 2][m] = f2tf32(v.z);
            As[lc4 * 4 + 3][m] = f2tf32(v.w);
        }
        if (tid < 192) {
            int kr = tid / 12, c4 = tid % 12;
            float4 v = *(const float4*)(B + (long long)(k0 + kr) * (3 * DIM) + c4 * 4);
            Bs[kr][c4 * 4 + 0] = f2tf32(v.x);
            Bs[kr][c4 * 4 + 1] = f2tf32(v.y);
            Bs[kr][c4 * 4 + 2] = f2tf32(v.z);
            Bs[kr][c4 * 4 + 3] = f2tf32(v.w);
        }
        __syncthreads();
#pragma unroll
        for (int ks = 0; ks < 2; ks++) {
            const int kb = ks * 8;
            uint32_t af[2][4], bf[3][2];
#pragma unroll
            for (int i = 0; i < 2; i++) {
                int m = wm0 + i * 16 + g;
                af[i][0] = As[kb + tig][m];
                af[i][1] = As[kb + tig][m + 8];
                af[i][2] = As[kb + tig + 4][m];
                af[i][3] = As[kb + tig + 4][m + 8];
            }
#pragma unroll
            for (int j = 0; j < 3; j++) {
                int n = wn0 + j * 8 + g;
                // B fragment: element (k, n) with n-major registers -> Bs[k][n]
                bf[j][0] = Bs[kb + tig][n];
                bf[j][1] = Bs[kb + tig + 4][n];
            }
#pragma unroll
            for (int i = 0; i < 2; i++)
#pragma unroll
                for (int j = 0; j < 3; j++)
                    mma_tf32(acc[i][j], af[i], bf[j]);
        }
        __syncthreads();
    }

#pragma unroll
    for (int i = 0; i < 2; i++) {
        int m = row0 + wm0 + i * 16 + g;
#pragma unroll
        for (int j = 0; j < 3; j++) {
            int n = wn0 + j * 8 + tig * 2;
            *(float2*)&C[(long long)m * DIM + n]       = make_float2(acc[i][j][0], acc[i][j][1]);
            *(float2*)&C[(long long)(m + 8) * DIM + n] = make_float2(acc[i][j][2], acc[i][j][3]);
        }
    }
}

// ---------------- output projection (tf32). grid (6,4,6), 256 thr -------------
__global__ __launch_bounds__(256) void wd_kernel(EncParams p) {
    int z = blockIdx.z, inst = z & 1;
    tf32_gemm128<false, true>(&g_ctx[z][0][0], DIM, p.Wd[inst], DIM,
                              &g_dproj[z][0][0], DIM, DIM, p.bd[inst], nullptr,
                              blockIdx.y * 128, blockIdx.x * 128);
}

// ---------------- block reduce (for LN) ----------------
__device__ __forceinline__ float blockReduceSum(float v) {
    __shared__ float sh[8];
    __shared__ float res;
#pragma unroll
    for (int o = 16; o > 0; o >>= 1) v += __shfl_xor_sync(0xffffffffu, v, o);
    __syncthreads();
    if ((threadIdx.x & 31) == 0) sh[threadIdx.x >> 5] = v;
    __syncthreads();
    if (threadIdx.x == 0) {
        float s = 0.f;
        for (int i = 0; i < 8; i++) s += sh[i];
        res = s;
    }
    __syncthreads();
    return res;
}

// ---------------- residual + LN + count weighting. grid (512, 6), 256 thr -----
__global__ void ln_kernel(const float* __restrict__ hidden, EncParams p) {
    int pos = blockIdx.x, z = blockIdx.y, inst = z & 1, b = z >> 1;
    const float* hr = hidden + ((long long)b * SEQP + pos) * DIM;
    const float* dr = &g_dproj[z][pos][0];
    const float* lng = p.lng[inst];
    const float* lnb = p.lnb[inst];
    float x[3];
    float s = 0.f;
#pragma unroll
    for (int i = 0; i < 3; i++) {
        int j = threadIdx.x + i * 256;
        x[i] = hr[j] + dr[j];
        s += x[i];
    }
    float mu = blockReduceSum(s) * (1.f / DIM);
    float vs = 0.f;
#pragma unroll
    for (int i = 0; i < 3; i++) {
        float d = x[i] - mu;
        vs += d * d;
    }
    float var = blockReduceSum(vs) * (1.f / DIM);
    float inv = rsqrtf(var + 1e-5f);
    float w = g_cnt[(b * 2 + inst) * SEQP + pos] * (1.f / 2048.f);
#pragma unroll
    for (int i = 0; i < 3; i++) {
        int j = threadIdx.x + i * 256;
        g_y[z][pos][j] = (lng[j] * (x[i] - mu) * inv + lnb[j]) * w;
    }
}

// ---------------- column sum -> output. grid (3, 6), 256 thr ----------------
__global__ void colsum_kernel(float* __restrict__ out) {
    int z = blockIdx.y;
    int j = blockIdx.x * 256 + threadIdx.x;
    const float* Y = &g_y[z][0][0];
    float s = 0.f;
#pragma unroll 8
    for (int p = 0; p < SEQP; p++) s += Y[(long long)p * DIM + j];
    out[(z >> 1) * 2 * DIM + (z & 1) * DIM + j] = s;
}

// ---------------- host ----------------
extern "C" void kernel_launch(void* const* d_in, const int* in_sizes, int n_in,
                              void* d_out, int out_size) {
    const float* hidden = (const float*)d_in[0];
    const int* fpos = (const int*)d_in[1];
    const int* tpos = (const int*)d_in[2];
    float* out = (float*)d_out;

    EncParams p;
    for (int inst = 0; inst < 2; inst++) {
        void* const* P = d_in + 3 + inst * 10;
        p.Wq[inst]  = (const float*)P[0];
        p.Wk[inst]  = (const float*)P[1];
        p.Wcb[inst] = (const float*)P[2];
        p.Wv[inst]  = (const float*)P[3];
        p.Wd[inst]  = (const float*)P[4];
        p.mix[inst] = (const float*)P[5];
        p.bv[inst]  = (const float*)P[6];
        p.bd[inst]  = (const float*)P[7];
        p.lng[inst] = (const float*)P[8];
        p.lnb[inst] = (const float*)P[9];
    }

    zero_counts_kernel<<<6, 512>>>();
    count_kernel<<<(3 * NF + 255) / 256, 256>>>(fpos, tpos);

    proj_kernel<<<dim3(18, 4, 6), 256>>>(hidden, p);     // QKV tf32
    cb_kernel<<<dim3(512, 6), 128>>>(hidden, p);         // content bias
    scores_kernel<<<dim3(4, 4, 96), 256>>>(p);           // tf32 scores
    softmax_kernel<<<dim3(64, 96), 256>>>();             // warp-per-row softmax
    pv_kernel<<<dim3(4, 96), 256>>>();                   // tf32 probs @ V
    wd_kernel<<<dim3(6, 4, 6), 256>>>(p);                // tf32 output projection
    ln_kernel<<<dim3(512, 6), 256>>>(hidden, p);         // residual + LN + weight
    colsum_kernel<<<dim3(3, 6), 256>>>(out);             // weighted mean -> out
}

// round 8
// speedup vs baseline: 7.1021x; 1.3574x over previous
#include <cuda_runtime.h>
#include <cuda_bf16.h>
#include <math.h>
#include <stdint.h>

#define SEQP 512
#define DIM 768
#define NH 16
#define DH 48
#define NF 2048
#define INV_SCALE 0.14433756729740643f  // 1/sqrt(768/16)

// ---------------- scratch ----------------
__device__ float g_cnt[3 * 2 * SEQP];
__device__ float g_QKV[6][SEQP][3 * DIM];         // per z6: Q | K | V(+bv)
__device__ float g_cb[6][SEQP][NH];
__device__ float g_scores[96][SEQP][SEQP];        // z96 = inst6*16 + h
__device__ float g_ctx[6][SEQP][DIM];
__device__ float g_dproj[6][SEQP][DIM];
__device__ float g_y[6][SEQP][DIM];

struct EncParams {
    const float *Wq[2], *Wk[2], *Wv[2], *Wcb[2], *Wd[2], *mix[2];
    const float *bv[2], *bd[2], *lng[2], *lnb[2];
};

// ---------------- counts ----------------
__global__ void zero_counts_kernel() {
    int i = blockIdx.x * blockDim.x + threadIdx.x;
    if (i < 3 * 2 * SEQP) g_cnt[i] = 0.f;
}

__global__ void count_kernel(const int* __restrict__ fpos, const int* __restrict__ tpos) {
    int i = blockIdx.x * blockDim.x + threadIdx.x;
    if (i >= 3 * NF) return;
    int b = i / NF;
    atomicAdd(&g_cnt[(b * 2 + 0) * SEQP + (fpos[i] & (SEQP - 1))], 1.f);
    atomicAdd(&g_cnt[(b * 2 + 1) * SEQP + (tpos[i] & (SEQP - 1))], 1.f);
}

// ================= mma primitives =================
__device__ __forceinline__ uint32_t f2tf32(float v) {
    uint32_t u;
    asm("cvt.rna.tf32.f32 %0, %1;" : "=r"(u) : "f"(v));
    return u;
}

__device__ __forceinline__ void mma_tf32(float* c, const uint32_t* a, const uint32_t* b) {
    asm volatile(
        "mma.sync.aligned.m16n8k8.row.col.f32.tf32.tf32.f32 "
        "{%0,%1,%2,%3}, {%4,%5,%6,%7}, {%8,%9}, {%0,%1,%2,%3};\n"
        : "+f"(c[0]), "+f"(c[1]), "+f"(c[2]), "+f"(c[3])
        : "r"(a[0]), "r"(a[1]), "r"(a[2]), "r"(a[3]), "r"(b[0]), "r"(b[1]));
}

__device__ __forceinline__ void mma_bf16(float* c, const uint32_t* a, const uint32_t* b) {
    asm volatile(
        "mma.sync.aligned.m16n8k16.row.col.f32.bf16.bf16.f32 "
        "{%0,%1,%2,%3}, {%4,%5,%6,%7}, {%8,%9}, {%0,%1,%2,%3};\n"
        : "+f"(c[0]), "+f"(c[1]), "+f"(c[2]), "+f"(c[3])
        : "r"(a[0]), "r"(a[1]), "r"(a[2]), "r"(a[3]), "r"(b[0]), "r"(b[1]));
}

__device__ __forceinline__ uint32_t packbf(float x, float y) {
    __nv_bfloat162 h = __float22bfloat162_rn(make_float2(x, y));
    return *(uint32_t*)&h;
}

// --------- generic 128x128 tf32 GEMM tile: C = A @ B^T (+bias) ----
// 256 threads = 8 warps (2x4), warp tile 64x32.
template <bool HAS_BIAS>
__device__ __forceinline__ void tf32_gemm128(
    const float* __restrict__ A, int lda,
    const float* __restrict__ B, int ldb,
    float* __restrict__ C, int ldc,
    int K, const float* __restrict__ bias,
    int row0, int col0)
{
    __shared__ uint32_t As[16][132];
    __shared__ uint32_t Bs[16][132];

    const int tid = threadIdx.x;
    const int lane = tid & 31;
    const int g = lane >> 2, tig = lane & 3;
    const int warp = tid >> 5;
    const int wm0 = (warp >> 2) * 64;
    const int wn0 = (warp & 3) * 32;
    const int lrow = tid >> 2, lc4 = tid & 3;

    float acc[4][4][4] = {};

    for (int k0 = 0; k0 < K; k0 += 16) {
#pragma unroll
        for (int r = 0; r < 2; r++) {
            int m = lrow + r * 64;
            float4 v = *(const float4*)(A + (long long)(row0 + m) * lda + k0 + lc4 * 4);
            As[lc4 * 4 + 0][m] = f2tf32(v.x);
            As[lc4 * 4 + 1][m] = f2tf32(v.y);
            As[lc4 * 4 + 2][m] = f2tf32(v.z);
            As[lc4 * 4 + 3][m] = f2tf32(v.w);
            float4 w = *(const float4*)(B + (long long)(col0 + m) * ldb + k0 + lc4 * 4);
            Bs[lc4 * 4 + 0][m] = f2tf32(w.x);
            Bs[lc4 * 4 + 1][m] = f2tf32(w.y);
            Bs[lc4 * 4 + 2][m] = f2tf32(w.z);
            Bs[lc4 * 4 + 3][m] = f2tf32(w.w);
        }
        __syncthreads();
#pragma unroll
        for (int ks = 0; ks < 2; ks++) {
            const int kb = ks * 8;
            uint32_t af[4][4], bf[4][2];
#pragma unroll
            for (int i = 0; i < 4; i++) {
                int m = wm0 + i * 16 + g;
                af[i][0] = As[kb + tig][m];
                af[i][1] = As[kb + tig][m + 8];
                af[i][2] = As[kb + tig + 4][m];
                af[i][3] = As[kb + tig + 4][m + 8];
            }
#pragma unroll
            for (int j = 0; j < 4; j++) {
                int n = wn0 + j * 8 + g;
                bf[j][0] = Bs[kb + tig][n];
                bf[j][1] = Bs[kb + tig + 4][n];
            }
#pragma unroll
            for (int i = 0; i < 4; i++)
#pragma unroll
                for (int j = 0; j < 4; j++)
                    mma_tf32(acc[i][j], af[i], bf[j]);
        }
        __syncthreads();
    }

#pragma unroll
    for (int i = 0; i < 4; i++) {
        int m = row0 + wm0 + i * 16 + g;
#pragma unroll
        for (int j = 0; j < 4; j++) {
            int n = col0 + wn0 + j * 8 + tig * 2;
            float2 lo = make_float2(acc[i][j][0], acc[i][j][1]);
            float2 hi = make_float2(acc[i][j][2], acc[i][j][3]);
            if (HAS_BIAS) {
                float2 bb = *(const float2*)&bias[n];
                lo.x += bb.x; lo.y += bb.y;
                hi.x += bb.x; hi.y += bb.y;
            }
            *(float2*)&C[(long long)m * ldc + n]       = lo;
            *(float2*)&C[(long long)(m + 8) * ldc + n] = hi;
        }
    }
}

// ---------------- projections (tf32): QKV fused. grid (18,4,6), 256 thr -------
__global__ __launch_bounds__(256) void proj_kernel(const float* __restrict__ hidden,
                                                   EncParams p) {
    int z = blockIdx.z, inst = z & 1, b = z >> 1;
    int sector = blockIdx.x / 6;
    int colL = (blockIdx.x % 6) * 128;
    int row0 = blockIdx.y * 128;
    const float* A = hidden + (long long)b * SEQP * DIM;
    const float* W = sector == 0 ? p.Wq[inst] : sector == 1 ? p.Wk[inst] : p.Wv[inst];
    float* C = &g_QKV[z][0][sector * DIM];
    if (sector == 2)
        tf32_gemm128<true>(A, DIM, W, DIM, C, 3 * DIM, DIM, p.bv[inst], row0, colL);
    else
        tf32_gemm128<false>(A, DIM, W, DIM, C, 3 * DIM, DIM, nullptr, row0, colL);
}

// ---------------- content bias. grid (512, 6), 128 threads ----------------
__global__ void cb_kernel(const float* __restrict__ hidden, EncParams p) {
    int z = blockIdx.y, inst = z & 1, b = z >> 1;
    const float* row = hidden + ((long long)b * SEQP + blockIdx.x) * DIM;
    __shared__ float sh[DIM];
    for (int i = threadIdx.x; i < DIM; i += 128) sh[i] = row[i];
    __syncthreads();
    int warp = threadIdx.x >> 5, lane = threadIdx.x & 31;
#pragma unroll
    for (int hh = 0; hh < 4; hh++) {
        int h = warp * 4 + hh;
        const float* w = p.Wcb[inst] + h * DIM;
        float s = 0.f;
        for (int i = lane; i < DIM; i += 32) s += sh[i] * w[i];
#pragma unroll
        for (int o = 16; o > 0; o >>= 1) s += __shfl_xor_sync(0xffffffffu, s, o);
        if (lane == 0) g_cb[z][blockIdx.x][h] = s;
    }
}

// ---------------- scores (bf16 m16n8k16): (Q*mix[h]) @ K^T. grid (4,4,96) -----
// 128x128 block tile, k-tile 32, packed bf16 k-pairs in smem.
__global__ __launch_bounds__(256, 2) void scores_kernel(EncParams p) {
    int z = blockIdx.z;
    int inst6 = z >> 4, h = z & 15, inst = inst6 & 1;
    const float* A = &g_QKV[inst6][0][0];      // Q, lda 2304
    const float* B = &g_QKV[inst6][0][DIM];    // K, ldb 2304
    const float* mix = p.mix[inst] + h * DIM;
    float* C = &g_scores[z][0][0];
    const int row0 = blockIdx.y * 128, col0 = blockIdx.x * 128;

    __shared__ uint32_t As[16][136];   // k-pair (32 k) x m, pad 136 -> conflict-free frag LDS
    __shared__ uint32_t Bs[16][136];

    const int tid = threadIdx.x;
    const int lane = tid & 31;
    const int g = lane >> 2, tig = lane & 3;
    const int warp = tid >> 5;
    const int wm0 = (warp >> 2) * 64;
    const int wn0 = (warp & 3) * 32;
    const int lrow = tid >> 2, lc4 = tid & 3;

    float acc[4][4][4] = {};

    for (int k0 = 0; k0 < DIM; k0 += 32) {
#pragma unroll
        for (int kc = 0; kc < 2; kc++) {
            const int kk = k0 + kc * 16 + lc4 * 4;
            const int kp = kc * 8 + lc4 * 2;
            float4 mx = *(const float4*)&mix[kk];
#pragma unroll
            for (int r = 0; r < 2; r++) {
                int m = lrow + r * 64;
                float4 v = *(const float4*)(A + (long long)(row0 + m) * (3 * DIM) + kk);
                As[kp][m]     = packbf(v.x * mx.x, v.y * mx.y);
                As[kp + 1][m] = packbf(v.z * mx.z, v.w * mx.w);
                float4 w = *(const float4*)(B + (long long)(col0 + m) * (3 * DIM) + kk);
                Bs[kp][m]     = packbf(w.x, w.y);
                Bs[kp + 1][m] = packbf(w.z, w.w);
            }
        }
        __syncthreads();
#pragma unroll
        for (int kc = 0; kc < 2; kc++) {
            const int kb = kc * 8;
            uint32_t af[4][4], bf[4][2];
#pragma unroll
            for (int i = 0; i < 4; i++) {
                int m = wm0 + i * 16 + g;
                af[i][0] = As[kb + tig][m];
                af[i][1] = As[kb + tig][m + 8];
                af[i][2] = As[kb + tig + 4][m];
                af[i][3] = As[kb + tig + 4][m + 8];
            }
#pragma unroll
            for (int j = 0; j < 4; j++) {
                int n = wn0 + j * 8 + g;
                bf[j][0] = Bs[kb + tig][n];
                bf[j][1] = Bs[kb + tig + 4][n];
            }
#pragma unroll
            for (int i = 0; i < 4; i++)
#pragma unroll
                for (int j = 0; j < 4; j++)
                    mma_bf16(acc[i][j], af[i], bf[j]);
        }
        __syncthreads();
    }

#pragma unroll
    for (int i = 0; i < 4; i++) {
        int m = row0 + wm0 + i * 16 + g;
#pragma unroll
        for (int j = 0; j < 4; j++) {
            int n = col0 + wn0 + j * 8 + tig * 2;
            *(float2*)&C[(long long)m * SEQP + n]       = make_float2(acc[i][j][0], acc[i][j][1]);
            *(float2*)&C[(long long)(m + 8) * SEQP + n] = make_float2(acc[i][j][2], acc[i][j][3]);
        }
    }
}

// ---------------- count-weighted softmax, warp-per-row. grid (64, 96), 256 thr -
__global__ void softmax_kernel() {
    int z = blockIdx.y;
    int inst6 = z >> 4, h = z & 15, inst = inst6 & 1, b = inst6 >> 1;
    const float* kcnt = g_cnt + (b * 2 + (1 - inst)) * SEQP;
    int warp = threadIdx.x >> 5, lane = threadIdx.x & 31;
    int r = blockIdx.x * 8 + warp;
    float* row = &g_scores[z][r][0];

    float s[16];
    float m = -1e30f;
#pragma unroll
    for (int j = 0; j < 4; j++) {
        int t = (lane + j * 32) * 4;
        float4 x = *(const float4*)&row[t];
        s[j * 4 + 0] = (x.x + g_cb[inst6][t + 0][h]) * INV_SCALE;
        s[j * 4 + 1] = (x.y + g_cb[inst6][t + 1][h]) * INV_SCALE;
        s[j * 4 + 2] = (x.z + g_cb[inst6][t + 2][h]) * INV_SCALE;
        s[j * 4 + 3] = (x.w + g_cb[inst6][t + 3][h]) * INV_SCALE;
#pragma unroll
        for (int c = 0; c < 4; c++) m = fmaxf(m, s[j * 4 + c]);
    }
#pragma unroll
    for (int o = 16; o > 0; o >>= 1) m = fmaxf(m, __shfl_xor_sync(0xffffffffu, m, o));

    float w[16];
    float sum = 0.f;
#pragma unroll
    for (int j = 0; j < 4; j++) {
        int t = (lane + j * 32) * 4;
        float4 c4 = *(const float4*)&kcnt[t];
        w[j * 4 + 0] = c4.x * __expf(s[j * 4 + 0] - m);
        w[j * 4 + 1] = c4.y * __expf(s[j * 4 + 1] - m);
        w[j * 4 + 2] = c4.z * __expf(s[j * 4 + 2] - m);
        w[j * 4 + 3] = c4.w * __expf(s[j * 4 + 3] - m);
        sum += w[j * 4 + 0] + w[j * 4 + 1] + w[j * 4 + 2] + w[j * 4 + 3];
    }
#pragma unroll
    for (int o = 16; o > 0; o >>= 1) sum += __shfl_xor_sync(0xffffffffu, sum, o);
    float inv = 1.f / sum;
#pragma unroll
    for (int j = 0; j < 4; j++) {
        int t = (lane + j * 32) * 4;
        *(float4*)&row[t] = make_float4(w[j * 4 + 0] * inv, w[j * 4 + 1] * inv,
                                        w[j * 4 + 2] * inv, w[j * 4 + 3] * inv);
    }
}

// ---------------- PV (tf32): ctx[:, h*48:+48] = probs[z] @ V. grid (4, 96) ----
__global__ __launch_bounds__(256) void pv_kernel() {
    int z = blockIdx.y, inst6 = z >> 4, h = z & 15;
    const float* A = &g_scores[z][0][0];                 // [512,512] probs
    const float* B = &g_QKV[inst6][0][2 * DIM + h * DH]; // V block [512 x 48], ldb 2304
    float* C = &g_ctx[inst6][0][h * DH];                 // ldc 768
    const int row0 = blockIdx.x * 128;

    __shared__ uint32_t As[16][132];
    __shared__ uint32_t Bs[16][56];

    const int tid = threadIdx.x;
    const int lane = tid & 31;
    const int g = lane >> 2, tig = lane & 3;
    const int warp = tid >> 5;
    const int wm0 = (warp >> 1) * 32;
    const int wn0 = (warp & 1) * 24;
    const int lrow = tid >> 2, lc4 = tid & 3;

    float acc[2][3][4] = {};

    for (int k0 = 0; k0 < SEQP; k0 += 16) {
#pragma unroll
        for (int r = 0; r < 2; r++) {
            int m = lrow + r * 64;
            float4 v = *(const float4*)(A + (long long)(row0 + m) * SEQP + k0 + lc4 * 4);
            As[lc4 * 4 + 0][m] = f2tf32(v.x);
            As[lc4 * 4 + 1][m] = f2tf32(v.y);
            As[lc4 * 4 + 2][m] = f2tf32(v.z);
            As[lc4 * 4 + 3][m] = f2tf32(v.w);
        }
        if (tid < 192) {
            int kr = tid / 12, c4 = tid % 12;
            float4 v = *(const float4*)(B + (long long)(k0 + kr) * (3 * DIM) + c4 * 4);
            Bs[kr][c4 * 4 + 0] = f2tf32(v.x);
            Bs[kr][c4 * 4 + 1] = f2tf32(v.y);
            Bs[kr][c4 * 4 + 2] = f2tf32(v.z);
            Bs[kr][c4 * 4 + 3] = f2tf32(v.w);
        }
        __syncthreads();
#pragma unroll
        for (int ks = 0; ks < 2; ks++) {
            const int kb = ks * 8;
            uint32_t af[2][4], bf[3][2];
#pragma unroll
            for (int i = 0; i < 2; i++) {
                int m = wm0 + i * 16 + g;
                af[i][0] = As[kb + tig][m];
                af[i][1] = As[kb + tig][m + 8];
                af[i][2] = As[kb + tig + 4][m];
                af[i][3] = As[kb + tig + 4][m + 8];
            }
#pragma unroll
            for (int j = 0; j < 3; j++) {
                int n = wn0 + j * 8 + g;
                bf[j][0] = Bs[kb + tig][n];
                bf[j][1] = Bs[kb + tig + 4][n];
            }
#pragma unroll
            for (int i = 0; i < 2; i++)
#pragma unroll
                for (int j = 0; j < 3; j++)
                    mma_tf32(acc[i][j], af[i], bf[j]);
        }
        __syncthreads();
    }

#pragma unroll
    for (int i = 0; i < 2; i++) {
        int m = row0 + wm0 + i * 16 + g;
#pragma unroll
        for (int j = 0; j < 3; j++) {
            int n = wn0 + j * 8 + tig * 2;
            *(float2*)&C[(long long)m * DIM + n]       = make_float2(acc[i][j][0], acc[i][j][1]);
            *(float2*)&C[(long long)(m + 8) * DIM + n] = make_float2(acc[i][j][2], acc[i][j][3]);
        }
    }
}

// ---------------- output projection (tf32). grid (6,4,6), 256 thr -------------
__global__ __launch_bounds__(256) void wd_kernel(EncParams p) {
    int z = blockIdx.z, inst = z & 1;
    tf32_gemm128<true>(&g_ctx[z][0][0], DIM, p.Wd[inst], DIM,
                       &g_dproj[z][0][0], DIM, DIM, p.bd[inst],
                       blockIdx.y * 128, blockIdx.x * 128);
}

// ---------------- block reduce (for LN) ----------------
__device__ __forceinline__ float blockReduceSum(float v) {
    __shared__ float sh[8];
    __shared__ float res;
#pragma unroll
    for (int o = 16; o > 0; o >>= 1) v += __shfl_xor_sync(0xffffffffu, v, o);
    __syncthreads();
    if ((threadIdx.x & 31) == 0) sh[threadIdx.x >> 5] = v;
    __syncthreads();
    if (threadIdx.x == 0) {
        float s = 0.f;
        for (int i = 0; i < 8; i++) s += sh[i];
        res = s;
    }
    __syncthreads();
    return res;
}

// ---------------- residual + LN + count weighting. grid (512, 6), 256 thr -----
__global__ void ln_kernel(const float* __restrict__ hidden, EncParams p) {
    int pos = blockIdx.x, z = blockIdx.y, inst = z & 1, b = z >> 1;
    const float* hr = hidden + ((long long)b * SEQP + pos) * DIM;
    const float* dr = &g_dproj[z][pos][0];
    const float* lng = p.lng[inst];
    const float* lnb = p.lnb[inst];
    float x[3];
    float s = 0.f;
#pragma unroll
    for (int i = 0; i < 3; i++) {
        int j = threadIdx.x + i * 256;
        x[i] = hr[j] + dr[j];
        s += x[i];
    }
    float mu = blockReduceSum(s) * (1.f / DIM);
    float vs = 0.f;
#pragma unroll
    for (int i = 0; i < 3; i++) {
        float d = x[i] - mu;
        vs += d * d;
    }
    float var = blockReduceSum(vs) * (1.f / DIM);
    float inv = rsqrtf(var + 1e-5f);
    float w = g_cnt[(b * 2 + inst) * SEQP + pos] * (1.f / 2048.f);
#pragma unroll
    for (int i = 0; i < 3; i++) {
        int j = threadIdx.x + i * 256;
        g_y[z][pos][j] = (lng[j] * (x[i] - mu) * inv + lnb[j]) * w;
    }
}

// ---------------- column sum -> output. grid (3, 6), 256 thr ----------------
__global__ void colsum_kernel(float* __restrict__ out) {
    int z = blockIdx.y;
    int j = blockIdx.x * 256 + threadIdx.x;
    const float* Y = &g_y[z][0][0];
    float s = 0.f;
#pragma unroll 8
    for (int p = 0; p < SEQP; p++) s += Y[(long long)p * DIM + j];
    out[(z >> 1) * 2 * DIM + (z & 1) * DIM + j] = s;
}

// ---------------- host ----------------
extern "C" void kernel_launch(void* const* d_in, const int* in_sizes, int n_in,
                              void* d_out, int out_size) {
    const float* hidden = (const float*)d_in[0];
    const int* fpos = (const int*)d_in[1];
    const int* tpos = (const int*)d_in[2];
    float* out = (float*)d_out;

    EncParams p;
    for (int inst = 0; inst < 2; inst++) {
        void* const* P = d_in + 3 + inst * 10;
        p.Wq[inst]  = (const float*)P[0];
        p.Wk[inst]  = (const float*)P[1];
        p.Wcb[inst] = (const float*)P[2];
        p.Wv[inst]  = (const float*)P[3];
        p.Wd[inst]  = (const float*)P[4];
        p.mix[inst] = (const float*)P[5];
        p.bv[inst]  = (const float*)P[6];
        p.bd[inst]  = (const float*)P[7];
        p.lng[inst] = (const float*)P[8];
        p.lnb[inst] = (const float*)P[9];
    }

    zero_counts_kernel<<<6, 512>>>();
    count_kernel<<<(3 * NF + 255) / 256, 256>>>(fpos, tpos);

    proj_kernel<<<dim3(18, 4, 6), 256>>>(hidden, p);     // QKV tf32
    cb_kernel<<<dim3(512, 6), 128>>>(hidden, p);         // content bias
    scores_kernel<<<dim3(4, 4, 96), 256>>>(p);           // bf16 m16n8k16 scores
    softmax_kernel<<<dim3(64, 96), 256>>>();             // warp-per-row softmax
    pv_kernel<<<dim3(4, 96), 256>>>();                   // tf32 probs @ V
    wd_kernel<<<dim3(6, 4, 6), 256>>>(p);                // tf32 output projection
    ln_kernel<<<dim3(512, 6), 256>>>(hidden, p);         // residual + LN + weight
    colsum_kernel<<<dim3(3, 6), 256>>>(out);             // weighted mean -> out
}

// round 9
// speedup vs baseline: 7.6545x; 1.0778x over previous
#include <cuda_runtime.h>
#include <cuda_bf16.h>
#include <math.h>
#include <stdint.h>

#define SEQP 512
#define DIM 768
#define NH 16
#define DH 48
#define NF 2048
#define INV_SCALE 0.14433756729740643f  // 1/sqrt(768/16)

// ---------------- scratch ----------------
__device__ float g_cnt[3 * 2 * SEQP];
__device__ __nv_bfloat16 g_QKbf[6][SEQP][2 * DIM];   // per z6: Q | K  (bf16)
__device__ float g_V[6][SEQP][DIM];                  // V (+bv), fp32 (value path)
__device__ float g_cb[6][SEQP][NH];
__device__ float g_scores[96][SEQP][SEQP];           // z96 = inst6*16 + h
__device__ __nv_bfloat16 g_pbf[96][SEQP][SEQP];      // softmax probs, bf16
__device__ float g_ctx[6][SEQP][DIM];
__device__ float g_dproj[6][SEQP][DIM];
__device__ float g_y[6][SEQP][DIM];

struct EncParams {
    const float *Wq[2], *Wk[2], *Wv[2], *Wcb[2], *Wd[2], *mix[2];
    const float *bv[2], *bd[2], *lng[2], *lnb[2];
};

// ---------------- counts ----------------
__global__ void zero_counts_kernel() {
    int i = blockIdx.x * blockDim.x + threadIdx.x;
    if (i < 3 * 2 * SEQP) g_cnt[i] = 0.f;
}

__global__ void count_kernel(const int* __restrict__ fpos, const int* __restrict__ tpos) {
    int i = blockIdx.x * blockDim.x + threadIdx.x;
    if (i >= 3 * NF) return;
    int b = i / NF;
    atomicAdd(&g_cnt[(b * 2 + 0) * SEQP + (fpos[i] & (SEQP - 1))], 1.f);
    atomicAdd(&g_cnt[(b * 2 + 1) * SEQP + (tpos[i] & (SEQP - 1))], 1.f);
}

// ================= mma primitives =================
__device__ __forceinline__ uint32_t f2tf32(float v) {
    uint32_t u;
    asm("cvt.rna.tf32.f32 %0, %1;" : "=r"(u) : "f"(v));
    return u;
}

__device__ __forceinline__ void mma_tf32(float* c, const uint32_t* a, const uint32_t* b) {
    asm volatile(
        "mma.sync.aligned.m16n8k8.row.col.f32.tf32.tf32.f32 "
        "{%0,%1,%2,%3}, {%4,%5,%6,%7}, {%8,%9}, {%0,%1,%2,%3};\n"
        : "+f"(c[0]), "+f"(c[1]), "+f"(c[2]), "+f"(c[3])
        : "r"(a[0]), "r"(a[1]), "r"(a[2]), "r"(a[3]), "r"(b[0]), "r"(b[1]));
}

__device__ __forceinline__ void mma_bf16(float* c, const uint32_t* a, const uint32_t* b) {
    asm volatile(
        "mma.sync.aligned.m16n8k16.row.col.f32.bf16.bf16.f32 "
        "{%0,%1,%2,%3}, {%4,%5,%6,%7}, {%8,%9}, {%0,%1,%2,%3};\n"
        : "+f"(c[0]), "+f"(c[1]), "+f"(c[2]), "+f"(c[3])
        : "r"(a[0]), "r"(a[1]), "r"(a[2]), "r"(a[3]), "r"(b[0]), "r"(b[1]));
}

__device__ __forceinline__ uint32_t packbf(float x, float y) {
    __nv_bfloat162 h = __float22bfloat162_rn(make_float2(x, y));
    return *(uint32_t*)&h;
}

// --------- 128x128 tf32 GEMM tile: C = A @ B^T (+bias), fp32 out ----
template <bool HAS_BIAS>
__device__ __forceinline__ void tf32_gemm128(
    const float* __restrict__ A, int lda,
    const float* __restrict__ B, int ldb,
    float* __restrict__ C, int ldc,
    int K, const float* __restrict__ bias,
    int row0, int col0)
{
    __shared__ uint32_t As[16][132];
    __shared__ uint32_t Bs[16][132];

    const int tid = threadIdx.x;
    const int lane = tid & 31;
    const int g = lane >> 2, tig = lane & 3;
    const int warp = tid >> 5;
    const int wm0 = (warp >> 2) * 64;
    const int wn0 = (warp & 3) * 32;
    const int lrow = tid >> 2, lc4 = tid & 3;

    float acc[4][4][4] = {};

    for (int k0 = 0; k0 < K; k0 += 16) {
#pragma unroll
        for (int r = 0; r < 2; r++) {
            int m = lrow + r * 64;
            float4 v = *(const float4*)(A + (long long)(row0 + m) * lda + k0 + lc4 * 4);
            As[lc4 * 4 + 0][m] = f2tf32(v.x);
            As[lc4 * 4 + 1][m] = f2tf32(v.y);
            As[lc4 * 4 + 2][m] = f2tf32(v.z);
            As[lc4 * 4 + 3][m] = f2tf32(v.w);
            float4 w = *(const float4*)(B + (long long)(col0 + m) * ldb + k0 + lc4 * 4);
            Bs[lc4 * 4 + 0][m] = f2tf32(w.x);
            Bs[lc4 * 4 + 1][m] = f2tf32(w.y);
            Bs[lc4 * 4 + 2][m] = f2tf32(w.z);
            Bs[lc4 * 4 + 3][m] = f2tf32(w.w);
        }
        __syncthreads();
#pragma unroll
        for (int ks = 0; ks < 2; ks++) {
            const int kb = ks * 8;
            uint32_t af[4][4], bf[4][2];
#pragma unroll
            for (int i = 0; i < 4; i++) {
                int m = wm0 + i * 16 + g;
                af[i][0] = As[kb + tig][m];
                af[i][1] = As[kb + tig][m + 8];
                af[i][2] = As[kb + tig + 4][m];
                af[i][3] = As[kb + tig + 4][m + 8];
            }
#pragma unroll
            for (int j = 0; j < 4; j++) {
                int n = wn0 + j * 8 + g;
                bf[j][0] = Bs[kb + tig][n];
                bf[j][1] = Bs[kb + tig + 4][n];
            }
#pragma unroll
            for (int i = 0; i < 4; i++)
#pragma unroll
                for (int j = 0; j < 4; j++)
                    mma_tf32(acc[i][j], af[i], bf[j]);
        }
        __syncthreads();
    }

#pragma unroll
    for (int i = 0; i < 4; i++) {
        int m = row0 + wm0 + i * 16 + g;
#pragma unroll
        for (int j = 0; j < 4; j++) {
            int n = col0 + wn0 + j * 8 + tig * 2;
            float2 lo = make_float2(acc[i][j][0], acc[i][j][1]);
            float2 hi = make_float2(acc[i][j][2], acc[i][j][3]);
            if (HAS_BIAS) {
                float2 bb = *(const float2*)&bias[n];
                lo.x += bb.x; lo.y += bb.y;
                hi.x += bb.x; hi.y += bb.y;
            }
            *(float2*)&C[(long long)m * ldc + n]       = lo;
            *(float2*)&C[(long long)(m + 8) * ldc + n] = hi;
        }
    }
}

// --------- 128x128 bf16 GEMM tile: Cbf16 = A @ B^T (fp32 in, bf16 out) ----
__device__ __forceinline__ void bf16_gemm128_obf(
    const float* __restrict__ A, int lda,
    const float* __restrict__ B, int ldb,
    __nv_bfloat16* __restrict__ C, int ldc,
    int K, int row0, int col0)
{
    __shared__ uint32_t As[16][136];
    __shared__ uint32_t Bs[16][136];

    const int tid = threadIdx.x;
    const int lane = tid & 31;
    const int g = lane >> 2, tig = lane & 3;
    const int warp = tid >> 5;
    const int wm0 = (warp >> 2) * 64;
    const int wn0 = (warp & 3) * 32;
    const int lrow = tid >> 2, lc4 = tid & 3;

    float acc[4][4][4] = {};

    for (int k0 = 0; k0 < K; k0 += 32) {
#pragma unroll
        for (int r = 0; r < 2; r++) {
            int m = lrow + r * 64;
            const float* ap = A + (long long)(row0 + m) * lda + k0 + lc4 * 8;
            float4 a0 = *(const float4*)ap;
            float4 a1 = *(const float4*)(ap + 4);
            As[lc4 * 4 + 0][m] = packbf(a0.x, a0.y);
            As[lc4 * 4 + 1][m] = packbf(a0.z, a0.w);
            As[lc4 * 4 + 2][m] = packbf(a1.x, a1.y);
            As[lc4 * 4 + 3][m] = packbf(a1.z, a1.w);
            const float* bp = B + (long long)(col0 + m) * ldb + k0 + lc4 * 8;
            float4 b0 = *(const float4*)bp;
            float4 b1 = *(const float4*)(bp + 4);
            Bs[lc4 * 4 + 0][m] = packbf(b0.x, b0.y);
            Bs[lc4 * 4 + 1][m] = packbf(b0.z, b0.w);
            Bs[lc4 * 4 + 2][m] = packbf(b1.x, b1.y);
            Bs[lc4 * 4 + 3][m] = packbf(b1.z, b1.w);
        }
        __syncthreads();
#pragma unroll
        for (int kc = 0; kc < 2; kc++) {
            const int kb = kc * 8;
            uint32_t af[4][4], bf[4][2];
#pragma unroll
            for (int i = 0; i < 4; i++) {
                int m = wm0 + i * 16 + g;
                af[i][0] = As[kb + tig][m];
                af[i][1] = As[kb + tig][m + 8];
                af[i][2] = As[kb + tig + 4][m];
                af[i][3] = As[kb + tig + 4][m + 8];
            }
#pragma unroll
            for (int j = 0; j < 4; j++) {
                int n = wn0 + j * 8 + g;
                bf[j][0] = Bs[kb + tig][n];
                bf[j][1] = Bs[kb + tig + 4][n];
            }
#pragma unroll
            for (int i = 0; i < 4; i++)
#pragma unroll
                for (int j = 0; j < 4; j++)
                    mma_bf16(acc[i][j], af[i], bf[j]);
        }
        __syncthreads();
    }

#pragma unroll
    for (int i = 0; i < 4; i++) {
        int m = row0 + wm0 + i * 16 + g;
#pragma unroll
        for (int j = 0; j < 4; j++) {
            int n = col0 + wn0 + j * 8 + tig * 2;
            *(uint32_t*)&C[(long long)m * ldc + n]       = packbf(acc[i][j][0], acc[i][j][1]);
            *(uint32_t*)&C[(long long)(m + 8) * ldc + n] = packbf(acc[i][j][2], acc[i][j][3]);
        }
    }
}

// ---------------- Q/K projections (bf16 out). grid (12,4,6), 256 thr ---------
__global__ __launch_bounds__(256, 2) void projqk_kernel(const float* __restrict__ hidden,
                                                        EncParams p) {
    int z = blockIdx.z, inst = z & 1, b = z >> 1;
    int sector = blockIdx.x / 6;                 // 0=Q, 1=K
    int colL = (blockIdx.x % 6) * 128;
    int row0 = blockIdx.y * 128;
    const float* A = hidden + (long long)b * SEQP * DIM;
    const float* W = sector == 0 ? p.Wq[inst] : p.Wk[inst];
    bf16_gemm128_obf(A, DIM, W, DIM, &g_QKbf[z][0][sector * DIM], 2 * DIM, DIM, row0, colL);
}

// ---------------- V projection (tf32, fp32 out). grid (6,4,6), 256 thr -------
__global__ __launch_bounds__(256) void projv_kernel(const float* __restrict__ hidden,
                                                    EncParams p) {
    int z = blockIdx.z, inst = z & 1, b = z >> 1;
    const float* A = hidden + (long long)b * SEQP * DIM;
    tf32_gemm128<true>(A, DIM, p.Wv[inst], DIM, &g_V[z][0][0], DIM, DIM, p.bv[inst],
                       blockIdx.y * 128, (blockIdx.x % 6) * 128);
}

// ---------------- content bias: both insts per block. grid (512, 3), 128 thr --
__global__ void cb_kernel(const float* __restrict__ hidden, EncParams p) {
    int b = blockIdx.y;
    const float* row = hidden + ((long long)b * SEQP + blockIdx.x) * DIM;
    __shared__ float sh[DIM];
    for (int i = threadIdx.x; i < DIM; i += 128) sh[i] = row[i];
    __syncthreads();
    int warp = threadIdx.x >> 5, lane = threadIdx.x & 31;
#pragma unroll
    for (int q = 0; q < 8; q++) {
        int idx = warp * 8 + q;                  // 0..31 = inst*16 + h
        int inst = idx >> 4, h = idx & 15;
        const float* w = p.Wcb[inst] + h * DIM;
        float s = 0.f;
        for (int i = lane; i < DIM; i += 32) s += sh[i] * w[i];
#pragma unroll
        for (int o = 16; o > 0; o >>= 1) s += __shfl_xor_sync(0xffffffffu, s, o);
        if (lane == 0) g_cb[b * 2 + inst][blockIdx.x][h] = s;
    }
}

// ---------------- scores (bf16 in, bf16 mma): (Q*mix[h]) @ K^T. grid (4,4,96) -
__global__ __launch_bounds__(256, 2) void scores_kernel(EncParams p) {
    int z = blockIdx.z;
    int inst6 = z >> 4, h = z & 15, inst = inst6 & 1;
    const __nv_bfloat16* A = &g_QKbf[inst6][0][0];      // Q, lda 1536
    const __nv_bfloat16* B = &g_QKbf[inst6][0][DIM];    // K, ldb 1536
    const float* mix = p.mix[inst] + h * DIM;
    float* C = &g_scores[z][0][0];
    const int row0 = blockIdx.y * 128, col0 = blockIdx.x * 128;

    __shared__ uint32_t As[16][136];
    __shared__ uint32_t Bs[16][136];
    __shared__ uint32_t mixbf[DIM / 2];

    const int tid = threadIdx.x;
    const int lane = tid & 31;
    const int g = lane >> 2, tig = lane & 3;
    const int warp = tid >> 5;
    const int wm0 = (warp >> 2) * 64;
    const int wn0 = (warp & 3) * 32;
    const int lrow = tid >> 2, lc4 = tid & 3;

    for (int i = tid; i < DIM / 2; i += 256) {
        float2 mf = *(const float2*)&mix[i * 2];
        mixbf[i] = packbf(mf.x, mf.y);
    }
    __syncthreads();

    float acc[4][4][4] = {};

    for (int k0 = 0; k0 < DIM; k0 += 32) {
        uint32_t mx[4];
#pragma unroll
        for (int j = 0; j < 4; j++) mx[j] = mixbf[k0 / 2 + lc4 * 4 + j];
#pragma unroll
        for (int r = 0; r < 2; r++) {
            int m = lrow + r * 64;
            uint4 qv = *(const uint4*)(A + (long long)(row0 + m) * (2 * DIM) + k0 + lc4 * 8);
            uint32_t q[4] = {qv.x, qv.y, qv.z, qv.w};
#pragma unroll
            for (int j = 0; j < 4; j++) {
                __nv_bfloat162 r2 = __hmul2(*(__nv_bfloat162*)&q[j], *(__nv_bfloat162*)&mx[j]);
                As[lc4 * 4 + j][m] = *(uint32_t*)&r2;
            }
            uint4 kv = *(const uint4*)(B + (long long)(col0 + m) * (2 * DIM) + k0 + lc4 * 8);
            Bs[lc4 * 4 + 0][m] = kv.x;
            Bs[lc4 * 4 + 1][m] = kv.y;
            Bs[lc4 * 4 + 2][m] = kv.z;
            Bs[lc4 * 4 + 3][m] = kv.w;
        }
        __syncthreads();
#pragma unroll
        for (int kc = 0; kc < 2; kc++) {
            const int kb = kc * 8;
            uint32_t af[4][4], bf[4][2];
#pragma unroll
            for (int i = 0; i < 4; i++) {
                int m = wm0 + i * 16 + g;
                af[i][0] = As[kb + tig][m];
                af[i][1] = As[kb + tig][m + 8];
                af[i][2] = As[kb + tig + 4][m];
                af[i][3] = As[kb + tig + 4][m + 8];
            }
#pragma unroll
            for (int j = 0; j < 4; j++) {
                int n = wn0 + j * 8 + g;
                bf[j][0] = Bs[kb + tig][n];
                bf[j][1] = Bs[kb + tig + 4][n];
            }
#pragma unroll
            for (int i = 0; i < 4; i++)
#pragma unroll
                for (int j = 0; j < 4; j++)
                    mma_bf16(acc[i][j], af[i], bf[j]);
        }
        __syncthreads();
    }

#pragma unroll
    for (int i = 0; i < 4; i++) {
        int m = row0 + wm0 + i * 16 + g;
#pragma unroll
        for (int j = 0; j < 4; j++) {
            int n = col0 + wn0 + j * 8 + tig * 2;
            *(float2*)&C[(long long)m * SEQP + n]       = make_float2(acc[i][j][0], acc[i][j][1]);
            *(float2*)&C[(long long)(m + 8) * SEQP + n] = make_float2(acc[i][j][2], acc[i][j][3]);
        }
    }
}

// ---------------- count-weighted softmax -> bf16 probs. grid (64, 96), 256 thr -
__global__ void softmax_kernel() {
    int z = blockIdx.y;
    int inst6 = z >> 4, h = z & 15, inst = inst6 & 1, b = inst6 >> 1;
    const float* kcnt = g_cnt + (b * 2 + (1 - inst)) * SEQP;
    int warp = threadIdx.x >> 5, lane = threadIdx.x & 31;
    int r = blockIdx.x * 8 + warp;
    const float* row = &g_scores[z][r][0];
    __nv_bfloat16* prow = &g_pbf[z][r][0];

    float s[16];
    float m = -1e30f;
#pragma unroll
    for (int j = 0; j < 4; j++) {
        int t = (lane + j * 32) * 4;
        float4 x = *(const float4*)&row[t];
        s[j * 4 + 0] = (x.x + g_cb[inst6][t + 0][h]) * INV_SCALE;
        s[j * 4 + 1] = (x.y + g_cb[inst6][t + 1][h]) * INV_SCALE;
        s[j * 4 + 2] = (x.z + g_cb[inst6][t + 2][h]) * INV_SCALE;
        s[j * 4 + 3] = (x.w + g_cb[inst6][t + 3][h]) * INV_SCALE;
#pragma unroll
        for (int c = 0; c < 4; c++) m = fmaxf(m, s[j * 4 + c]);
    }
#pragma unroll
    for (int o = 16; o > 0; o >>= 1) m = fmaxf(m, __shfl_xor_sync(0xffffffffu, m, o));

    float w[16];
    float sum = 0.f;
#pragma unroll
    for (int j = 0; j < 4; j++) {
        int t = (lane + j * 32) * 4;
        float4 c4 = *(const float4*)&kcnt[t];
        w[j * 4 + 0] = c4.x * __expf(s[j * 4 + 0] - m);
        w[j * 4 + 1] = c4.y * __expf(s[j * 4 + 1] - m);
        w[j * 4 + 2] = c4.z * __expf(s[j * 4 + 2] - m);
        w[j * 4 + 3] = c4.w * __expf(s[j * 4 + 3] - m);
        sum += w[j * 4 + 0] + w[j * 4 + 1] + w[j * 4 + 2] + w[j * 4 + 3];
    }
#pragma unroll
    for (int o = 16; o > 0; o >>= 1) sum += __shfl_xor_sync(0xffffffffu, sum, o);
    float inv = 1.f / sum;
#pragma unroll
    for (int j = 0; j < 4; j++) {
        int t = (lane + j * 32) * 4;
        uint2 pk;
        pk.x = packbf(w[j * 4 + 0] * inv, w[j * 4 + 1] * inv);
        pk.y = packbf(w[j * 4 + 2] * inv, w[j * 4 + 3] * inv);
        *(uint2*)&prow[t] = pk;
    }
}

// ---------------- PV (bf16): ctx[:, h*48:+48] = probs[z] @ V. grid (4, 96) ----
// 128x48 block tile, 8 warps (4x2), warp tile 32x24.
__global__ __launch_bounds__(256) void pv_kernel() {
    int z = blockIdx.y, inst6 = z >> 4, h = z & 15;
    const __nv_bfloat16* A = &g_pbf[z][0][0];    // [512,512] probs bf16
    const float* B = &g_V[inst6][0][h * DH];     // V block [512 x 48], ldb 768
    float* C = &g_ctx[inst6][0][h * DH];         // ldc 768
    const int row0 = blockIdx.x * 128;

    __shared__ uint32_t As[16][136];             // k-pairs x m
    __shared__ uint32_t Bs[16][56];              // k-pairs x n

    const int tid = threadIdx.x;
    const int lane = tid & 31;
    const int g = lane >> 2, tig = lane & 3;
    const int warp = tid >> 5;
    const int wm0 = (warp >> 1) * 32;
    const int wn0 = (warp & 1) * 24;
    const int lrow = tid >> 2, lc4 = tid & 3;

    float acc[2][3][4] = {};

    for (int k0 = 0; k0 < SEQP; k0 += 32) {
#pragma unroll
        for (int r = 0; r < 2; r++) {
            int m = lrow + r * 64;
            uint4 pv = *(const uint4*)(A + (long long)(row0 + m) * SEQP + k0 + lc4 * 8);
            As[lc4 * 4 + 0][m] = pv.x;
            As[lc4 * 4 + 1][m] = pv.y;
            As[lc4 * 4 + 2][m] = pv.z;
            As[lc4 * 4 + 3][m] = pv.w;
        }
        if (tid < 192) {
            int kp = tid / 12, n4 = tid % 12;
            const float* b0 = B + (long long)(k0 + kp * 2) * DIM + n4 * 4;
            float4 v0 = *(const float4*)b0;
            float4 v1 = *(const float4*)(b0 + DIM);
            Bs[kp][n4 * 4 + 0] = packbf(v0.x, v1.x);
            Bs[kp][n4 * 4 + 1] = packbf(v0.y, v1.y);
            Bs[kp][n4 * 4 + 2] = packbf(v0.z, v1.z);
            Bs[kp][n4 * 4 + 3] = packbf(v0.w, v1.w);
        }
        __syncthreads();
#pragma unroll
        for (int kc = 0; kc < 2; kc++) {
            const int kb = kc * 8;
            uint32_t af[2][4], bf[3][2];
#pragma unroll
            for (int i = 0; i < 2; i++) {
                int m = wm0 + i * 16 + g;
                af[i][0] = As[kb + tig][m];
                af[i][1] = As[kb + tig][m + 8];
                af[i][2] = As[kb + tig + 4][m];
                af[i][3] = As[kb + tig + 4][m + 8];
            }
#pragma unroll
            for (int j = 0; j < 3; j++) {
                int n = wn0 + j * 8 + g;
                bf[j][0] = Bs[kb + tig][n];
                bf[j][1] = Bs[kb + tig + 4][n];
            }
#pragma unroll
            for (int i = 0; i < 2; i++)
#pragma unroll
                for (int j = 0; j < 3; j++)
                    mma_bf16(acc[i][j], af[i], bf[j]);
        }
        __syncthreads();
    }

#pragma unroll
    for (int i = 0; i < 2; i++) {
        int m = row0 + wm0 + i * 16 + g;
#pragma unroll
        for (int j = 0; j < 3; j++) {
            int n = wn0 + j * 8 + tig * 2;
            *(float2*)&C[(long long)m * DIM + n]       = make_float2(acc[i][j][0], acc[i][j][1]);
            *(float2*)&C[(long long)(m + 8) * DIM + n] = make_float2(acc[i][j][2], acc[i][j][3]);
        }
    }
}

// ---------------- output projection (tf32). grid (6,4,6), 256 thr -------------
__global__ __launch_bounds__(256) void wd_kernel(EncParams p) {
    int z = blockIdx.z, inst = z & 1;
    tf32_gemm128<true>(&g_ctx[z][0][0], DIM, p.Wd[inst], DIM,
                       &g_dproj[z][0][0], DIM, DIM, p.bd[inst],
                       blockIdx.y * 128, blockIdx.x * 128);
}

// ---------------- block reduce (for LN) ----------------
__device__ __forceinline__ float blockReduceSum(float v) {
    __shared__ float sh[8];
    __shared__ float res;
#pragma unroll
    for (int o = 16; o > 0; o >>= 1) v += __shfl_xor_sync(0xffffffffu, v, o);
    __syncthreads();
    if ((threadIdx.x & 31) == 0) sh[threadIdx.x >> 5] = v;
    __syncthreads();
    if (threadIdx.x == 0) {
        float s = 0.f;
        for (int i = 0; i < 8; i++) s += sh[i];
        res = s;
    }
    __syncthreads();
    return res;
}

// ---------------- residual + LN + count weighting. grid (512, 6), 256 thr -----
__global__ void ln_kernel(const float* __restrict__ hidden, EncParams p) {
    int pos = blockIdx.x, z = blockIdx.y, inst = z & 1, b = z >> 1;
    const float* hr = hidden + ((long long)b * SEQP + pos) * DIM;
    const float* dr = &g_dproj[z][pos][0];
    const float* lng = p.lng[inst];
    const float* lnb = p.lnb[inst];
    float x[3];
    float s = 0.f;
#pragma unroll
    for (int i = 0; i < 3; i++) {
        int j = threadIdx.x + i * 256;
        x[i] = hr[j] + dr[j];
        s += x[i];
    }
    float mu = blockReduceSum(s) * (1.f / DIM);
    float vs = 0.f;
#pragma unroll
    for (int i = 0; i < 3; i++) {
        float d = x[i] - mu;
        vs += d * d;
    }
    float var = blockReduceSum(vs) * (1.f / DIM);
    float inv = rsqrtf(var + 1e-5f);
    float w = g_cnt[(b * 2 + inst) * SEQP + pos] * (1.f / 2048.f);
#pragma unroll
    for (int i = 0; i < 3; i++) {
        int j = threadIdx.x + i * 256;
        g_y[z][pos][j] = (lng[j] * (x[i] - mu) * inv + lnb[j]) * w;
    }
}

// ---------------- column sum -> output. grid (3, 6), 256 thr ----------------
__global__ void colsum_kernel(float* __restrict__ out) {
    int z = blockIdx.y;
    int j = blockIdx.x * 256 + threadIdx.x;
    const float* Y = &g_y[z][0][0];
    float s = 0.f;
#pragma unroll 8
    for (int p = 0; p < SEQP; p++) s += Y[(long long)p * DIM + j];
    out[(z >> 1) * 2 * DIM + (z & 1) * DIM + j] = s;
}

// ---------------- host ----------------
extern "C" void kernel_launch(void* const* d_in, const int* in_sizes, int n_in,
                              void* d_out, int out_size) {
    const float* hidden = (const float*)d_in[0];
    const int* fpos = (const int*)d_in[1];
    const int* tpos = (const int*)d_in[2];
    float* out = (float*)d_out;

    EncParams p;
    for (int inst = 0; inst < 2; inst++) {
        void* const* P = d_in + 3 + inst * 10;
        p.Wq[inst]  = (const float*)P[0];
        p.Wk[inst]  = (const float*)P[1];
        p.Wcb[inst] = (const float*)P[2];
        p.Wv[inst]  = (const float*)P[3];
        p.Wd[inst]  = (const float*)P[4];
        p.mix[inst] = (const float*)P[5];
        p.bv[inst]  = (const float*)P[6];
        p.bd[inst]  = (const float*)P[7];
        p.lng[inst] = (const float*)P[8];
        p.lnb[inst] = (const float*)P[9];
    }

    zero_counts_kernel<<<6, 512>>>();
    count_kernel<<<(3 * NF + 255) / 256, 256>>>(fpos, tpos);

    projqk_kernel<<<dim3(12, 4, 6), 256>>>(hidden, p);   // Q,K bf16
    projv_kernel<<<dim3(6, 4, 6), 256>>>(hidden, p);     // V tf32
    cb_kernel<<<dim3(512, 3), 128>>>(hidden, p);         // content bias
    scores_kernel<<<dim3(4, 4, 96), 256>>>(p);           // bf16 scores
    softmax_kernel<<<dim3(64, 96), 256>>>();             // softmax -> bf16 probs
    pv_kernel<<<dim3(4, 96), 256>>>();                   // bf16 probs @ V
    wd_kernel<<<dim3(6, 4, 6), 256>>>(p);                // tf32 output projection
    ln_kernel<<<dim3(512, 6), 256>>>(hidden, p);         // residual + LN + weight
    colsum_kernel<<<dim3(3, 6), 256>>>(out);             // weighted mean -> out
}

// round 12
// speedup vs baseline: 8.1792x; 1.0685x over previous
#include <cuda_runtime.h>
#include <cuda_bf16.h>
#include <math.h>
#include <stdint.h>

#define SEQP 512
#define DIM 768
#define NH 16
#define DH 48
#define NF 2048
#define INV_SCALE 0.14433756729740643f  // 1/sqrt(768/16)

// ---------------- scratch ----------------
__device__ float g_cnt[3 * 2 * SEQP];
__device__ __nv_bfloat16 g_QKbf[6][SEQP][2 * DIM];   // per z6: Q | K  (bf16)
__device__ float g_V[6][SEQP][DIM];                  // V (+bv), fp32 (value path)
__device__ float g_cbk[6][NH][SEQP];                 // cb*INV_SCALE + log(kcnt)
__device__ float g_ctx[6][SEQP][DIM];
__device__ float g_dproj[6][SEQP][DIM];
__device__ float g_y[6][SEQP][DIM];

struct EncParams {
    const float *Wq[2], *Wk[2], *Wv[2], *Wcb[2], *Wd[2], *mix[2];
    const float *bv[2], *bd[2], *lng[2], *lnb[2];
};

// ---------------- counts ----------------
__global__ void zero_counts_kernel() {
    int i = blockIdx.x * blockDim.x + threadIdx.x;
    if (i < 3 * 2 * SEQP) g_cnt[i] = 0.f;
}

__global__ void count_kernel(const int* __restrict__ fpos, const int* __restrict__ tpos) {
    int i = blockIdx.x * blockDim.x + threadIdx.x;
    if (i >= 3 * NF) return;
    int b = i / NF;
    atomicAdd(&g_cnt[(b * 2 + 0) * SEQP + (fpos[i] & (SEQP - 1))], 1.f);
    atomicAdd(&g_cnt[(b * 2 + 1) * SEQP + (tpos[i] & (SEQP - 1))], 1.f);
}

// ================= mma primitives =================
__device__ __forceinline__ uint32_t f2tf32(float v) {
    uint32_t u;
    asm("cvt.rna.tf32.f32 %0, %1;" : "=r"(u) : "f"(v));
    return u;
}

__device__ __forceinline__ void mma_tf32(float* c, const uint32_t* a, const uint32_t* b) {
    asm volatile(
        "mma.sync.aligned.m16n8k8.row.col.f32.tf32.tf32.f32 "
        "{%0,%1,%2,%3}, {%4,%5,%6,%7}, {%8,%9}, {%0,%1,%2,%3};\n"
        : "+f"(c[0]), "+f"(c[1]), "+f"(c[2]), "+f"(c[3])
        : "r"(a[0]), "r"(a[1]), "r"(a[2]), "r"(a[3]), "r"(b[0]), "r"(b[1]));
}

__device__ __forceinline__ void mma_bf16(float* c, const uint32_t* a, const uint32_t* b) {
    asm volatile(
        "mma.sync.aligned.m16n8k16.row.col.f32.bf16.bf16.f32 "
        "{%0,%1,%2,%3}, {%4,%5,%6,%7}, {%8,%9}, {%0,%1,%2,%3};\n"
        : "+f"(c[0]), "+f"(c[1]), "+f"(c[2]), "+f"(c[3])
        : "r"(a[0]), "r"(a[1]), "r"(a[2]), "r"(a[3]), "r"(b[0]), "r"(b[1]));
}

__device__ __forceinline__ uint32_t packbf(float x, float y) {
    __nv_bfloat162 h = __float22bfloat162_rn(make_float2(x, y));
    return *(uint32_t*)&h;
}

// --------- 128x128 tf32 GEMM tile: C = A @ B^T (+bias), fp32 out ----
template <bool HAS_BIAS>
__device__ __forceinline__ void tf32_gemm128(
    const float* __restrict__ A, int lda,
    const float* __restrict__ B, int ldb,
    float* __restrict__ C, int ldc,
    int K, const float* __restrict__ bias,
    int row0, int col0)
{
    __shared__ uint32_t As[16][132];
    __shared__ uint32_t Bs[16][132];

    const int tid = threadIdx.x;
    const int lane = tid & 31;
    const int g = lane >> 2, tig = lane & 3;
    const int warp = tid >> 5;
    const int wm0 = (warp >> 2) * 64;
    const int wn0 = (warp & 3) * 32;
    const int lrow = tid >> 2, lc4 = tid & 3;

    float acc[4][4][4] = {};

    for (int k0 = 0; k0 < K; k0 += 16) {
#pragma unroll
        for (int r = 0; r < 2; r++) {
            int m = lrow + r * 64;
            float4 v = *(const float4*)(A + (long long)(row0 + m) * lda + k0 + lc4 * 4);
            As[lc4 * 4 + 0][m] = f2tf32(v.x);
            As[lc4 * 4 + 1][m] = f2tf32(v.y);
            As[lc4 * 4 + 2][m] = f2tf32(v.z);
            As[lc4 * 4 + 3][m] = f2tf32(v.w);
            float4 w = *(const float4*)(B + (long long)(col0 + m) * ldb + k0 + lc4 * 4);
            Bs[lc4 * 4 + 0][m] = f2tf32(w.x);
            Bs[lc4 * 4 + 1][m] = f2tf32(w.y);
            Bs[lc4 * 4 + 2][m] = f2tf32(w.z);
            Bs[lc4 * 4 + 3][m] = f2tf32(w.w);
        }
        __syncthreads();
#pragma unroll
        for (int ks = 0; ks < 2; ks++) {
            const int kb = ks * 8;
            uint32_t af[4][4], bf[4][2];
#pragma unroll
            for (int i = 0; i < 4; i++) {
                int m = wm0 + i * 16 + g;
                af[i][0] = As[kb + tig][m];
                af[i][1] = As[kb + tig][m + 8];
                af[i][2] = As[kb + tig + 4][m];
                af[i][3] = As[kb + tig + 4][m + 8];
            }
#pragma unroll
            for (int j = 0; j < 4; j++) {
                int n = wn0 + j * 8 + g;
                bf[j][0] = Bs[kb + tig][n];
                bf[j][1] = Bs[kb + tig + 4][n];
            }
#pragma unroll
            for (int i = 0; i < 4; i++)
#pragma unroll
                for (int j = 0; j < 4; j++)
                    mma_tf32(acc[i][j], af[i], bf[j]);
        }
        __syncthreads();
    }

#pragma unroll
    for (int i = 0; i < 4; i++) {
        int m = row0 + wm0 + i * 16 + g;
#pragma unroll
        for (int j = 0; j < 4; j++) {
            int n = col0 + wn0 + j * 8 + tig * 2;
            float2 lo = make_float2(acc[i][j][0], acc[i][j][1]);
            float2 hi = make_float2(acc[i][j][2], acc[i][j][3]);
            if (HAS_BIAS) {
                float2 bb = *(const float2*)&bias[n];
                lo.x += bb.x; lo.y += bb.y;
                hi.x += bb.x; hi.y += bb.y;
            }
            *(float2*)&C[(long long)m * ldc + n]       = lo;
            *(float2*)&C[(long long)(m + 8) * ldc + n] = hi;
        }
    }
}

// --------- 128x128 bf16 GEMM tile: Cbf16 = A @ B^T (fp32 in, bf16 out) ----
__device__ __forceinline__ void bf16_gemm128_obf(
    const float* __restrict__ A, int lda,
    const float* __restrict__ B, int ldb,
    __nv_bfloat16* __restrict__ C, int ldc,
    int K, int row0, int col0)
{
    __shared__ uint32_t As[16][136];
    __shared__ uint32_t Bs[16][136];

    const int tid = threadIdx.x;
    const int lane = tid & 31;
    const int g = lane >> 2, tig = lane & 3;
    const int warp = tid >> 5;
    const int wm0 = (warp >> 2) * 64;
    const int wn0 = (warp & 3) * 32;
    const int lrow = tid >> 2, lc4 = tid & 3;

    float acc[4][4][4] = {};

    for (int k0 = 0; k0 < K; k0 += 32) {
#pragma unroll
        for (int r = 0; r < 2; r++) {
            int m = lrow + r * 64;
            const float* ap = A + (long long)(row0 + m) * lda + k0 + lc4 * 8;
            float4 a0 = *(const float4*)ap;
            float4 a1 = *(const float4*)(ap + 4);
            As[lc4 * 4 + 0][m] = packbf(a0.x, a0.y);
            As[lc4 * 4 + 1][m] = packbf(a0.z, a0.w);
            As[lc4 * 4 + 2][m] = packbf(a1.x, a1.y);
            As[lc4 * 4 + 3][m] = packbf(a1.z, a1.w);
            const float* bp = B + (long long)(col0 + m) * ldb + k0 + lc4 * 8;
            float4 b0 = *(const float4*)bp;
            float4 b1 = *(const float4*)(bp + 4);
            Bs[lc4 * 4 + 0][m] = packbf(b0.x, b0.y);
            Bs[lc4 * 4 + 1][m] = packbf(b0.z, b0.w);
            Bs[lc4 * 4 + 2][m] = packbf(b1.x, b1.y);
            Bs[lc4 * 4 + 3][m] = packbf(b1.z, b1.w);
        }
        __syncthreads();
#pragma unroll
        for (int kc = 0; kc < 2; kc++) {
            const int kb = kc * 8;
            uint32_t af[4][4], bf[4][2];
#pragma unroll
            for (int i = 0; i < 4; i++) {
                int m = wm0 + i * 16 + g;
                af[i][0] = As[kb + tig][m];
                af[i][1] = As[kb + tig][m + 8];
                af[i][2] = As[kb + tig + 4][m];
                af[i][3] = As[kb + tig + 4][m + 8];
            }
#pragma unroll
            for (int j = 0; j < 4; j++) {
                int n = wn0 + j * 8 + g;
                bf[j][0] = Bs[kb + tig][n];
                bf[j][1] = Bs[kb + tig + 4][n];
            }
#pragma unroll
            for (int i = 0; i < 4; i++)
#pragma unroll
                for (int j = 0; j < 4; j++)
                    mma_bf16(acc[i][j], af[i], bf[j]);
        }
        __syncthreads();
    }

#pragma unroll
    for (int i = 0; i < 4; i++) {
        int m = row0 + wm0 + i * 16 + g;
#pragma unroll
        for (int j = 0; j < 4; j++) {
            int n = col0 + wn0 + j * 8 + tig * 2;
            *(uint32_t*)&C[(long long)m * ldc + n]       = packbf(acc[i][j][0], acc[i][j][1]);
            *(uint32_t*)&C[(long long)(m + 8) * ldc + n] = packbf(acc[i][j][2], acc[i][j][3]);
        }
    }
}

// ---------------- Q/K projections (bf16 out). grid (12,4,6), 256 thr ---------
__global__ __launch_bounds__(256, 2) void projqk_kernel(const float* __restrict__ hidden,
                                                        EncParams p) {
    int z = blockIdx.z, inst = z & 1, b = z >> 1;
    int sector = blockIdx.x / 6;                 // 0=Q, 1=K
    int colL = (blockIdx.x % 6) * 128;
    int row0 = blockIdx.y * 128;
    const float* A = hidden + (long long)b * SEQP * DIM;
    const float* W = sector == 0 ? p.Wq[inst] : p.Wk[inst];
    bf16_gemm128_obf(A, DIM, W, DIM, &g_QKbf[z][0][sector * DIM], 2 * DIM, DIM, row0, colL);
}

// ---------------- V projection (tf32, fp32 out). grid (6,4,6), 256 thr -------
__global__ __launch_bounds__(256) void projv_kernel(const float* __restrict__ hidden,
                                                    EncParams p) {
    int z = blockIdx.z, inst = z & 1, b = z >> 1;
    const float* A = hidden + (long long)b * SEQP * DIM;
    tf32_gemm128<true>(A, DIM, p.Wv[inst], DIM, &g_V[z][0][0], DIM, DIM, p.bv[inst],
                       blockIdx.y * 128, (blockIdx.x % 6) * 128);
}

// ---------------- content bias + log(count). grid (512, 3), 128 thr ----------
// cbk[z][h][t] = (h_t . Wcb[h]) * INV_SCALE + log(kcnt_z[t])
__global__ void cb_kernel(const float* __restrict__ hidden, EncParams p) {
    int b = blockIdx.y;
    const float* row = hidden + ((long long)b * SEQP + blockIdx.x) * DIM;
    __shared__ float sh[DIM];
    for (int i = threadIdx.x; i < DIM; i += 128) sh[i] = row[i];
    __syncthreads();
    int warp = threadIdx.x >> 5, lane = threadIdx.x & 31;
#pragma unroll
    for (int q = 0; q < 8; q++) {
        int idx = warp * 8 + q;                  // 0..31 = inst*16 + h
        int inst = idx >> 4, h = idx & 15;
        const float* w = p.Wcb[inst] + h * DIM;
        float s = 0.f;
        for (int i = lane; i < DIM; i += 32) s += sh[i] * w[i];
#pragma unroll
        for (int o = 16; o > 0; o >>= 1) s += __shfl_xor_sync(0xffffffffu, s, o);
        if (lane == 0) {
            float cnt = g_cnt[(b * 2 + (1 - inst)) * SEQP + blockIdx.x];
            g_cbk[b * 2 + inst][h][blockIdx.x] = s * INV_SCALE + logf(cnt);
        }
    }
}

// ============ fused attention: scores + count-softmax + PV ============
// grid (8, 96): 64 q-rows per CTA, z96 = inst6*16 + h. 256 threads.
// No max-subtraction: |s*INV_SCALE + cbk| is O(4) for this problem's scale.
__global__ __launch_bounds__(256, 2) void attn_kernel(EncParams p) {
    const int z = blockIdx.y;
    const int inst6 = z >> 4, h = z & 15, inst = inst6 & 1;
    const int row0 = blockIdx.x * 64;
    const __nv_bfloat16* Qg = &g_QKbf[inst6][0][0];
    const __nv_bfloat16* Kg = &g_QKbf[inst6][0][DIM];
    const float* Vg = &g_V[inst6][0][h * DH];
    const float* mix = p.mix[inst] + h * DIM;

    // uSh: S-phase As(16x72 @0) + Bs(16x136 @1152) overlaid by P-phase Pp(64x72)
    __shared__ uint32_t uSh[4608];
    __shared__ uint32_t Vs[64][56];
    __shared__ uint32_t mixbf[DIM / 2];
    __shared__ float cbk[SEQP];
    __shared__ float redsum[4][64];
    __shared__ float lfin[64];

    const int tid = threadIdx.x;
    const int lane = tid & 31, warp = tid >> 5;
    const int g = lane >> 2, tig = lane & 3;
    const int wm0 = (warp >> 2) * 32;            // scores: 2x4 warps, warp 32x32
    const int wn0 = (warp & 3) * 32;
    const int wmp = (warp >> 1) * 16;            // pv: 4x2 warps, warp 16x24
    const int wnp = (warp & 1) * 24;
    const int lrow = tid >> 2, lc4 = tid & 3;    // loaders: 64 rows x 4 uint4-quarters

    for (int i = tid; i < DIM / 2; i += 256) {
        float2 mf = *(const float2*)&mix[i * 2];
        mixbf[i] = packbf(mf.x, mf.y);
    }
    for (int i = tid; i < SEQP; i += 256) cbk[i] = g_cbk[inst6][h][i];
    __syncthreads();

    float accO[3][4] = {};                        // O (unnormalized), warp 16x24
    float lpart[2][2] = {};                       // row sums

    for (int kv0 = 0; kv0 < SEQP; kv0 += 128) {
        // ---- S = (Q*mix) @ K_blk^T : 64x128, bf16 mma, k-tile 32 ----
        float acc[2][4][4] = {};
        for (int k0 = 0; k0 < DIM; k0 += 32) {
            // Q: 64 rows x 16 k-pairs (each thread: 1 uint4 = 4 k-pairs)
            {
                uint4 qv = *(const uint4*)(Qg + (long long)(row0 + lrow) * (2 * DIM) + k0 + lc4 * 8);
                uint32_t q[4] = {qv.x, qv.y, qv.z, qv.w};
#pragma unroll
                for (int c = 0; c < 4; c++) {
                    uint32_t mx = mixbf[(k0 + lc4 * 8) / 2 + c];
                    __nv_bfloat162 r2 = __hmul2(*(__nv_bfloat162*)&q[c], *(__nv_bfloat162*)&mx);
                    uSh[(lc4 * 4 + c) * 72 + lrow] = *(uint32_t*)&r2;
                }
            }
            // K: 128 rows x 16 k-pairs (each thread: 2 uint4)
#pragma unroll
            for (int r = 0; r < 2; r++) {
                int krow = lrow + r * 64;
                uint4 kv = *(const uint4*)(Kg + (long long)(kv0 + krow) * (2 * DIM) + k0 + lc4 * 8);
                uSh[1152 + (lc4 * 4 + 0) * 136 + krow] = kv.x;
                uSh[1152 + (lc4 * 4 + 1) * 136 + krow] = kv.y;
                uSh[1152 + (lc4 * 4 + 2) * 136 + krow] = kv.z;
                uSh[1152 + (lc4 * 4 + 3) * 136 + krow] = kv.w;
            }
            __syncthreads();
#pragma unroll
            for (int kc = 0; kc < 2; kc++) {
                const int kb = kc * 8;
                uint32_t af[2][4], bf[4][2];
#pragma unroll
                for (int i = 0; i < 2; i++) {
                    int m = wm0 + i * 16 + g;
                    af[i][0] = uSh[(kb + tig) * 72 + m];
                    af[i][1] = uSh[(kb + tig) * 72 + m + 8];
                    af[i][2] = uSh[(kb + tig + 4) * 72 + m];
                    af[i][3] = uSh[(kb + tig + 4) * 72 + m + 8];
                }
#pragma unroll
                for (int j = 0; j < 4; j++) {
                    int n = wn0 + j * 8 + g;
                    bf[j][0] = uSh[1152 + (kb + tig) * 136 + n];
                    bf[j][1] = uSh[1152 + (kb + tig + 4) * 136 + n];
                }
#pragma unroll
                for (int i = 0; i < 2; i++)
#pragma unroll
                    for (int j = 0; j < 4; j++)
                        mma_bf16(acc[i][j], af[i], bf[j]);
            }
            __syncthreads();
        }

        // ---- P = exp(S*INV_SCALE + cbk[t]); accumulate l; store P (overlays As/Bs) ----
#pragma unroll
        for (int i = 0; i < 2; i++) {
#pragma unroll
            for (int j = 0; j < 4; j++) {
                int colA = kv0 + wn0 + j * 8 + tig * 2;
                float c0 = cbk[colA], c1 = cbk[colA + 1];
                float w0 = __expf(acc[i][j][0] * INV_SCALE + c0);
                float w1 = __expf(acc[i][j][1] * INV_SCALE + c1);
                float w2 = __expf(acc[i][j][2] * INV_SCALE + c0);
                float w3 = __expf(acc[i][j][3] * INV_SCALE + c1);
                lpart[i][0] += w0 + w1;
                lpart[i][1] += w2 + w3;
                int kp = (wn0 >> 1) + j * 4 + tig;
                int m = wm0 + i * 16 + g;
                uSh[kp * 72 + m]     = packbf(w0, w1);
                uSh[kp * 72 + m + 8] = packbf(w2, w3);
            }
        }
        // ---- load V block (128 x 48 fp32 -> bf16 k-pairs) ----
#pragma unroll
        for (int r = 0; r < 3; r++) {
            int idx = tid + r * 256;                 // 0..767 = 64 kpairs x 12 n4
            int kp = idx / 12, n4 = idx % 12;
            const float* b0 = Vg + (long long)(kv0 + kp * 2) * DIM + n4 * 4;
            float4 v0 = *(const float4*)b0;
            float4 v1 = *(const float4*)(b0 + DIM);
            Vs[kp][n4 * 4 + 0] = packbf(v0.x, v1.x);
            Vs[kp][n4 * 4 + 1] = packbf(v0.y, v1.y);
            Vs[kp][n4 * 4 + 2] = packbf(v0.z, v1.z);
            Vs[kp][n4 * 4 + 3] = packbf(v0.w, v1.w);
        }
        __syncthreads();

        // ---- O += P @ V_blk : 64x48, k=128 ----
#pragma unroll
        for (int kb8 = 0; kb8 < 8; kb8++) {
            const int kb = kb8 * 8;
            uint32_t af[4], bf2[3][2];
            int m = wmp + g;
            af[0] = uSh[(kb + tig) * 72 + m];
            af[1] = uSh[(kb + tig) * 72 + m + 8];
            af[2] = uSh[(kb + tig + 4) * 72 + m];
            af[3] = uSh[(kb + tig + 4) * 72 + m + 8];
#pragma unroll
            for (int j = 0; j < 3; j++) {
                int n = wnp + j * 8 + g;
                bf2[j][0] = Vs[kb + tig][n];
                bf2[j][1] = Vs[kb + tig + 4][n];
            }
#pragma unroll
            for (int j = 0; j < 3; j++)
                mma_bf16(accO[j], af, bf2[j]);
        }
        __syncthreads();   // Pp/Vs consumed before next block overwrites
    }

    // ---- reduce l across quad (tig) + across the 4 warp-cols ----
#pragma unroll
    for (int i = 0; i < 2; i++)
#pragma unroll
        for (int hf = 0; hf < 2; hf++) {
            float v = lpart[i][hf];
            v += __shfl_xor_sync(0xffffffffu, v, 1);
            v += __shfl_xor_sync(0xffffffffu, v, 2);
            lpart[i][hf] = v;
        }
    if (tig == 0) {
#pragma unroll
        for (int i = 0; i < 2; i++)
#pragma unroll
            for (int hf = 0; hf < 2; hf++)
                redsum[warp & 3][wm0 + i * 16 + g + hf * 8] = lpart[i][hf];
    }
    __syncthreads();
    if (tid < 64) lfin[tid] = redsum[0][tid] + redsum[1][tid] + redsum[2][tid] + redsum[3][tid];
    __syncthreads();

    // ---- epilogue: ctx = O / l ----
    float* C = &g_ctx[inst6][0][h * DH];
    int mrow = wmp + g;
    float inv0 = 1.f / lfin[mrow];
    float inv1 = 1.f / lfin[mrow + 8];
#pragma unroll
    for (int j = 0; j < 3; j++) {
        int n = wnp + j * 8 + tig * 2;
        *(float2*)&C[(long long)(row0 + mrow) * DIM + n] =
            make_float2(accO[j][0] * inv0, accO[j][1] * inv0);
        *(float2*)&C[(long long)(row0 + mrow + 8) * DIM + n] =
            make_float2(accO[j][2] * inv1, accO[j][3] * inv1);
    }
}

// ---------------- output projection (tf32). grid (6,4,6), 256 thr -------------
__global__ __launch_bounds__(256) void wd_kernel(EncParams p) {
    int z = blockIdx.z, inst = z & 1;
    tf32_gemm128<true>(&g_ctx[z][0][0], DIM, p.Wd[inst], DIM,
                       &g_dproj[z][0][0], DIM, DIM, p.bd[inst],
                       blockIdx.y * 128, blockIdx.x * 128);
}

// ---------------- block reduce (for LN) ----------------
__device__ __forceinline__ float blockReduceSum(float v) {
    __shared__ float sh[8];
    __shared__ float res;
#pragma unroll
    for (int o = 16; o > 0; o >>= 1) v += __shfl_xor_sync(0xffffffffu, v, o);
    __syncthreads();
    if ((threadIdx.x & 31) == 0) sh[threadIdx.x >> 5] = v;
    __syncthreads();
    if (threadIdx.x == 0) {
        float s = 0.f;
        for (int i = 0; i < 8; i++) s += sh[i];
        res = s;
    }
    __syncthreads();
    return res;
}

// ---------------- residual + LN + count weighting. grid (512, 6), 256 thr -----
__global__ void ln_kernel(const float* __restrict__ hidden, EncParams p) {
    int pos = blockIdx.x, z = blockIdx.y, inst = z & 1, b = z >> 1;
    const float* hr = hidden + ((long long)b * SEQP + pos) * DIM;
    const float* dr = &g_dproj[z][pos][0];
    const float* lng = p.lng[inst];
    const float* lnb = p.lnb[inst];
    float x[3];
    float s = 0.f;
#pragma unroll
    for (int i = 0; i < 3; i++) {
        int j = threadIdx.x + i * 256;
        x[i] = hr[j] + dr[j];
        s += x[i];
    }
    float mu = blockReduceSum(s) * (1.f / DIM);
    float vs = 0.f;
#pragma unroll
    for (int i = 0; i < 3; i++) {
        float d = x[i] - mu;
        vs += d * d;
    }
    float var = blockReduceSum(vs) * (1.f / DIM);
    float inv = rsqrtf(var + 1e-5f);
    float w = g_cnt[(b * 2 + inst) * SEQP + pos] * (1.f / 2048.f);
#pragma unroll
    for (int i = 0; i < 3; i++) {
        int j = threadIdx.x + i * 256;
        g_y[z][pos][j] = (lng[j] * (x[i] - mu) * inv + lnb[j]) * w;
    }
}

// ---------------- output zero + parallel column sum ----------------
__global__ void zero_out_kernel(float* __restrict__ out, int n) {
    int i = blockIdx.x * blockDim.x + threadIdx.x;
    if (i < n) out[i] = 0.f;
}

// grid (3, 6, 8): each block sums 64 rows for 256 columns, atomicAdd into out.
__global__ void colsum_kernel(float* __restrict__ out) {
    int z = blockIdx.y;
    int j = blockIdx.x * 256 + threadIdx.x;
    int p0 = blockIdx.z * 64;
    const float* Y = &g_y[z][0][0];
    float s = 0.f;
#pragma unroll 8
    for (int p = p0; p < p0 + 64; p++) s += Y[(long long)p * DIM + j];
    atomicAdd(&out[(z >> 1) * 2 * DIM + (z & 1) * DIM + j], s);
}

// ---------------- host ----------------
extern "C" void kernel_launch(void* const* d_in, const int* in_sizes, int n_in,
                              void* d_out, int out_size) {
    const float* hidden = (const float*)d_in[0];
    const int* fpos = (const int*)d_in[1];
    const int* tpos = (const int*)d_in[2];
    float* out = (float*)d_out;

    EncParams p;
    for (int inst = 0; inst < 2; inst++) {
        void* const* P = d_in + 3 + inst * 10;
        p.Wq[inst]  = (const float*)P[0];
        p.Wk[inst]  = (const float*)P[1];
        p.Wcb[inst] = (const float*)P[2];
        p.Wv[inst]  = (const float*)P[3];
        p.Wd[inst]  = (const float*)P[4];
        p.mix[inst] = (const float*)P[5];
        p.bv[inst]  = (const float*)P[6];
        p.bd[inst]  = (const float*)P[7];
        p.lng[inst] = (const float*)P[8];
        p.lnb[inst] = (const float*)P[9];
    }

    zero_counts_kernel<<<6, 512>>>();
    count_kernel<<<(3 * NF + 255) / 256, 256>>>(fpos, tpos);

    projqk_kernel<<<dim3(12, 4, 6), 256>>>(hidden, p);   // Q,K bf16
    projv_kernel<<<dim3(6, 4, 6), 256>>>(hidden, p);     // V tf32
    cb_kernel<<<dim3(512, 3), 128>>>(hidden, p);         // cb*scale + log(cnt)
    attn_kernel<<<dim3(8, 96), 256>>>(p);                // fused scores+softmax+PV
    wd_kernel<<<dim3(6, 4, 6), 256>>>(p);                // tf32 output projection
    ln_kernel<<<dim3(512, 6), 256>>>(hidden, p);         // residual + LN + weight
    zero_out_kernel<<<(3 * 2 * DIM + 255) / 256, 256>>>(out, 3 * 2 * DIM);
    colsum_kernel<<<dim3(3, 6, 8), 256>>>(out);          // weighted mean -> out
}

// round 14
// speedup vs baseline: 8.9146x; 1.0899x over previous
#include <cuda_runtime.h>
#include <cuda_bf16.h>
#include <math.h>
#include <stdint.h>

#define SEQP 512
#define DIM 768
#define NH 16
#define DH 48
#define NF 2048
#define INV_SCALE 0.14433756729740643f  // 1/sqrt(768/16)

// ---------------- scratch ----------------
__device__ float g_cnt[3 * 2 * SEQP];
__device__ __nv_bfloat16 g_QKbf[6][SEQP][2 * DIM];   // per z6: Q | K  (bf16)
__device__ float g_V[6][SEQP][DIM];                  // V (+bv), fp32 (value path)
__device__ float g_cbk[6][NH][SEQP];                 // cb*INV_SCALE + log(kcnt)
__device__ float g_ctx[6][SEQP][DIM];
__device__ float g_dproj[6][SEQP][DIM];
__device__ float g_y[6][SEQP][DIM];

struct EncParams {
    const float *Wq[2], *Wk[2], *Wv[2], *Wcb[2], *Wd[2], *mix[2];
    const float *bv[2], *bd[2], *lng[2], *lnb[2];
};

// ---------------- counts ----------------
__global__ void zero_counts_kernel() {
    int i = blockIdx.x * blockDim.x + threadIdx.x;
    if (i < 3 * 2 * SEQP) g_cnt[i] = 0.f;
}

__global__ void count_kernel(const int* __restrict__ fpos, const int* __restrict__ tpos) {
    int i = blockIdx.x * blockDim.x + threadIdx.x;
    if (i >= 3 * NF) return;
    int b = i / NF;
    atomicAdd(&g_cnt[(b * 2 + 0) * SEQP + (fpos[i] & (SEQP - 1))], 1.f);
    atomicAdd(&g_cnt[(b * 2 + 1) * SEQP + (tpos[i] & (SEQP - 1))], 1.f);
}

// ================= mma primitives =================
__device__ __forceinline__ uint32_t f2tf32(float v) {
    uint32_t u;
    asm("cvt.rna.tf32.f32 %0, %1;" : "=r"(u) : "f"(v));
    return u;
}

__device__ __forceinline__ void mma_tf32(float* c, const uint32_t* a, const uint32_t* b) {
    asm volatile(
        "mma.sync.aligned.m16n8k8.row.col.f32.tf32.tf32.f32 "
        "{%0,%1,%2,%3}, {%4,%5,%6,%7}, {%8,%9}, {%0,%1,%2,%3};\n"
        : "+f"(c[0]), "+f"(c[1]), "+f"(c[2]), "+f"(c[3])
        : "r"(a[0]), "r"(a[1]), "r"(a[2]), "r"(a[3]), "r"(b[0]), "r"(b[1]));
}

__device__ __forceinline__ void mma_bf16(float* c, const uint32_t* a, const uint32_t* b) {
    asm volatile(
        "mma.sync.aligned.m16n8k16.row.col.f32.bf16.bf16.f32 "
        "{%0,%1,%2,%3}, {%4,%5,%6,%7}, {%8,%9}, {%0,%1,%2,%3};\n"
        : "+f"(c[0]), "+f"(c[1]), "+f"(c[2]), "+f"(c[3])
        : "r"(a[0]), "r"(a[1]), "r"(a[2]), "r"(a[3]), "r"(b[0]), "r"(b[1]));
}

__device__ __forceinline__ uint32_t packbf(float x, float y) {
    __nv_bfloat162 h = __float22bfloat162_rn(make_float2(x, y));
    return *(uint32_t*)&h;
}

// --------- 128x128 tf32 GEMM tile, double-buffered: C = A @ B^T (+bias) ----
template <bool HAS_BIAS>
__device__ __forceinline__ void tf32_gemm128(
    const float* __restrict__ A, int lda,
    const float* __restrict__ B, int ldb,
    float* __restrict__ C, int ldc,
    int K, const float* __restrict__ bias,
    int row0, int col0)
{
    __shared__ uint32_t As[2][16][132];
    __shared__ uint32_t Bs[2][16][132];

    const int tid = threadIdx.x;
    const int lane = tid & 31;
    const int g = lane >> 2, tig = lane & 3;
    const int warp = tid >> 5;
    const int wm0 = (warp >> 2) * 64;
    const int wn0 = (warp & 3) * 32;
    const int lrow = tid >> 2, lc4 = tid & 3;

    float4 aR[2], bR[2];

    // preload tile 0 into stage 0
#pragma unroll
    for (int r = 0; r < 2; r++) {
        int m = lrow + r * 64;
        aR[r] = *(const float4*)(A + (long long)(row0 + m) * lda + lc4 * 4);
        bR[r] = *(const float4*)(B + (long long)(col0 + m) * ldb + lc4 * 4);
    }
#pragma unroll
    for (int r = 0; r < 2; r++) {
        int m = lrow + r * 64;
        As[0][lc4 * 4 + 0][m] = f2tf32(aR[r].x);
        As[0][lc4 * 4 + 1][m] = f2tf32(aR[r].y);
        As[0][lc4 * 4 + 2][m] = f2tf32(aR[r].z);
        As[0][lc4 * 4 + 3][m] = f2tf32(aR[r].w);
        Bs[0][lc4 * 4 + 0][m] = f2tf32(bR[r].x);
        Bs[0][lc4 * 4 + 1][m] = f2tf32(bR[r].y);
        Bs[0][lc4 * 4 + 2][m] = f2tf32(bR[r].z);
        Bs[0][lc4 * 4 + 3][m] = f2tf32(bR[r].w);
    }
    __syncthreads();

    float acc[4][4][4] = {};
    const int NT = K / 16;

    for (int t = 0; t < NT; t++) {
        const int st = t & 1;
        if (t + 1 < NT) {
            int k0 = (t + 1) * 16;
#pragma unroll
            for (int r = 0; r < 2; r++) {
                int m = lrow + r * 64;
                aR[r] = *(const float4*)(A + (long long)(row0 + m) * lda + k0 + lc4 * 4);
                bR[r] = *(const float4*)(B + (long long)(col0 + m) * ldb + k0 + lc4 * 4);
            }
        }
#pragma unroll
        for (int ks = 0; ks < 2; ks++) {
            const int kb = ks * 8;
            uint32_t af[4][4], bf[4][2];
#pragma unroll
            for (int i = 0; i < 4; i++) {
                int m = wm0 + i * 16 + g;
                af[i][0] = As[st][kb + tig][m];
                af[i][1] = As[st][kb + tig][m + 8];
                af[i][2] = As[st][kb + tig + 4][m];
                af[i][3] = As[st][kb + tig + 4][m + 8];
            }
#pragma unroll
            for (int j = 0; j < 4; j++) {
                int n = wn0 + j * 8 + g;
                bf[j][0] = Bs[st][kb + tig][n];
                bf[j][1] = Bs[st][kb + tig + 4][n];
            }
#pragma unroll
            for (int i = 0; i < 4; i++)
#pragma unroll
                for (int j = 0; j < 4; j++)
                    mma_tf32(acc[i][j], af[i], bf[j]);
        }
        if (t + 1 < NT) {
            const int sn = st ^ 1;
#pragma unroll
            for (int r = 0; r < 2; r++) {
                int m = lrow + r * 64;
                As[sn][lc4 * 4 + 0][m] = f2tf32(aR[r].x);
                As[sn][lc4 * 4 + 1][m] = f2tf32(aR[r].y);
                As[sn][lc4 * 4 + 2][m] = f2tf32(aR[r].z);
                As[sn][lc4 * 4 + 3][m] = f2tf32(aR[r].w);
                Bs[sn][lc4 * 4 + 0][m] = f2tf32(bR[r].x);
                Bs[sn][lc4 * 4 + 1][m] = f2tf32(bR[r].y);
                Bs[sn][lc4 * 4 + 2][m] = f2tf32(bR[r].z);
                Bs[sn][lc4 * 4 + 3][m] = f2tf32(bR[r].w);
            }
        }
        __syncthreads();
    }

#pragma unroll
    for (int i = 0; i < 4; i++) {
        int m = row0 + wm0 + i * 16 + g;
#pragma unroll
        for (int j = 0; j < 4; j++) {
            int n = col0 + wn0 + j * 8 + tig * 2;
            float2 lo = make_float2(acc[i][j][0], acc[i][j][1]);
            float2 hi = make_float2(acc[i][j][2], acc[i][j][3]);
            if (HAS_BIAS) {
                float2 bb = *(const float2*)&bias[n];
                lo.x += bb.x; lo.y += bb.y;
                hi.x += bb.x; hi.y += bb.y;
            }
            *(float2*)&C[(long long)m * ldc + n]       = lo;
            *(float2*)&C[(long long)(m + 8) * ldc + n] = hi;
        }
    }
}

// --------- 128x128 bf16 GEMM tile: Cbf16 = A @ B^T (fp32 in, bf16 out) ----
__device__ __forceinline__ void bf16_gemm128_obf(
    const float* __restrict__ A, int lda,
    const float* __restrict__ B, int ldb,
    __nv_bfloat16* __restrict__ C, int ldc,
    int K, int row0, int col0)
{
    __shared__ uint32_t As[16][136];
    __shared__ uint32_t Bs[16][136];

    const int tid = threadIdx.x;
    const int lane = tid & 31;
    const int g = lane >> 2, tig = lane & 3;
    const int warp = tid >> 5;
    const int wm0 = (warp >> 2) * 64;
    const int wn0 = (warp & 3) * 32;
    const int lrow = tid >> 2, lc4 = tid & 3;

    float acc[4][4][4] = {};

    for (int k0 = 0; k0 < K; k0 += 32) {
#pragma unroll
        for (int r = 0; r < 2; r++) {
            int m = lrow + r * 64;
            const float* ap = A + (long long)(row0 + m) * lda + k0 + lc4 * 8;
            float4 a0 = *(const float4*)ap;
            float4 a1 = *(const float4*)(ap + 4);
            As[lc4 * 4 + 0][m] = packbf(a0.x, a0.y);
            As[lc4 * 4 + 1][m] = packbf(a0.z, a0.w);
            As[lc4 * 4 + 2][m] = packbf(a1.x, a1.y);
            As[lc4 * 4 + 3][m] = packbf(a1.z, a1.w);
            const float* bp = B + (long long)(col0 + m) * ldb + k0 + lc4 * 8;
            float4 b0 = *(const float4*)bp;
            float4 b1 = *(const float4*)(bp + 4);
            Bs[lc4 * 4 + 0][m] = packbf(b0.x, b0.y);
            Bs[lc4 * 4 + 1][m] = packbf(b0.z, b0.w);
            Bs[lc4 * 4 + 2][m] = packbf(b1.x, b1.y);
            Bs[lc4 * 4 + 3][m] = packbf(b1.z, b1.w);
        }
        __syncthreads();
#pragma unroll
        for (int kc = 0; kc < 2; kc++) {
            const int kb = kc * 8;
            uint32_t af[4][4], bf[4][2];
#pragma unroll
            for (int i = 0; i < 4; i++) {
                int m = wm0 + i * 16 + g;
                af[i][0] = As[kb + tig][m];
                af[i][1] = As[kb + tig][m + 8];
                af[i][2] = As[kb + tig + 4][m];
                af[i][3] = As[kb + tig + 4][m + 8];
            }
#pragma unroll
            for (int j = 0; j < 4; j++) {
                int n = wn0 + j * 8 + g;
                bf[j][0] = Bs[kb + tig][n];
                bf[j][1] = Bs[kb + tig + 4][n];
            }
#pragma unroll
            for (int i = 0; i < 4; i++)
#pragma unroll
                for (int j = 0; j < 4; j++)
                    mma_bf16(acc[i][j], af[i], bf[j]);
        }
        __syncthreads();
    }

#pragma unroll
    for (int i = 0; i < 4; i++) {
        int m = row0 + wm0 + i * 16 + g;
#pragma unroll
        for (int j = 0; j < 4; j++) {
            int n = col0 + wn0 + j * 8 + tig * 2;
            *(uint32_t*)&C[(long long)m * ldc + n]       = packbf(acc[i][j][0], acc[i][j][1]);
            *(uint32_t*)&C[(long long)(m + 8) * ldc + n] = packbf(acc[i][j][2], acc[i][j][3]);
        }
    }
}

// ---------------- Q/K projections (bf16 out). grid (12,4,6), 256 thr ---------
__global__ __launch_bounds__(256, 2) void projqk_kernel(const float* __restrict__ hidden,
                                                        EncParams p) {
    int z = blockIdx.z, inst = z & 1, b = z >> 1;
    int sector = blockIdx.x / 6;                 // 0=Q, 1=K
    int colL = (blockIdx.x % 6) * 128;
    int row0 = blockIdx.y * 128;
    const float* A = hidden + (long long)b * SEQP * DIM;
    const float* W = sector == 0 ? p.Wq[inst] : p.Wk[inst];
    bf16_gemm128_obf(A, DIM, W, DIM, &g_QKbf[z][0][sector * DIM], 2 * DIM, DIM, row0, colL);
}

// ---------------- V projection (tf32, fp32 out). grid (6,4,6), 256 thr -------
__global__ __launch_bounds__(256) void projv_kernel(const float* __restrict__ hidden,
                                                    EncParams p) {
    int z = blockIdx.z, inst = z & 1, b = z >> 1;
    const float* A = hidden + (long long)b * SEQP * DIM;
    tf32_gemm128<true>(A, DIM, p.Wv[inst], DIM, &g_V[z][0][0], DIM, DIM, p.bv[inst],
                       blockIdx.y * 128, (blockIdx.x % 6) * 128);
}

// ---------------- content bias + log(count). grid (512, 3), 128 thr ----------
__global__ void cb_kernel(const float* __restrict__ hidden, EncParams p) {
    int b = blockIdx.y;
    const float* row = hidden + ((long long)b * SEQP + blockIdx.x) * DIM;
    __shared__ float sh[DIM];
    for (int i = threadIdx.x; i < DIM; i += 128) sh[i] = row[i];
    __syncthreads();
    int warp = threadIdx.x >> 5, lane = threadIdx.x & 31;
#pragma unroll
    for (int q = 0; q < 8; q++) {
        int idx = warp * 8 + q;                  // 0..31 = inst*16 + h
        int inst = idx >> 4, h = idx & 15;
        const float* w = p.Wcb[inst] + h * DIM;
        float s = 0.f;
        for (int i = lane; i < DIM; i += 32) s += sh[i] * w[i];
#pragma unroll
        for (int o = 16; o > 0; o >>= 1) s += __shfl_xor_sync(0xffffffffu, s, o);
        if (lane == 0) {
            float cnt = g_cnt[(b * 2 + (1 - inst)) * SEQP + blockIdx.x];
            g_cbk[b * 2 + inst][h][blockIdx.x] = s * INV_SCALE + logf(cnt);
        }
    }
}

// ============ fused attention: scores + count-softmax + PV, double-buffered ====
// grid (8, 96): 64 q-rows per CTA, z96 = inst6*16 + h. 256 threads.
#define AS_OFF(st) ((st) * 1152)
#define BS_OFF(st) (2304 + (st) * 2176)

__global__ __launch_bounds__(256, 2) void attn_kernel(EncParams p) {
    const int z = blockIdx.y;
    const int inst6 = z >> 4, h = z & 15, inst = inst6 & 1;
    const int row0 = blockIdx.x * 64;
    const __nv_bfloat16* Qg = &g_QKbf[inst6][0][0];
    const __nv_bfloat16* Kg = &g_QKbf[inst6][0][DIM];
    const float* Vg = &g_V[inst6][0][h * DH];
    const float* mix = p.mix[inst] + h * DIM;

    // uSh: S-phase As0/As1 (16x72 each) + Bs0/Bs1 (16x136 each);
    // P-phase overlays [0, 4608) after final S-stage sync.
    __shared__ uint32_t uSh[6656];
    __shared__ uint32_t Vs[64][56];
    __shared__ uint32_t mixbf[DIM / 2];
    __shared__ float cbk[SEQP];
    __shared__ float redsum[4][64];
    __shared__ float lfin[64];

    const int tid = threadIdx.x;
    const int lane = tid & 31, warp = tid >> 5;
    const int g = lane >> 2, tig = lane & 3;
    const int wm0 = (warp >> 2) * 32;            // scores: 2x4 warps, warp 32x32
    const int wn0 = (warp & 3) * 32;
    const int wmp = (warp >> 1) * 16;            // pv: 4x2 warps, warp 16x24
    const int wnp = (warp & 1) * 24;
    const int lrow = tid >> 2, lc4 = tid & 3;    // loaders: 64 rows x 4 uint4-quarters

    for (int i = tid; i < DIM / 2; i += 256) {
        float2 mf = *(const float2*)&mix[i * 2];
        mixbf[i] = packbf(mf.x, mf.y);
    }
    for (int i = tid; i < SEQP; i += 256) cbk[i] = g_cbk[inst6][h][i];
    __syncthreads();

    float accO[3][4] = {};                        // O (unnormalized), warp 16x24
    float lpart[2][2] = {};                       // row sums
    float accS[2][4][4];

    uint32_t qreg[4];
    uint4 kreg0, kreg1;

    auto load_tile = [&](int kv0, int k0) {
        uint4 qv = *(const uint4*)(Qg + (long long)(row0 + lrow) * (2 * DIM) + k0 + lc4 * 8);
        uint32_t q[4] = {qv.x, qv.y, qv.z, qv.w};
#pragma unroll
        for (int c = 0; c < 4; c++) {
            uint32_t mx = mixbf[k0 / 2 + lc4 * 4 + c];
            __nv_bfloat162 r2 = __hmul2(*(__nv_bfloat162*)&q[c], *(__nv_bfloat162*)&mx);
            qreg[c] = *(uint32_t*)&r2;
        }
        kreg0 = *(const uint4*)(Kg + (long long)(kv0 + lrow) * (2 * DIM) + k0 + lc4 * 8);
        kreg1 = *(const uint4*)(Kg + (long long)(kv0 + lrow + 64) * (2 * DIM) + k0 + lc4 * 8);
    };

    auto sts_tile = [&](int st) {
        const int a = AS_OFF(st), b = BS_OFF(st);
#pragma unroll
        for (int c = 0; c < 4; c++)
            uSh[a + (lc4 * 4 + c) * 72 + lrow] = qreg[c];
        uSh[b + (lc4 * 4 + 0) * 136 + lrow] = kreg0.x;
        uSh[b + (lc4 * 4 + 1) * 136 + lrow] = kreg0.y;
        uSh[b + (lc4 * 4 + 2) * 136 + lrow] = kreg0.z;
        uSh[b + (lc4 * 4 + 3) * 136 + lrow] = kreg0.w;
        uSh[b + (lc4 * 4 + 0) * 136 + lrow + 64] = kreg1.x;
        uSh[b + (lc4 * 4 + 1) * 136 + lrow + 64] = kreg1.y;
        uSh[b + (lc4 * 4 + 2) * 136 + lrow + 64] = kreg1.z;
        uSh[b + (lc4 * 4 + 3) * 136 + lrow + 64] = kreg1.w;
    };

    auto mma_stage = [&](int st) {
        const int a = AS_OFF(st), b = BS_OFF(st);
#pragma unroll
        for (int kc = 0; kc < 2; kc++) {
            const int kb = kc * 8;
            uint32_t af[2][4], bf[4][2];
#pragma unroll
            for (int i = 0; i < 2; i++) {
                int m = wm0 + i * 16 + g;
                af[i][0] = uSh[a + (kb + tig) * 72 + m];
                af[i][1] = uSh[a + (kb + tig) * 72 + m + 8];
                af[i][2] = uSh[a + (kb + tig + 4) * 72 + m];
                af[i][3] = uSh[a + (kb + tig + 4) * 72 + m + 8];
            }
#pragma unroll
            for (int j = 0; j < 4; j++) {
                int n = wn0 + j * 8 + g;
                bf[j][0] = uSh[b + (kb + tig) * 136 + n];
                bf[j][1] = uSh[b + (kb + tig + 4) * 136 + n];
            }
#pragma unroll
            for (int i = 0; i < 2; i++)
#pragma unroll
                for (int j = 0; j < 4; j++)
                    mma_bf16(accS[i][j], af[i], bf[j]);
        }
    };

    for (int kv0 = 0; kv0 < SEQP; kv0 += 128) {
#pragma unroll
        for (int i = 0; i < 2; i++)
#pragma unroll
            for (int j = 0; j < 4; j++)
#pragma unroll
                for (int c = 0; c < 4; c++) accS[i][j][c] = 0.f;

        // ---- S = (Q*mix) @ K_blk^T : 64x128, double-buffered k-tiles of 32 ----
        load_tile(kv0, 0);
        sts_tile(0);
        __syncthreads();
#pragma unroll 4
        for (int kt = 0; kt < 24; kt++) {
            const int st = kt & 1;
            if (kt < 23) load_tile(kv0, (kt + 1) * 32);
            mma_stage(st);
            if (kt < 23) sts_tile(st ^ 1);
            __syncthreads();
        }

        // ---- P = exp(S*INV_SCALE + cbk[t]); accumulate l; store P (overlays) ----
#pragma unroll
        for (int i = 0; i < 2; i++) {
#pragma unroll
            for (int j = 0; j < 4; j++) {
                int colA = kv0 + wn0 + j * 8 + tig * 2;
                float c0 = cbk[colA], c1 = cbk[colA + 1];
                float w0 = __expf(accS[i][j][0] * INV_SCALE + c0);
                float w1 = __expf(accS[i][j][1] * INV_SCALE + c1);
                float w2 = __expf(accS[i][j][2] * INV_SCALE + c0);
                float w3 = __expf(accS[i][j][3] * INV_SCALE + c1);
                lpart[i][0] += w0 + w1;
                lpart[i][1] += w2 + w3;
                int kp = (wn0 >> 1) + j * 4 + tig;
                int m = wm0 + i * 16 + g;
                uSh[kp * 72 + m]     = packbf(w0, w1);
                uSh[kp * 72 + m + 8] = packbf(w2, w3);
            }
        }
        // ---- load V block (128 x 48 fp32 -> bf16 k-pairs) ----
#pragma unroll
        for (int r = 0; r < 3; r++) {
            int idx = tid + r * 256;                 // 0..767 = 64 kpairs x 12 n4
            int kp = idx / 12, n4 = idx % 12;
            const float* b0 = Vg + (long long)(kv0 + kp * 2) * DIM + n4 * 4;
            float4 v0 = *(const float4*)b0;
            float4 v1 = *(const float4*)(b0 + DIM);
            Vs[kp][n4 * 4 + 0] = packbf(v0.x, v1.x);
            Vs[kp][n4 * 4 + 1] = packbf(v0.y, v1.y);
            Vs[kp][n4 * 4 + 2] = packbf(v0.z, v1.z);
            Vs[kp][n4 * 4 + 3] = packbf(v0.w, v1.w);
        }
        __syncthreads();

        // ---- O += P @ V_blk : 64x48, k=128 ----
#pragma unroll
        for (int kb8 = 0; kb8 < 8; kb8++) {
            const int kb = kb8 * 8;
            uint32_t af[4], bf2[3][2];
            int m = wmp + g;
            af[0] = uSh[(kb + tig) * 72 + m];
            af[1] = uSh[(kb + tig) * 72 + m + 8];
            af[2] = uSh[(kb + tig + 4) * 72 + m];
            af[3] = uSh[(kb + tig + 4) * 72 + m + 8];
#pragma unroll
            for (int j = 0; j < 3; j++) {
                int n = wnp + j * 8 + g;
                bf2[j][0] = Vs[kb + tig][n];
                bf2[j][1] = Vs[kb + tig + 4][n];
            }
#pragma unroll
            for (int j = 0; j < 3; j++)
                mma_bf16(accO[j], af, bf2[j]);
        }
        __syncthreads();   // Pp/Vs consumed before next block overwrites
    }

    // ---- reduce l across quad (tig) + across the 4 warp-cols ----
#pragma unroll
    for (int i = 0; i < 2; i++)
#pragma unroll
        for (int hf = 0; hf < 2; hf++) {
            float v = lpart[i][hf];
            v += __shfl_xor_sync(0xffffffffu, v, 1);
            v += __shfl_xor_sync(0xffffffffu, v, 2);
            lpart[i][hf] = v;
        }
    if (tig == 0) {
#pragma unroll
        for (int i = 0; i < 2; i++)
#pragma unroll
            for (int hf = 0; hf < 2; hf++)
                redsum[warp & 3][wm0 + i * 16 + g + hf * 8] = lpart[i][hf];
    }
    __syncthreads();
    if (tid < 64) lfin[tid] = redsum[0][tid] + redsum[1][tid] + redsum[2][tid] + redsum[3][tid];
    __syncthreads();

    // ---- epilogue: ctx = O / l ----
    float* C = &g_ctx[inst6][0][h * DH];
    int mrow = wmp + g;
    float inv0 = 1.f / lfin[mrow];
    float inv1 = 1.f / lfin[mrow + 8];
#pragma unroll
    for (int j = 0; j < 3; j++) {
        int n = wnp + j * 8 + tig * 2;
        *(float2*)&C[(long long)(row0 + mrow) * DIM + n] =
            make_float2(accO[j][0] * inv0, accO[j][1] * inv0);
        *(float2*)&C[(long long)(row0 + mrow + 8) * DIM + n] =
            make_float2(accO[j][2] * inv1, accO[j][3] * inv1);
    }
}

// ---------------- output projection (tf32). grid (6,4,6), 256 thr -------------
__global__ __launch_bounds__(256) void wd_kernel(EncParams p) {
    int z = blockIdx.z, inst = z & 1;
    tf32_gemm128<true>(&g_ctx[z][0][0], DIM, p.Wd[inst], DIM,
                       &g_dproj[z][0][0], DIM, DIM, p.bd[inst],
                       blockIdx.y * 128, blockIdx.x * 128);
}

// ---------------- block reduce (for LN) ----------------
__device__ __forceinline__ float blockReduceSum(float v) {
    __shared__ float sh[8];
    __shared__ float res;
#pragma unroll
    for (int o = 16; o > 0; o >>= 1) v += __shfl_xor_sync(0xffffffffu, v, o);
    __syncthreads();
    if ((threadIdx.x & 31) == 0) sh[threadIdx.x >> 5] = v;
    __syncthreads();
    if (threadIdx.x == 0) {
        float s = 0.f;
        for (int i = 0; i < 8; i++) s += sh[i];
        res = s;
    }
    __syncthreads();
    return res;
}

// ---------------- residual + LN + count weighting. grid (512, 6), 256 thr -----
__global__ void ln_kernel(const float* __restrict__ hidden, EncParams p) {
    int pos = blockIdx.x, z = blockIdx.y, inst = z & 1, b = z >> 1;
    const float* hr = hidden + ((long long)b * SEQP + pos) * DIM;
    const float* dr = &g_dproj[z][pos][0];
    const float* lng = p.lng[inst];
    const float* lnb = p.lnb[inst];
    float x[3];
    float s = 0.f;
#pragma unroll
    for (int i = 0; i < 3; i++) {
        int j = threadIdx.x + i * 256;
        x[i] = hr[j] + dr[j];
        s += x[i];
    }
    float mu = blockReduceSum(s) * (1.f / DIM);
    float vs = 0.f;
#pragma unroll
    for (int i = 0; i < 3; i++) {
        float d = x[i] - mu;
        vs += d * d;
    }
    float var = blockReduceSum(vs) * (1.f / DIM);
    float inv = rsqrtf(var + 1e-5f);
    float w = g_cnt[(b * 2 + inst) * SEQP + pos] * (1.f / 2048.f);
#pragma unroll
    for (int i = 0; i < 3; i++) {
        int j = threadIdx.x + i * 256;
        g_y[z][pos][j] = (lng[j] * (x[i] - mu) * inv + lnb[j]) * w;
    }
}

// ---------------- output zero + parallel column sum ----------------
__global__ void zero_out_kernel(float* __restrict__ out, int n) {
    int i = blockIdx.x * blockDim.x + threadIdx.x;
    if (i < n) out[i] = 0.f;
}

// grid (3, 6, 8): each block sums 64 rows for 256 columns, atomicAdd into out.
__global__ void colsum_kernel(float* __restrict__ out) {
    int z = blockIdx.y;
    int j = blockIdx.x * 256 + threadIdx.x;
    int p0 = blockIdx.z * 64;
    const float* Y = &g_y[z][0][0];
    float s = 0.f;
#pragma unroll 8
    for (int p = p0; p < p0 + 64; p++) s += Y[(long long)p * DIM + j];
    atomicAdd(&out[(z >> 1) * 2 * DIM + (z & 1) * DIM + j], s);
}

// ---------------- host ----------------
extern "C" void kernel_launch(void* const* d_in, const int* in_sizes, int n_in,
                              void* d_out, int out_size) {
    const float* hidden = (const float*)d_in[0];
    const int* fpos = (const int*)d_in[1];
    const int* tpos = (const int*)d_in[2];
    float* out = (float*)d_out;

    EncParams p;
    for (int inst = 0; inst < 2; inst++) {
        void* const* P = d_in + 3 + inst * 10;
        p.Wq[inst]  = (const float*)P[0];
        p.Wk[inst]  = (const float*)P[1];
        p.Wcb[inst] = (const float*)P[2];
        p.Wv[inst]  = (const float*)P[3];
        p.Wd[inst]  = (const float*)P[4];
        p.mix[inst] = (const float*)P[5];
        p.bv[inst]  = (const float*)P[6];
        p.bd[inst]  = (const float*)P[7];
        p.lng[inst] = (const float*)P[8];
        p.lnb[inst] = (const float*)P[9];
    }

    zero_counts_kernel<<<6, 512>>>();
    count_kernel<<<(3 * NF + 255) / 256, 256>>>(fpos, tpos);

    projqk_kernel<<<dim3(12, 4, 6), 256>>>(hidden, p);   // Q,K bf16
    projv_kernel<<<dim3(6, 4, 6), 256>>>(hidden, p);     // V tf32 (double-buffered)
    cb_kernel<<<dim3(512, 3), 128>>>(hidden, p);         // cb*scale + log(cnt)
    attn_kernel<<<dim3(8, 96), 256>>>(p);                // fused attn (double-buffered)
    wd_kernel<<<dim3(6, 4, 6), 256>>>(p);                // tf32 output projection
    ln_kernel<<<dim3(512, 6), 256>>>(hidden, p);         // residual + LN + weight
    zero_out_kernel<<<(3 * 2 * DIM + 255) / 256, 256>>>(out, 3 * 2 * DIM);
    colsum_kernel<<<dim3(3, 6, 8), 256>>>(out);          // weighted mean -> out
}

// round 15
// speedup vs baseline: 9.1515x; 1.0266x over previous
#include <cuda_runtime.h>
#include <cuda_bf16.h>
#include <math.h>
#include <stdint.h>

#define SEQP 512
#define DIM 768
#define NH 16
#define DH 48
#define NF 2048
#define INV_SCALE 0.14433756729740643f  // 1/sqrt(768/16)

// ---------------- scratch ----------------
__device__ float g_cnt[3 * 2 * SEQP];
__device__ __nv_bfloat16 g_QKbf[6][SEQP][2 * DIM];   // per z6: Q | K  (bf16)
__device__ float g_V[6][SEQP][DIM];                  // V (+bv), fp32 (value path)
__device__ float g_cbk[6][NH][SEQP];                 // cb*INV_SCALE + log(kcnt)
__device__ float g_ctx[6][SEQP][DIM];
__device__ float g_dproj[6][SEQP][DIM];
__device__ float g_y[6][SEQP][DIM];

struct EncParams {
    const float *Wq[2], *Wk[2], *Wv[2], *Wcb[2], *Wd[2], *mix[2];
    const float *bv[2], *bd[2], *lng[2], *lnb[2];
};

// ---------------- counts ----------------
__global__ void zero_counts_kernel() {
    int i = blockIdx.x * blockDim.x + threadIdx.x;
    if (i < 3 * 2 * SEQP) g_cnt[i] = 0.f;
}

__global__ void count_kernel(const int* __restrict__ fpos, const int* __restrict__ tpos) {
    int i = blockIdx.x * blockDim.x + threadIdx.x;
    if (i >= 3 * NF) return;
    int b = i / NF;
    atomicAdd(&g_cnt[(b * 2 + 0) * SEQP + (fpos[i] & (SEQP - 1))], 1.f);
    atomicAdd(&g_cnt[(b * 2 + 1) * SEQP + (tpos[i] & (SEQP - 1))], 1.f);
}

// ================= mma primitives =================
__device__ __forceinline__ uint32_t f2tf32(float v) {
    uint32_t u;
    asm("cvt.rna.tf32.f32 %0, %1;" : "=r"(u) : "f"(v));
    return u;
}

__device__ __forceinline__ void mma_tf32(float* c, const uint32_t* a, const uint32_t* b) {
    asm volatile(
        "mma.sync.aligned.m16n8k8.row.col.f32.tf32.tf32.f32 "
        "{%0,%1,%2,%3}, {%4,%5,%6,%7}, {%8,%9}, {%0,%1,%2,%3};\n"
        : "+f"(c[0]), "+f"(c[1]), "+f"(c[2]), "+f"(c[3])
        : "r"(a[0]), "r"(a[1]), "r"(a[2]), "r"(a[3]), "r"(b[0]), "r"(b[1]));
}

__device__ __forceinline__ void mma_bf16(float* c, const uint32_t* a, const uint32_t* b) {
    asm volatile(
        "mma.sync.aligned.m16n8k16.row.col.f32.bf16.bf16.f32 "
        "{%0,%1,%2,%3}, {%4,%5,%6,%7}, {%8,%9}, {%0,%1,%2,%3};\n"
        : "+f"(c[0]), "+f"(c[1]), "+f"(c[2]), "+f"(c[3])
        : "r"(a[0]), "r"(a[1]), "r"(a[2]), "r"(a[3]), "r"(b[0]), "r"(b[1]));
}

__device__ __forceinline__ uint32_t packbf(float x, float y) {
    __nv_bfloat162 h = __float22bfloat162_rn(make_float2(x, y));
    return *(uint32_t*)&h;
}

// --------- 128x128 tf32 GEMM tile, double-buffered: C = A @ B^T (+bias) ----
// sh layout (uint32): A stage st at st*2112, B stage st at 4224+st*2112; row stride 132.
// Total 8448 u32.
template <bool HAS_BIAS>
__device__ __forceinline__ void tf32_gemm128(
    uint32_t* sh,
    const float* __restrict__ A, int lda,
    const float* __restrict__ B, int ldb,
    float* __restrict__ C, int ldc,
    int K, const float* __restrict__ bias,
    int row0, int col0)
{
    const int tid = threadIdx.x;
    const int lane = tid & 31;
    const int g = lane >> 2, tig = lane & 3;
    const int warp = tid >> 5;
    const int wm0 = (warp >> 2) * 64;
    const int wn0 = (warp & 3) * 32;
    const int lrow = tid >> 2, lc4 = tid & 3;

    float4 aR[2], bR[2];

    auto ldg = [&](int k0) {
#pragma unroll
        for (int r = 0; r < 2; r++) {
            int m = lrow + r * 64;
            aR[r] = *(const float4*)(A + (long long)(row0 + m) * lda + k0 + lc4 * 4);
            bR[r] = *(const float4*)(B + (long long)(col0 + m) * ldb + k0 + lc4 * 4);
        }
    };
    auto sts = [&](int st) {
        uint32_t* As = sh + st * 2112;
        uint32_t* Bs = sh + 4224 + st * 2112;
#pragma unroll
        for (int r = 0; r < 2; r++) {
            int m = lrow + r * 64;
            As[(lc4 * 4 + 0) * 132 + m] = f2tf32(aR[r].x);
            As[(lc4 * 4 + 1) * 132 + m] = f2tf32(aR[r].y);
            As[(lc4 * 4 + 2) * 132 + m] = f2tf32(aR[r].z);
            As[(lc4 * 4 + 3) * 132 + m] = f2tf32(aR[r].w);
            Bs[(lc4 * 4 + 0) * 132 + m] = f2tf32(bR[r].x);
            Bs[(lc4 * 4 + 1) * 132 + m] = f2tf32(bR[r].y);
            Bs[(lc4 * 4 + 2) * 132 + m] = f2tf32(bR[r].z);
            Bs[(lc4 * 4 + 3) * 132 + m] = f2tf32(bR[r].w);
        }
    };

    ldg(0);
    sts(0);
    __syncthreads();

    float acc[4][4][4] = {};
    const int NT = K / 16;

    for (int t = 0; t < NT; t++) {
        const int st = t & 1;
        if (t + 1 < NT) ldg((t + 1) * 16);
        const uint32_t* As = sh + st * 2112;
        const uint32_t* Bs = sh + 4224 + st * 2112;
#pragma unroll
        for (int ks = 0; ks < 2; ks++) {
            const int kb = ks * 8;
            uint32_t af[4][4], bf[4][2];
#pragma unroll
            for (int i = 0; i < 4; i++) {
                int m = wm0 + i * 16 + g;
                af[i][0] = As[(kb + tig) * 132 + m];
                af[i][1] = As[(kb + tig) * 132 + m + 8];
                af[i][2] = As[(kb + tig + 4) * 132 + m];
                af[i][3] = As[(kb + tig + 4) * 132 + m + 8];
            }
#pragma unroll
            for (int j = 0; j < 4; j++) {
                int n = wn0 + j * 8 + g;
                bf[j][0] = Bs[(kb + tig) * 132 + n];
                bf[j][1] = Bs[(kb + tig + 4) * 132 + n];
            }
#pragma unroll
            for (int i = 0; i < 4; i++)
#pragma unroll
                for (int j = 0; j < 4; j++)
                    mma_tf32(acc[i][j], af[i], bf[j]);
        }
        if (t + 1 < NT) sts(st ^ 1);
        __syncthreads();
    }

#pragma unroll
    for (int i = 0; i < 4; i++) {
        int m = row0 + wm0 + i * 16 + g;
#pragma unroll
        for (int j = 0; j < 4; j++) {
            int n = col0 + wn0 + j * 8 + tig * 2;
            float2 lo = make_float2(acc[i][j][0], acc[i][j][1]);
            float2 hi = make_float2(acc[i][j][2], acc[i][j][3]);
            if (HAS_BIAS) {
                float2 bb = *(const float2*)&bias[n];
                lo.x += bb.x; lo.y += bb.y;
                hi.x += bb.x; hi.y += bb.y;
            }
            *(float2*)&C[(long long)m * ldc + n]       = lo;
            *(float2*)&C[(long long)(m + 8) * ldc + n] = hi;
        }
    }
}

// --------- 128x128 bf16 GEMM tile, double-buffered: Cbf16 = A @ B^T ----
// sh layout (uint32): A stage st at st*2176, B stage st at 4352+st*2176; row stride 136.
// Total 8704 u32.
__device__ __forceinline__ void bf16_gemm128_obf(
    uint32_t* sh,
    const float* __restrict__ A, int lda,
    const float* __restrict__ B, int ldb,
    __nv_bfloat16* __restrict__ C, int ldc,
    int K, int row0, int col0)
{
    const int tid = threadIdx.x;
    const int lane = tid & 31;
    const int g = lane >> 2, tig = lane & 3;
    const int warp = tid >> 5;
    const int wm0 = (warp >> 2) * 64;
    const int wn0 = (warp & 3) * 32;
    const int lrow = tid >> 2, lc4 = tid & 3;

    float4 aR[2][2], bR[2][2];

    auto ldg = [&](int k0) {
#pragma unroll
        for (int r = 0; r < 2; r++) {
            int m = lrow + r * 64;
            const float* ap = A + (long long)(row0 + m) * lda + k0 + lc4 * 8;
            aR[r][0] = *(const float4*)ap;
            aR[r][1] = *(const float4*)(ap + 4);
            const float* bp = B + (long long)(col0 + m) * ldb + k0 + lc4 * 8;
            bR[r][0] = *(const float4*)bp;
            bR[r][1] = *(const float4*)(bp + 4);
        }
    };
    auto sts = [&](int st) {
        uint32_t* As = sh + st * 2176;
        uint32_t* Bs = sh + 4352 + st * 2176;
#pragma unroll
        for (int r = 0; r < 2; r++) {
            int m = lrow + r * 64;
            As[(lc4 * 4 + 0) * 136 + m] = packbf(aR[r][0].x, aR[r][0].y);
            As[(lc4 * 4 + 1) * 136 + m] = packbf(aR[r][0].z, aR[r][0].w);
            As[(lc4 * 4 + 2) * 136 + m] = packbf(aR[r][1].x, aR[r][1].y);
            As[(lc4 * 4 + 3) * 136 + m] = packbf(aR[r][1].z, aR[r][1].w);
            Bs[(lc4 * 4 + 0) * 136 + m] = packbf(bR[r][0].x, bR[r][0].y);
            Bs[(lc4 * 4 + 1) * 136 + m] = packbf(bR[r][0].z, bR[r][0].w);
            Bs[(lc4 * 4 + 2) * 136 + m] = packbf(bR[r][1].x, bR[r][1].y);
            Bs[(lc4 * 4 + 3) * 136 + m] = packbf(bR[r][1].z, bR[r][1].w);
        }
    };

    ldg(0);
    sts(0);
    __syncthreads();

    float acc[4][4][4] = {};
    const int NT = K / 32;

    for (int t = 0; t < NT; t++) {
        const int st = t & 1;
        if (t + 1 < NT) ldg((t + 1) * 32);
        const uint32_t* As = sh + st * 2176;
        const uint32_t* Bs = sh + 4352 + st * 2176;
#pragma unroll
        for (int kc = 0; kc < 2; kc++) {
            const int kb = kc * 8;
            uint32_t af[4][4], bf[4][2];
#pragma unroll
            for (int i = 0; i < 4; i++) {
                int m = wm0 + i * 16 + g;
                af[i][0] = As[(kb + tig) * 136 + m];
                af[i][1] = As[(kb + tig) * 136 + m + 8];
                af[i][2] = As[(kb + tig + 4) * 136 + m];
                af[i][3] = As[(kb + tig + 4) * 136 + m + 8];
            }
#pragma unroll
            for (int j = 0; j < 4; j++) {
                int n = wn0 + j * 8 + g;
                bf[j][0] = Bs[(kb + tig) * 136 + n];
                bf[j][1] = Bs[(kb + tig + 4) * 136 + n];
            }
#pragma unroll
            for (int i = 0; i < 4; i++)
#pragma unroll
                for (int j = 0; j < 4; j++)
                    mma_bf16(acc[i][j], af[i], bf[j]);
        }
        if (t + 1 < NT) sts(st ^ 1);
        __syncthreads();
    }

#pragma unroll
    for (int i = 0; i < 4; i++) {
        int m = row0 + wm0 + i * 16 + g;
#pragma unroll
        for (int j = 0; j < 4; j++) {
            int n = col0 + wn0 + j * 8 + tig * 2;
            *(uint32_t*)&C[(long long)m * ldc + n]       = packbf(acc[i][j][0], acc[i][j][1]);
            *(uint32_t*)&C[(long long)(m + 8) * ldc + n] = packbf(acc[i][j][2], acc[i][j][3]);
        }
    }
}

// ---------------- merged projections: Q,K (bf16) + V (tf32). grid 432 --------
// blocks [0,288): projqk (12 x-tiles, 4 row-tiles, 6 z); [288,432): projv (6,4,6)
__global__ __launch_bounds__(256, 2) void proj_kernel(const float* __restrict__ hidden,
                                                      EncParams p) {
    __shared__ uint32_t sh[8704];
    int bid = blockIdx.x;
    if (bid < 288) {
        int x = bid % 12, y = (bid / 12) % 4, z = bid / 48;
        int inst = z & 1, b = z >> 1;
        int sector = x / 6;                    // 0=Q, 1=K
        int colL = (x % 6) * 128;
        int row0 = y * 128;
        const float* A = hidden + (long long)b * SEQP * DIM;
        const float* W = sector == 0 ? p.Wq[inst] : p.Wk[inst];
        bf16_gemm128_obf(sh, A, DIM, W, DIM, &g_QKbf[z][0][sector * DIM], 2 * DIM,
                         DIM, row0, colL);
    } else {
        int id = bid - 288;
        int x = id % 6, y = (id / 6) % 4, z = id / 24;
        int inst = z & 1, b = z >> 1;
        const float* A = hidden + (long long)b * SEQP * DIM;
        tf32_gemm128<true>(sh, A, DIM, p.Wv[inst], DIM, &g_V[z][0][0], DIM, DIM,
                           p.bv[inst], y * 128, x * 128);
    }
}

// ---------------- content bias + log(count). grid (512, 3), 128 thr ----------
__global__ void cb_kernel(const float* __restrict__ hidden, EncParams p) {
    int b = blockIdx.y;
    const float* row = hidden + ((long long)b * SEQP + blockIdx.x) * DIM;
    __shared__ float sh[DIM];
    for (int i = threadIdx.x; i < DIM; i += 128) sh[i] = row[i];
    __syncthreads();
    int warp = threadIdx.x >> 5, lane = threadIdx.x & 31;
#pragma unroll
    for (int q = 0; q < 8; q++) {
        int idx = warp * 8 + q;                  // 0..31 = inst*16 + h
        int inst = idx >> 4, h = idx & 15;
        const float* w = p.Wcb[inst] + h * DIM;
        float s = 0.f;
        for (int i = lane; i < DIM; i += 32) s += sh[i] * w[i];
#pragma unroll
        for (int o = 16; o > 0; o >>= 1) s += __shfl_xor_sync(0xffffffffu, s, o);
        if (lane == 0) {
            float cnt = g_cnt[(b * 2 + (1 - inst)) * SEQP + blockIdx.x];
            g_cbk[b * 2 + inst][h][blockIdx.x] = s * INV_SCALE + logf(cnt);
        }
    }
}

// ============ fused attention: scores + count-softmax + PV, double-buffered ====
// grid (8, 96): 64 q-rows per CTA, z96 = inst6*16 + h. 256 threads.
#define AS_OFF(st) ((st) * 1152)
#define BS_OFF(st) (2304 + (st) * 2176)

__global__ __launch_bounds__(256, 2) void attn_kernel(EncParams p) {
    const int z = blockIdx.y;
    const int inst6 = z >> 4, h = z & 15, inst = inst6 & 1;
    const int row0 = blockIdx.x * 64;
    const __nv_bfloat16* Qg = &g_QKbf[inst6][0][0];
    const __nv_bfloat16* Kg = &g_QKbf[inst6][0][DIM];
    const float* Vg = &g_V[inst6][0][h * DH];
    const float* mix = p.mix[inst] + h * DIM;

    __shared__ uint32_t uSh[6656];
    __shared__ uint32_t Vs[64][56];
    __shared__ uint32_t mixbf[DIM / 2];
    __shared__ float cbk[SEQP];
    __shared__ float redsum[4][64];
    __shared__ float lfin[64];

    const int tid = threadIdx.x;
    const int lane = tid & 31, warp = tid >> 5;
    const int g = lane >> 2, tig = lane & 3;
    const int wm0 = (warp >> 2) * 32;            // scores: 2x4 warps, warp 32x32
    const int wn0 = (warp & 3) * 32;
    const int wmp = (warp >> 1) * 16;            // pv: 4x2 warps, warp 16x24
    const int wnp = (warp & 1) * 24;
    const int lrow = tid >> 2, lc4 = tid & 3;

    for (int i = tid; i < DIM / 2; i += 256) {
        float2 mf = *(const float2*)&mix[i * 2];
        mixbf[i] = packbf(mf.x, mf.y);
    }
    for (int i = tid; i < SEQP; i += 256) cbk[i] = g_cbk[inst6][h][i];
    __syncthreads();

    float accO[3][4] = {};
    float lpart[2][2] = {};
    float accS[2][4][4];

    uint32_t qreg[4];
    uint4 kreg0, kreg1;

    auto load_tile = [&](int kv0, int k0) {
        uint4 qv = *(const uint4*)(Qg + (long long)(row0 + lrow) * (2 * DIM) + k0 + lc4 * 8);
        uint32_t q[4] = {qv.x, qv.y, qv.z, qv.w};
#pragma unroll
        for (int c = 0; c < 4; c++) {
            uint32_t mx = mixbf[k0 / 2 + lc4 * 4 + c];
            __nv_bfloat162 r2 = __hmul2(*(__nv_bfloat162*)&q[c], *(__nv_bfloat162*)&mx);
            qreg[c] = *(uint32_t*)&r2;
        }
        kreg0 = *(const uint4*)(Kg + (long long)(kv0 + lrow) * (2 * DIM) + k0 + lc4 * 8);
        kreg1 = *(const uint4*)(Kg + (long long)(kv0 + lrow + 64) * (2 * DIM) + k0 + lc4 * 8);
    };

    auto sts_tile = [&](int st) {
        const int a = AS_OFF(st), b = BS_OFF(st);
#pragma unroll
        for (int c = 0; c < 4; c++)
            uSh[a + (lc4 * 4 + c) * 72 + lrow] = qreg[c];
        uSh[b + (lc4 * 4 + 0) * 136 + lrow] = kreg0.x;
        uSh[b + (lc4 * 4 + 1) * 136 + lrow] = kreg0.y;
        uSh[b + (lc4 * 4 + 2) * 136 + lrow] = kreg0.z;
        uSh[b + (lc4 * 4 + 3) * 136 + lrow] = kreg0.w;
        uSh[b + (lc4 * 4 + 0) * 136 + lrow + 64] = kreg1.x;
        uSh[b + (lc4 * 4 + 1) * 136 + lrow + 64] = kreg1.y;
        uSh[b + (lc4 * 4 + 2) * 136 + lrow + 64] = kreg1.z;
        uSh[b + (lc4 * 4 + 3) * 136 + lrow + 64] = kreg1.w;
    };

    auto mma_stage = [&](int st) {
        const int a = AS_OFF(st), b = BS_OFF(st);
#pragma unroll
        for (int kc = 0; kc < 2; kc++) {
            const int kb = kc * 8;
            uint32_t af[2][4], bf[4][2];
#pragma unroll
            for (int i = 0; i < 2; i++) {
                int m = wm0 + i * 16 + g;
                af[i][0] = uSh[a + (kb + tig) * 72 + m];
                af[i][1] = uSh[a + (kb + tig) * 72 + m + 8];
                af[i][2] = uSh[a + (kb + tig + 4) * 72 + m];
                af[i][3] = uSh[a + (kb + tig + 4) * 72 + m + 8];
            }
#pragma unroll
            for (int j = 0; j < 4; j++) {
                int n = wn0 + j * 8 + g;
                bf[j][0] = uSh[b + (kb + tig) * 136 + n];
                bf[j][1] = uSh[b + (kb + tig + 4) * 136 + n];
            }
#pragma unroll
            for (int i = 0; i < 2; i++)
#pragma unroll
                for (int j = 0; j < 4; j++)
                    mma_bf16(accS[i][j], af[i], bf[j]);
        }
    };

    for (int kv0 = 0; kv0 < SEQP; kv0 += 128) {
#pragma unroll
        for (int i = 0; i < 2; i++)
#pragma unroll
            for (int j = 0; j < 4; j++)
#pragma unroll
                for (int c = 0; c < 4; c++) accS[i][j][c] = 0.f;

        load_tile(kv0, 0);
        sts_tile(0);
        __syncthreads();
#pragma unroll 4
        for (int kt = 0; kt < 24; kt++) {
            const int st = kt & 1;
            if (kt < 23) load_tile(kv0, (kt + 1) * 32);
            mma_stage(st);
            if (kt < 23) sts_tile(st ^ 1);
            __syncthreads();
        }

        // ---- P = exp(S*INV_SCALE + cbk[t]); accumulate l; store P (overlays) ----
#pragma unroll
        for (int i = 0; i < 2; i++) {
#pragma unroll
            for (int j = 0; j < 4; j++) {
                int colA = kv0 + wn0 + j * 8 + tig * 2;
                float c0 = cbk[colA], c1 = cbk[colA + 1];
                float w0 = __expf(accS[i][j][0] * INV_SCALE + c0);
                float w1 = __expf(accS[i][j][1] * INV_SCALE + c1);
                float w2 = __expf(accS[i][j][2] * INV_SCALE + c0);
                float w3 = __expf(accS[i][j][3] * INV_SCALE + c1);
                lpart[i][0] += w0 + w1;
                lpart[i][1] += w2 + w3;
                int kp = (wn0 >> 1) + j * 4 + tig;
                int m = wm0 + i * 16 + g;
                uSh[kp * 72 + m]     = packbf(w0, w1);
                uSh[kp * 72 + m + 8] = packbf(w2, w3);
            }
        }
        // ---- load V block (128 x 48 fp32 -> bf16 k-pairs) ----
#pragma unroll
        for (int r = 0; r < 3; r++) {
            int idx = tid + r * 256;
            int kp = idx / 12, n4 = idx % 12;
            const float* b0 = Vg + (long long)(kv0 + kp * 2) * DIM + n4 * 4;
            float4 v0 = *(const float4*)b0;
            float4 v1 = *(const float4*)(b0 + DIM);
            Vs[kp][n4 * 4 + 0] = packbf(v0.x, v1.x);
            Vs[kp][n4 * 4 + 1] = packbf(v0.y, v1.y);
            Vs[kp][n4 * 4 + 2] = packbf(v0.z, v1.z);
            Vs[kp][n4 * 4 + 3] = packbf(v0.w, v1.w);
        }
        __syncthreads();

        // ---- O += P @ V_blk : 64x48, k=128 ----
#pragma unroll
        for (int kb8 = 0; kb8 < 8; kb8++) {
            const int kb = kb8 * 8;
            uint32_t af[4], bf2[3][2];
            int m = wmp + g;
            af[0] = uSh[(kb + tig) * 72 + m];
            af[1] = uSh[(kb + tig) * 72 + m + 8];
            af[2] = uSh[(kb + tig + 4) * 72 + m];
            af[3] = uSh[(kb + tig + 4) * 72 + m + 8];
#pragma unroll
            for (int j = 0; j < 3; j++) {
                int n = wnp + j * 8 + g;
                bf2[j][0] = Vs[kb + tig][n];
                bf2[j][1] = Vs[kb + tig + 4][n];
            }
#pragma unroll
            for (int j = 0; j < 3; j++)
                mma_bf16(accO[j], af, bf2[j]);
        }
        __syncthreads();
    }

    // ---- reduce l across quad (tig) + across the 4 warp-cols ----
#pragma unroll
    for (int i = 0; i < 2; i++)
#pragma unroll
        for (int hf = 0; hf < 2; hf++) {
            float v = lpart[i][hf];
            v += __shfl_xor_sync(0xffffffffu, v, 1);
            v += __shfl_xor_sync(0xffffffffu, v, 2);
            lpart[i][hf] = v;
        }
    if (tig == 0) {
#pragma unroll
        for (int i = 0; i < 2; i++)
#pragma unroll
            for (int hf = 0; hf < 2; hf++)
                redsum[warp & 3][wm0 + i * 16 + g + hf * 8] = lpart[i][hf];
    }
    __syncthreads();
    if (tid < 64) lfin[tid] = redsum[0][tid] + redsum[1][tid] + redsum[2][tid] + redsum[3][tid];
    __syncthreads();

    // ---- epilogue: ctx = O / l ----
    float* C = &g_ctx[inst6][0][h * DH];
    int mrow = wmp + g;
    float inv0 = 1.f / lfin[mrow];
    float inv1 = 1.f / lfin[mrow + 8];
#pragma unroll
    for (int j = 0; j < 3; j++) {
        int n = wnp + j * 8 + tig * 2;
        *(float2*)&C[(long long)(row0 + mrow) * DIM + n] =
            make_float2(accO[j][0] * inv0, accO[j][1] * inv0);
        *(float2*)&C[(long long)(row0 + mrow + 8) * DIM + n] =
            make_float2(accO[j][2] * inv1, accO[j][3] * inv1);
    }
}

// ---------------- output projection (tf32). grid (6,4,6), 256 thr -------------
__global__ __launch_bounds__(256) void wd_kernel(EncParams p) {
    __shared__ uint32_t sh[8448];
    int z = blockIdx.z, inst = z & 1;
    tf32_gemm128<true>(sh, &g_ctx[z][0][0], DIM, p.Wd[inst], DIM,
                       &g_dproj[z][0][0], DIM, DIM, p.bd[inst],
                       blockIdx.y * 128, blockIdx.x * 128);
}

// ---------------- residual + LN + count weighting, warp-per-position ---------
// grid (64, 6), 256 thr: 8 warps = 8 positions per block.
__global__ void ln_kernel(const float* __restrict__ hidden, EncParams p) {
    int z = blockIdx.y, inst = z & 1, b = z >> 1;
    int warp = threadIdx.x >> 5, lane = threadIdx.x & 31;
    int pos = blockIdx.x * 8 + warp;
    const float* hr = hidden + ((long long)b * SEQP + pos) * DIM;
    const float* dr = &g_dproj[z][pos][0];
    const float* lng = p.lng[inst];
    const float* lnb = p.lnb[inst];

    float x[24];
    float s = 0.f;
#pragma unroll
    for (int j = 0; j < 6; j++) {
        int c = (lane + j * 32) * 4;
        float4 hv = *(const float4*)&hr[c];
        float4 dv = *(const float4*)&dr[c];
        x[j * 4 + 0] = hv.x + dv.x;
        x[j * 4 + 1] = hv.y + dv.y;
        x[j * 4 + 2] = hv.z + dv.z;
        x[j * 4 + 3] = hv.w + dv.w;
        s += x[j * 4 + 0] + x[j * 4 + 1] + x[j * 4 + 2] + x[j * 4 + 3];
    }
#pragma unroll
    for (int o = 16; o > 0; o >>= 1) s += __shfl_xor_sync(0xffffffffu, s, o);
    float mu = s * (1.f / DIM);

    float vs = 0.f;
#pragma unroll
    for (int i = 0; i < 24; i++) {
        float d = x[i] - mu;
        vs += d * d;
    }
#pragma unroll
    for (int o = 16; o > 0; o >>= 1) vs += __shfl_xor_sync(0xffffffffu, vs, o);
    float inv = rsqrtf(vs * (1.f / DIM) + 1e-5f);
    float w = g_cnt[(b * 2 + inst) * SEQP + pos] * (1.f / 2048.f);

    float* yr = &g_y[z][pos][0];
#pragma unroll
    for (int j = 0; j < 6; j++) {
        int c = (lane + j * 32) * 4;
        float4 gv = *(const float4*)&lng[c];
        float4 bb = *(const float4*)&lnb[c];
        float4 o;
        o.x = (gv.x * (x[j * 4 + 0] - mu) * inv + bb.x) * w;
        o.y = (gv.y * (x[j * 4 + 1] - mu) * inv + bb.y) * w;
        o.z = (gv.z * (x[j * 4 + 2] - mu) * inv + bb.z) * w;
        o.w = (gv.w * (x[j * 4 + 3] - mu) * inv + bb.w) * w;
        *(float4*)&yr[c] = o;
    }
}

// ---------------- output zero + parallel column sum ----------------
__global__ void zero_out_kernel(float* __restrict__ out, int n) {
    int i = blockIdx.x * blockDim.x + threadIdx.x;
    if (i < n) out[i] = 0.f;
}

// grid (3, 6, 8): each block sums 64 rows for 256 columns, atomicAdd into out.
__global__ void colsum_kernel(float* __restrict__ out) {
    int z = blockIdx.y;
    int j = blockIdx.x * 256 + threadIdx.x;
    int p0 = blockIdx.z * 64;
    const float* Y = &g_y[z][0][0];
    float s = 0.f;
#pragma unroll 8
    for (int p = p0; p < p0 + 64; p++) s += Y[(long long)p * DIM + j];
    atomicAdd(&out[(z >> 1) * 2 * DIM + (z & 1) * DIM + j], s);
}

// ---------------- host ----------------
extern "C" void kernel_launch(void* const* d_in, const int* in_sizes, int n_in,
                              void* d_out, int out_size) {
    const float* hidden = (const float*)d_in[0];
    const int* fpos = (const int*)d_in[1];
    const int* tpos = (const int*)d_in[2];
    float* out = (float*)d_out;

    EncParams p;
    for (int inst = 0; inst < 2; inst++) {
        void* const* P = d_in + 3 + inst * 10;
        p.Wq[inst]  = (const float*)P[0];
        p.Wk[inst]  = (const float*)P[1];
        p.Wcb[inst] = (const float*)P[2];
        p.Wv[inst]  = (const float*)P[3];
        p.Wd[inst]  = (const float*)P[4];
        p.mix[inst] = (const float*)P[5];
        p.bv[inst]  = (const float*)P[6];
        p.bd[inst]  = (const float*)P[7];
        p.lng[inst] = (const float*)P[8];
        p.lnb[inst] = (const float*)P[9];
    }

    zero_counts_kernel<<<6, 512>>>();
    count_kernel<<<(3 * NF + 255) / 256, 256>>>(fpos, tpos);

    proj_kernel<<<432, 256>>>(hidden, p);                // Q,K bf16 + V tf32 merged
    cb_kernel<<<dim3(512, 3), 128>>>(hidden, p);         // cb*scale + log(cnt)
    attn_kernel<<<dim3(8, 96), 256>>>(p);                // fused attn (double-buffered)
    wd_kernel<<<dim3(6, 4, 6), 256>>>(p);                // tf32 output projection
    ln_kernel<<<dim3(64, 6), 256>>>(hidden, p);          // residual + LN + weight
    zero_out_kernel<<<(3 * 2 * DIM + 255) / 256, 256>>>(out, 3 * 2 * DIM);
    colsum_kernel<<<dim3(3, 6, 8), 256>>>(out);          // weighted mean -> out
}

// round 17
// speedup vs baseline: 9.3486x; 1.0215x over previous
#include <cuda_runtime.h>
#include <cuda_bf16.h>
#include <math.h>
#include <stdint.h>

#define SEQP 512
#define DIM 768
#define NH 16
#define DH 48
#define NF 2048
#define INV_SCALE 0.14433756729740643f  // 1/sqrt(768/16)

// ---------------- scratch ----------------
__device__ float g_cnt[3 * 2 * SEQP];
__device__ __nv_bfloat16 g_QKbf[6][SEQP][2 * DIM];   // per z6: Q | K  (bf16)
__device__ float g_V[6][SEQP][DIM];                  // V (+bv), fp32 (value path)
__device__ float g_cbk[6][NH][SEQP];                 // cb*INV_SCALE + log(kcnt)
__device__ float g_ctx[6][SEQP][DIM];
__device__ float g_dproj[6][SEQP][DIM];

struct EncParams {
    const float *Wq[2], *Wk[2], *Wv[2], *Wcb[2], *Wd[2], *mix[2];
    const float *bv[2], *bd[2], *lng[2], *lnb[2];
};

// ---------------- zero counts + output (MUST cover 4608 out elements) --------
__global__ void zero_kernel(float* __restrict__ out) {
    int i = blockIdx.x * blockDim.x + threadIdx.x;
    if (i < 3 * 2 * SEQP) g_cnt[i] = 0.f;
    if (i < 3 * 2 * DIM) out[i] = 0.f;
}

__global__ void count_kernel(const int* __restrict__ fpos, const int* __restrict__ tpos) {
    int i = blockIdx.x * blockDim.x + threadIdx.x;
    if (i >= 3 * NF) return;
    int b = i / NF;
    atomicAdd(&g_cnt[(b * 2 + 0) * SEQP + (fpos[i] & (SEQP - 1))], 1.f);
    atomicAdd(&g_cnt[(b * 2 + 1) * SEQP + (tpos[i] & (SEQP - 1))], 1.f);
}

// ================= mma primitives =================
__device__ __forceinline__ uint32_t f2tf32(float v) {
    uint32_t u;
    asm("cvt.rna.tf32.f32 %0, %1;" : "=r"(u) : "f"(v));
    return u;
}

__device__ __forceinline__ void mma_tf32(float* c, const uint32_t* a, const uint32_t* b) {
    asm volatile(
        "mma.sync.aligned.m16n8k8.row.col.f32.tf32.tf32.f32 "
        "{%0,%1,%2,%3}, {%4,%5,%6,%7}, {%8,%9}, {%0,%1,%2,%3};\n"
        : "+f"(c[0]), "+f"(c[1]), "+f"(c[2]), "+f"(c[3])
        : "r"(a[0]), "r"(a[1]), "r"(a[2]), "r"(a[3]), "r"(b[0]), "r"(b[1]));
}

__device__ __forceinline__ void mma_bf16(float* c, const uint32_t* a, const uint32_t* b) {
    asm volatile(
        "mma.sync.aligned.m16n8k16.row.col.f32.bf16.bf16.f32 "
        "{%0,%1,%2,%3}, {%4,%5,%6,%7}, {%8,%9}, {%0,%1,%2,%3};\n"
        : "+f"(c[0]), "+f"(c[1]), "+f"(c[2]), "+f"(c[3])
        : "r"(a[0]), "r"(a[1]), "r"(a[2]), "r"(a[3]), "r"(b[0]), "r"(b[1]));
}

__device__ __forceinline__ uint32_t packbf(float x, float y) {
    __nv_bfloat162 h = __float22bfloat162_rn(make_float2(x, y));
    return *(uint32_t*)&h;
}

// --------- 128x128 tf32 GEMM tile, double-buffered: C = A @ B^T (+bias) ----
template <bool HAS_BIAS>
__device__ __forceinline__ void tf32_gemm128(
    uint32_t* sh,
    const float* __restrict__ A, int lda,
    const float* __restrict__ B, int ldb,
    float* __restrict__ C, int ldc,
    int K, const float* __restrict__ bias,
    int row0, int col0)
{
    const int tid = threadIdx.x;
    const int lane = tid & 31;
    const int g = lane >> 2, tig = lane & 3;
    const int warp = tid >> 5;
    const int wm0 = (warp >> 2) * 64;
    const int wn0 = (warp & 3) * 32;
    const int lrow = tid >> 2, lc4 = tid & 3;

    float4 aR[2], bR[2];

    auto ldg = [&](int k0) {
#pragma unroll
        for (int r = 0; r < 2; r++) {
            int m = lrow + r * 64;
            aR[r] = *(const float4*)(A + (long long)(row0 + m) * lda + k0 + lc4 * 4);
            bR[r] = *(const float4*)(B + (long long)(col0 + m) * ldb + k0 + lc4 * 4);
        }
    };
    auto sts = [&](int st) {
        uint32_t* As = sh + st * 2112;
        uint32_t* Bs = sh + 4224 + st * 2112;
#pragma unroll
        for (int r = 0; r < 2; r++) {
            int m = lrow + r * 64;
            As[(lc4 * 4 + 0) * 132 + m] = f2tf32(aR[r].x);
            As[(lc4 * 4 + 1) * 132 + m] = f2tf32(aR[r].y);
            As[(lc4 * 4 + 2) * 132 + m] = f2tf32(aR[r].z);
            As[(lc4 * 4 + 3) * 132 + m] = f2tf32(aR[r].w);
            Bs[(lc4 * 4 + 0) * 132 + m] = f2tf32(bR[r].x);
            Bs[(lc4 * 4 + 1) * 132 + m] = f2tf32(bR[r].y);
            Bs[(lc4 * 4 + 2) * 132 + m] = f2tf32(bR[r].z);
            Bs[(lc4 * 4 + 3) * 132 + m] = f2tf32(bR[r].w);
        }
    };

    ldg(0);
    sts(0);
    __syncthreads();

    float acc[4][4][4] = {};
    const int NT = K / 16;

    for (int t = 0; t < NT; t++) {
        const int st = t & 1;
        if (t + 1 < NT) ldg((t + 1) * 16);
        const uint32_t* As = sh + st * 2112;
        const uint32_t* Bs = sh + 4224 + st * 2112;
#pragma unroll
        for (int ks = 0; ks < 2; ks++) {
            const int kb = ks * 8;
            uint32_t af[4][4], bf[4][2];
#pragma unroll
            for (int i = 0; i < 4; i++) {
                int m = wm0 + i * 16 + g;
                af[i][0] = As[(kb + tig) * 132 + m];
                af[i][1] = As[(kb + tig) * 132 + m + 8];
                af[i][2] = As[(kb + tig + 4) * 132 + m];
                af[i][3] = As[(kb + tig + 4) * 132 + m + 8];
            }
#pragma unroll
            for (int j = 0; j < 4; j++) {
                int n = wn0 + j * 8 + g;
                bf[j][0] = Bs[(kb + tig) * 132 + n];
                bf[j][1] = Bs[(kb + tig + 4) * 132 + n];
            }
#pragma unroll
            for (int i = 0; i < 4; i++)
#pragma unroll
                for (int j = 0; j < 4; j++)
                    mma_tf32(acc[i][j], af[i], bf[j]);
        }
        if (t + 1 < NT) sts(st ^ 1);
        __syncthreads();
    }

#pragma unroll
    for (int i = 0; i < 4; i++) {
        int m = row0 + wm0 + i * 16 + g;
#pragma unroll
        for (int j = 0; j < 4; j++) {
            int n = col0 + wn0 + j * 8 + tig * 2;
            float2 lo = make_float2(acc[i][j][0], acc[i][j][1]);
            float2 hi = make_float2(acc[i][j][2], acc[i][j][3]);
            if (HAS_BIAS) {
                float2 bb = *(const float2*)&bias[n];
                lo.x += bb.x; lo.y += bb.y;
                hi.x += bb.x; hi.y += bb.y;
            }
            *(float2*)&C[(long long)m * ldc + n]       = lo;
            *(float2*)&C[(long long)(m + 8) * ldc + n] = hi;
        }
    }
}

// --------- 128x128 bf16 GEMM tile, double-buffered: Cbf16 = A @ B^T ----
__device__ __forceinline__ void bf16_gemm128_obf(
    uint32_t* sh,
    const float* __restrict__ A, int lda,
    const float* __restrict__ B, int ldb,
    __nv_bfloat16* __restrict__ C, int ldc,
    int K, int row0, int col0)
{
    const int tid = threadIdx.x;
    const int lane = tid & 31;
    const int g = lane >> 2, tig = lane & 3;
    const int warp = tid >> 5;
    const int wm0 = (warp >> 2) * 64;
    const int wn0 = (warp & 3) * 32;
    const int lrow = tid >> 2, lc4 = tid & 3;

    float4 aR[2][2], bR[2][2];

    auto ldg = [&](int k0) {
#pragma unroll
        for (int r = 0; r < 2; r++) {
            int m = lrow + r * 64;
            const float* ap = A + (long long)(row0 + m) * lda + k0 + lc4 * 8;
            aR[r][0] = *(const float4*)ap;
            aR[r][1] = *(const float4*)(ap + 4);
            const float* bp = B + (long long)(col0 + m) * ldb + k0 + lc4 * 8;
            bR[r][0] = *(const float4*)bp;
            bR[r][1] = *(const float4*)(bp + 4);
        }
    };
    auto sts = [&](int st) {
        uint32_t* As = sh + st * 2176;
        uint32_t* Bs = sh + 4352 + st * 2176;
#pragma unroll
        for (int r = 0; r < 2; r++) {
            int m = lrow + r * 64;
            As[(lc4 * 4 + 0) * 136 + m] = packbf(aR[r][0].x, aR[r][0].y);
            As[(lc4 * 4 + 1) * 136 + m] = packbf(aR[r][0].z, aR[r][0].w);
            As[(lc4 * 4 + 2) * 136 + m] = packbf(aR[r][1].x, aR[r][1].y);
            As[(lc4 * 4 + 3) * 136 + m] = packbf(aR[r][1].z, aR[r][1].w);
            Bs[(lc4 * 4 + 0) * 136 + m] = packbf(bR[r][0].x, bR[r][0].y);
            Bs[(lc4 * 4 + 1) * 136 + m] = packbf(bR[r][0].z, bR[r][0].w);
            Bs[(lc4 * 4 + 2) * 136 + m] = packbf(bR[r][1].x, bR[r][1].y);
            Bs[(lc4 * 4 + 3) * 136 + m] = packbf(bR[r][1].z, bR[r][1].w);
        }
    };

    ldg(0);
    sts(0);
    __syncthreads();

    float acc[4][4][4] = {};
    const int NT = K / 32;

    for (int t = 0; t < NT; t++) {
        const int st = t & 1;
        if (t + 1 < NT) ldg((t + 1) * 32);
        const uint32_t* As = sh + st * 2176;
        const uint32_t* Bs = sh + 4352 + st * 2176;
#pragma unroll
        for (int kc = 0; kc < 2; kc++) {
            const int kb = kc * 8;
            uint32_t af[4][4], bf[4][2];
#pragma unroll
            for (int i = 0; i < 4; i++) {
                int m = wm0 + i * 16 + g;
                af[i][0] = As[(kb + tig) * 136 + m];
                af[i][1] = As[(kb + tig) * 136 + m + 8];
                af[i][2] = As[(kb + tig + 4) * 136 + m];
                af[i][3] = As[(kb + tig + 4) * 136 + m + 8];
            }
#pragma unroll
            for (int j = 0; j < 4; j++) {
                int n = wn0 + j * 8 + g;
                bf[j][0] = Bs[(kb + tig) * 136 + n];
                bf[j][1] = Bs[(kb + tig + 4) * 136 + n];
            }
#pragma unroll
            for (int i = 0; i < 4; i++)
#pragma unroll
                for (int j = 0; j < 4; j++)
                    mma_bf16(acc[i][j], af[i], bf[j]);
        }
        if (t + 1 < NT) sts(st ^ 1);
        __syncthreads();
    }

#pragma unroll
    for (int i = 0; i < 4; i++) {
        int m = row0 + wm0 + i * 16 + g;
#pragma unroll
        for (int j = 0; j < 4; j++) {
            int n = col0 + wn0 + j * 8 + tig * 2;
            *(uint32_t*)&C[(long long)m * ldc + n]       = packbf(acc[i][j][0], acc[i][j][1]);
            *(uint32_t*)&C[(long long)(m + 8) * ldc + n] = packbf(acc[i][j][2], acc[i][j][3]);
        }
    }
}

// ---------------- merged projections: Q,K (bf16) + V (tf32). grid 432 --------
__global__ __launch_bounds__(256, 2) void proj_kernel(const float* __restrict__ hidden,
                                                      EncParams p) {
    __shared__ uint32_t sh[8704];
    int bid = blockIdx.x;
    if (bid < 288) {
        int x = bid % 12, y = (bid / 12) % 4, z = bid / 48;
        int inst = z & 1, b = z >> 1;
        int sector = x / 6;                    // 0=Q, 1=K
        int colL = (x % 6) * 128;
        int row0 = y * 128;
        const float* A = hidden + (long long)b * SEQP * DIM;
        const float* W = sector == 0 ? p.Wq[inst] : p.Wk[inst];
        bf16_gemm128_obf(sh, A, DIM, W, DIM, &g_QKbf[z][0][sector * DIM], 2 * DIM,
                         DIM, row0, colL);
    } else {
        int id = bid - 288;
        int x = id % 6, y = (id / 6) % 4, z = id / 24;
        int inst = z & 1, b = z >> 1;
        const float* A = hidden + (long long)b * SEQP * DIM;
        tf32_gemm128<true>(sh, A, DIM, p.Wv[inst], DIM, &g_V[z][0][0], DIM, DIM,
                           p.bv[inst], y * 128, x * 128);
    }
}

// ---------------- content bias + log(count), 4 positions/block ----------------
__global__ void cb_kernel(const float* __restrict__ hidden, EncParams p) {
    int b = blockIdx.y;
    int p0 = blockIdx.x * 4;
    const float* rows = hidden + ((long long)b * SEQP + p0) * DIM;
    __shared__ float sh[4][DIM];
    for (int i = threadIdx.x; i < 4 * DIM; i += 128)
        sh[i / DIM][i % DIM] = rows[(i / DIM) * DIM + (i % DIM)];
    __syncthreads();
    int warp = threadIdx.x >> 5, lane = threadIdx.x & 31;
#pragma unroll
    for (int q = 0; q < 8; q++) {
        int idx = warp * 8 + q;                  // 0..31 = inst*16 + h
        int inst = idx >> 4, h = idx & 15;
        const float* w = p.Wcb[inst] + h * DIM;
        float s0 = 0.f, s1 = 0.f, s2 = 0.f, s3 = 0.f;
        for (int i = lane; i < DIM; i += 32) {
            float wv = w[i];
            s0 += sh[0][i] * wv;
            s1 += sh[1][i] * wv;
            s2 += sh[2][i] * wv;
            s3 += sh[3][i] * wv;
        }
#pragma unroll
        for (int o = 16; o > 0; o >>= 1) {
            s0 += __shfl_xor_sync(0xffffffffu, s0, o);
            s1 += __shfl_xor_sync(0xffffffffu, s1, o);
            s2 += __shfl_xor_sync(0xffffffffu, s2, o);
            s3 += __shfl_xor_sync(0xffffffffu, s3, o);
        }
        if (lane == 0) {
            const float* cnt = &g_cnt[(b * 2 + (1 - inst)) * SEQP + p0];
            float* dst = &g_cbk[b * 2 + inst][h][p0];
            dst[0] = s0 * INV_SCALE + logf(cnt[0]);
            dst[1] = s1 * INV_SCALE + logf(cnt[1]);
            dst[2] = s2 * INV_SCALE + logf(cnt[2]);
            dst[3] = s3 * INV_SCALE + logf(cnt[3]);
        }
    }
}

// ============ fused attention: scores + count-softmax + PV, double-buffered ====
#define AS_OFF(st) ((st) * 1152)
#define BS_OFF(st) (2304 + (st) * 2176)

__global__ __launch_bounds__(256, 2) void attn_kernel(EncParams p) {
    const int z = blockIdx.y;
    const int inst6 = z >> 4, h = z & 15, inst = inst6 & 1;
    const int row0 = blockIdx.x * 64;
    const __nv_bfloat16* Qg = &g_QKbf[inst6][0][0];
    const __nv_bfloat16* Kg = &g_QKbf[inst6][0][DIM];
    const float* Vg = &g_V[inst6][0][h * DH];
    const float* mix = p.mix[inst] + h * DIM;

    __shared__ uint32_t uSh[6656];
    __shared__ uint32_t Vs[64][56];
    __shared__ uint32_t mixbf[DIM / 2];
    __shared__ float cbk[SEQP];
    __shared__ float redsum[4][64];
    __shared__ float lfin[64];

    const int tid = threadIdx.x;
    const int lane = tid & 31, warp = tid >> 5;
    const int g = lane >> 2, tig = lane & 3;
    const int wm0 = (warp >> 2) * 32;            // scores: 2x4 warps, warp 32x32
    const int wn0 = (warp & 3) * 32;
    const int wmp = (warp >> 1) * 16;            // pv: 4x2 warps, warp 16x24
    const int wnp = (warp & 1) * 24;
    const int lrow = tid >> 2, lc4 = tid & 3;

    for (int i = tid; i < DIM / 2; i += 256) {
        float2 mf = *(const float2*)&mix[i * 2];
        mixbf[i] = packbf(mf.x, mf.y);
    }
    for (int i = tid; i < SEQP; i += 256) cbk[i] = g_cbk[inst6][h][i];
    __syncthreads();

    float accO[3][4] = {};
    float lpart[2][2] = {};
    float accS[2][4][4];

    uint32_t qreg[4];
    uint4 kreg0, kreg1;

    auto load_tile = [&](int kv0, int k0) {
        uint4 qv = *(const uint4*)(Qg + (long long)(row0 + lrow) * (2 * DIM) + k0 + lc4 * 8);
        uint32_t q[4] = {qv.x, qv.y, qv.z, qv.w};
#pragma unroll
        for (int c = 0; c < 4; c++) {
            uint32_t mx = mixbf[k0 / 2 + lc4 * 4 + c];
            __nv_bfloat162 r2 = __hmul2(*(__nv_bfloat162*)&q[c], *(__nv_bfloat162*)&mx);
            qreg[c] = *(uint32_t*)&r2;
        }
        kreg0 = *(const uint4*)(Kg + (long long)(kv0 + lrow) * (2 * DIM) + k0 + lc4 * 8);
        kreg1 = *(const uint4*)(Kg + (long long)(kv0 + lrow + 64) * (2 * DIM) + k0 + lc4 * 8);
    };

    auto sts_tile = [&](int st) {
        const int a = AS_OFF(st), b = BS_OFF(st);
#pragma unroll
        for (int c = 0; c < 4; c++)
            uSh[a + (lc4 * 4 + c) * 72 + lrow] = qreg[c];
        uSh[b + (lc4 * 4 + 0) * 136 + lrow] = kreg0.x;
        uSh[b + (lc4 * 4 + 1) * 136 + lrow] = kreg0.y;
        uSh[b + (lc4 * 4 + 2) * 136 + lrow] = kreg0.z;
        uSh[b + (lc4 * 4 + 3) * 136 + lrow] = kreg0.w;
        uSh[b + (lc4 * 4 + 0) * 136 + lrow + 64] = kreg1.x;
        uSh[b + (lc4 * 4 + 1) * 136 + lrow + 64] = kreg1.y;
        uSh[b + (lc4 * 4 + 2) * 136 + lrow + 64] = kreg1.z;
        uSh[b + (lc4 * 4 + 3) * 136 + lrow + 64] = kreg1.w;
    };

    auto mma_stage = [&](int st) {
        const int a = AS_OFF(st), b = BS_OFF(st);
#pragma unroll
        for (int kc = 0; kc < 2; kc++) {
            const int kb = kc * 8;
            uint32_t af[2][4], bf[4][2];
#pragma unroll
            for (int i = 0; i < 2; i++) {
                int m = wm0 + i * 16 + g;
                af[i][0] = uSh[a + (kb + tig) * 72 + m];
                af[i][1] = uSh[a + (kb + tig) * 72 + m + 8];
                af[i][2] = uSh[a + (kb + tig + 4) * 72 + m];
                af[i][3] = uSh[a + (kb + tig + 4) * 72 + m + 8];
            }
#pragma unroll
            for (int j = 0; j < 4; j++) {
                int n = wn0 + j * 8 + g;
                bf[j][0] = uSh[b + (kb + tig) * 136 + n];
                bf[j][1] = uSh[b + (kb + tig + 4) * 136 + n];
            }
#pragma unroll
            for (int i = 0; i < 2; i++)
#pragma unroll
                for (int j = 0; j < 4; j++)
                    mma_bf16(accS[i][j], af[i], bf[j]);
        }
    };

    for (int kv0 = 0; kv0 < SEQP; kv0 += 128) {
#pragma unroll
        for (int i = 0; i < 2; i++)
#pragma unroll
            for (int j = 0; j < 4; j++)
#pragma unroll
                for (int c = 0; c < 4; c++) accS[i][j][c] = 0.f;

        load_tile(kv0, 0);
        sts_tile(0);
        __syncthreads();
#pragma unroll 4
        for (int kt = 0; kt < 24; kt++) {
            const int st = kt & 1;
            if (kt < 23) load_tile(kv0, (kt + 1) * 32);
            mma_stage(st);
            if (kt < 23) sts_tile(st ^ 1);
            __syncthreads();
        }

        // ---- P = exp(S*INV_SCALE + cbk[t]); accumulate l; store P (overlays) ----
#pragma unroll
        for (int i = 0; i < 2; i++) {
#pragma unroll
            for (int j = 0; j < 4; j++) {
                int colA = kv0 + wn0 + j * 8 + tig * 2;
                float c0 = cbk[colA], c1 = cbk[colA + 1];
                float w0 = __expf(accS[i][j][0] * INV_SCALE + c0);
                float w1 = __expf(accS[i][j][1] * INV_SCALE + c1);
                float w2 = __expf(accS[i][j][2] * INV_SCALE + c0);
                float w3 = __expf(accS[i][j][3] * INV_SCALE + c1);
                lpart[i][0] += w0 + w1;
                lpart[i][1] += w2 + w3;
                int kp = (wn0 >> 1) + j * 4 + tig;
                int m = wm0 + i * 16 + g;
                uSh[kp * 72 + m]     = packbf(w0, w1);
                uSh[kp * 72 + m + 8] = packbf(w2, w3);
            }
        }
        // ---- load V block (128 x 48 fp32 -> bf16 k-pairs) ----
#pragma unroll
        for (int r = 0; r < 3; r++) {
            int idx = tid + r * 256;
            int kp = idx / 12, n4 = idx % 12;
            const float* b0 = Vg + (long long)(kv0 + kp * 2) * DIM + n4 * 4;
            float4 v0 = *(const float4*)b0;
            float4 v1 = *(const float4*)(b0 + DIM);
            Vs[kp][n4 * 4 + 0] = packbf(v0.x, v1.x);
            Vs[kp][n4 * 4 + 1] = packbf(v0.y, v1.y);
            Vs[kp][n4 * 4 + 2] = packbf(v0.z, v1.z);
            Vs[kp][n4 * 4 + 3] = packbf(v0.w, v1.w);
        }
        __syncthreads();

        // ---- O += P @ V_blk : 64x48, k=128 ----
#pragma unroll
        for (int kb8 = 0; kb8 < 8; kb8++) {
            const int kb = kb8 * 8;
            uint32_t af[4], bf2[3][2];
            int m = wmp + g;
            af[0] = uSh[(kb + tig) * 72 + m];
            af[1] = uSh[(kb + tig) * 72 + m + 8];
            af[2] = uSh[(kb + tig + 4) * 72 + m];
            af[3] = uSh[(kb + tig + 4) * 72 + m + 8];
#pragma unroll
            for (int j = 0; j < 3; j++) {
                int n = wnp + j * 8 + g;
                bf2[j][0] = Vs[kb + tig][n];
                bf2[j][1] = Vs[kb + tig + 4][n];
            }
#pragma unroll
            for (int j = 0; j < 3; j++)
                mma_bf16(accO[j], af, bf2[j]);
        }
        __syncthreads();
    }

    // ---- reduce l across quad (tig) + across the 4 warp-cols ----
#pragma unroll
    for (int i = 0; i < 2; i++)
#pragma unroll
        for (int hf = 0; hf < 2; hf++) {
            float v = lpart[i][hf];
            v += __shfl_xor_sync(0xffffffffu, v, 1);
            v += __shfl_xor_sync(0xffffffffu, v, 2);
            lpart[i][hf] = v;
        }
    if (tig == 0) {
#pragma unroll
        for (int i = 0; i < 2; i++)
#pragma unroll
            for (int hf = 0; hf < 2; hf++)
                redsum[warp & 3][wm0 + i * 16 + g + hf * 8] = lpart[i][hf];
    }
    __syncthreads();
    if (tid < 64) lfin[tid] = redsum[0][tid] + redsum[1][tid] + redsum[2][tid] + redsum[3][tid];
    __syncthreads();

    // ---- epilogue: ctx = O / l ----
    float* C = &g_ctx[inst6][0][h * DH];
    int mrow = wmp + g;
    float inv0 = 1.f / lfin[mrow];
    float inv1 = 1.f / lfin[mrow + 8];
#pragma unroll
    for (int j = 0; j < 3; j++) {
        int n = wnp + j * 8 + tig * 2;
        *(float2*)&C[(long long)(row0 + mrow) * DIM + n] =
            make_float2(accO[j][0] * inv0, accO[j][1] * inv0);
        *(float2*)&C[(long long)(row0 + mrow + 8) * DIM + n] =
            make_float2(accO[j][2] * inv1, accO[j][3] * inv1);
    }
}

// ---------------- output projection (tf32). grid (6,4,6), 256 thr -------------
__global__ __launch_bounds__(256) void wd_kernel(EncParams p) {
    __shared__ uint32_t sh[8448];
    int z = blockIdx.z, inst = z & 1;
    tf32_gemm128<true>(sh, &g_ctx[z][0][0], DIM, p.Wd[inst], DIM,
                       &g_dproj[z][0][0], DIM, DIM, p.bd[inst],
                       blockIdx.y * 128, blockIdx.x * 128);
}

// ---------------- residual + LN + weight + column-sum, fused -----------------
// grid (64, 6), 256 thr: 8 warps = 8 positions; block sums its 8 weighted rows
// and atomicAdds one partial per column into out.
__global__ void ln_kernel(const float* __restrict__ hidden, EncParams p,
                          float* __restrict__ out) {
    __shared__ float ys[8][DIM];
    int z = blockIdx.y, inst = z & 1, b = z >> 1;
    int warp = threadIdx.x >> 5, lane = threadIdx.x & 31;
    int pos = blockIdx.x * 8 + warp;
    const float* hr = hidden + ((long long)b * SEQP + pos) * DIM;
    const float* dr = &g_dproj[z][pos][0];
    const float* lng = p.lng[inst];
    const float* lnb = p.lnb[inst];

    float x[24];
    float s = 0.f;
#pragma unroll
    for (int j = 0; j < 6; j++) {
        int c = (lane + j * 32) * 4;
        float4 hv = *(const float4*)&hr[c];
        float4 dv = *(const float4*)&dr[c];
        x[j * 4 + 0] = hv.x + dv.x;
        x[j * 4 + 1] = hv.y + dv.y;
        x[j * 4 + 2] = hv.z + dv.z;
        x[j * 4 + 3] = hv.w + dv.w;
        s += x[j * 4 + 0] + x[j * 4 + 1] + x[j * 4 + 2] + x[j * 4 + 3];
    }
#pragma unroll
    for (int o = 16; o > 0; o >>= 1) s += __shfl_xor_sync(0xffffffffu, s, o);
    float mu = s * (1.f / DIM);

    float vs = 0.f;
#pragma unroll
    for (int i = 0; i < 24; i++) {
        float d = x[i] - mu;
        vs += d * d;
    }
#pragma unroll
    for (int o = 16; o > 0; o >>= 1) vs += __shfl_xor_sync(0xffffffffu, vs, o);
    float inv = rsqrtf(vs * (1.f / DIM) + 1e-5f);
    float w = g_cnt[(b * 2 + inst) * SEQP + pos] * (1.f / 2048.f);

#pragma unroll
    for (int j = 0; j < 6; j++) {
        int c = (lane + j * 32) * 4;
        float4 gv = *(const float4*)&lng[c];
        float4 bb = *(const float4*)&lnb[c];
        float4 o;
        o.x = (gv.x * (x[j * 4 + 0] - mu) * inv + bb.x) * w;
        o.y = (gv.y * (x[j * 4 + 1] - mu) * inv + bb.y) * w;
        o.z = (gv.z * (x[j * 4 + 2] - mu) * inv + bb.z) * w;
        o.w = (gv.w * (x[j * 4 + 3] - mu) * inv + bb.w) * w;
        *(float4*)&ys[warp][c] = o;
    }
    __syncthreads();

    float* od = &out[(long long)b * 2 * DIM + inst * DIM];
    for (int c = threadIdx.x; c < DIM; c += 256) {
        float acc = ys[0][c] + ys[1][c] + ys[2][c] + ys[3][c]
                  + ys[4][c] + ys[5][c] + ys[6][c] + ys[7][c];
        atomicAdd(&od[c], acc);
    }
}

// ---------------- host ----------------
extern "C" void kernel_launch(void* const* d_in, const int* in_sizes, int n_in,
                              void* d_out, int out_size) {
    const float* hidden = (const float*)d_in[0];
    const int* fpos = (const int*)d_in[1];
    const int* tpos = (const int*)d_in[2];
    float* out = (float*)d_out;

    EncParams p;
    for (int inst = 0; inst < 2; inst++) {
        void* const* P = d_in + 3 + inst * 10;
        p.Wq[inst]  = (const float*)P[0];
        p.Wk[inst]  = (const float*)P[1];
        p.Wcb[inst] = (const float*)P[2];
        p.Wv[inst]  = (const float*)P[3];
        p.Wd[inst]  = (const float*)P[4];
        p.mix[inst] = (const float*)P[5];
        p.bv[inst]  = (const float*)P[6];
        p.bd[inst]  = (const float*)P[7];
        p.lng[inst] = (const float*)P[8];
        p.lnb[inst] = (const float*)P[9];
    }

    zero_kernel<<<18, 256>>>(out);                       // zero counts + FULL out (4608)
    count_kernel<<<(3 * NF + 255) / 256, 256>>>(fpos, tpos);

    proj_kernel<<<432, 256>>>(hidden, p);                // Q,K bf16 + V tf32 merged
    cb_kernel<<<dim3(128, 3), 128>>>(hidden, p);         // cb*scale + log(cnt), 4 pos/blk
    attn_kernel<<<dim3(8, 96), 256>>>(p);                // fused attn (double-buffered)
    wd_kernel<<<dim3(6, 4, 6), 256>>>(p);                // tf32 output projection
    ln_kernel<<<dim3(64, 6), 256>>>(hidden, p, out);     // LN + weight + colsum fused
}